// round 2
// baseline (speedup 1.0000x reference)
#include <cuda_runtime.h>
#include <math.h>

#define NU 100000
#define NI 50000
#define DD 64
#define NE 2000000
#define NTOT (NU + NI)
#define SPART 128

// ----------------------------- scratch --------------------------------------
__device__ float g_img_feat[NI * DD];
__device__ float g_txt_feat[NI * DD];
__device__ float g_u_tmp[NU * DD];
__device__ float g_u_acc[NU * DD];
__device__ float g_i_tmp[NI * DD];
__device__ float g_i_acc[NI * DD];

__device__ int   g_cnt_u[NU];
__device__ int   g_offs_u[NU + 1];
__device__ int   g_cnt_i[NI];
__device__ int   g_offs_i[NI + 1];
__device__ unsigned short g_rank_u[NE];
__device__ unsigned short g_rank_i[NE];

__device__ int   g_src_u[NE];
__device__ float g_val_u[NE];
__device__ int   g_src_i[NE];
__device__ float g_val_i[NE];

__device__ float g_part[SPART * DD];
__device__ float g_part1[SPART];
__device__ float g_colmean[DD];
__device__ float g_invrnm;

// ----------------------------- f32x2 packed helpers -------------------------
__device__ __forceinline__ unsigned long long pk2(float x, float y) {
    unsigned long long r;
    asm("mov.b64 %0, {%1, %2};" : "=l"(r) : "f"(x), "f"(y));
    return r;
}
__device__ __forceinline__ void fma2(unsigned long long& d, unsigned long long a,
                                     unsigned long long b) {
    asm("fma.rn.f32x2 %0, %1, %2, %3;" : "=l"(d) : "l"(a), "l"(b), "l"(d));
}
__device__ __forceinline__ float2 upk2(unsigned long long v) {
    float2 f;
    asm("mov.b64 {%0, %1}, %2;" : "=f"(f.x), "=f"(f.y) : "l"(v));
    return f;
}

// ----------------------------- CSR build ------------------------------------
__global__ void k_init() {
    int i = blockIdx.x * blockDim.x + threadIdx.x;
    int st = gridDim.x * blockDim.x;
    for (int k = i; k < NU; k += st) g_cnt_u[k] = 0;
    for (int k = i; k < NI; k += st) g_cnt_i[k] = 0;
}

// histogram + record each edge's rank within its destination row
__global__ void k_hist(const int* __restrict__ eu, const int* __restrict__ ei) {
    int i = blockIdx.x * blockDim.x + threadIdx.x;
    int st = gridDim.x * blockDim.x;
    for (int e = i; e < NE; e += st) {
        g_rank_u[e] = (unsigned short)atomicAdd(&g_cnt_u[eu[e]], 1);
        g_rank_i[e] = (unsigned short)atomicAdd(&g_cnt_i[ei[e]], 1);
    }
}

// grid = 2 blocks x 1024: block 0 scans user counts, block 1 item counts
__global__ void k_scan() {
    const int* cnt;
    int* offs;
    int n;
    if (blockIdx.x == 0) { cnt = g_cnt_u; offs = g_offs_u; n = NU; }
    else                 { cnt = g_cnt_i; offs = g_offs_i; n = NI; }

    __shared__ int warpsum[32];
    __shared__ int s_carry;
    int t = threadIdx.x, lane = t & 31, w = t >> 5;
    if (t == 0) { s_carry = 0; offs[0] = 0; }
    __syncthreads();

    for (int base = 0; base < n; base += 1024) {
        int i = base + t;
        int v = (i < n) ? cnt[i] : 0;
        int x = v;
#pragma unroll
        for (int d = 1; d < 32; d <<= 1) {
            int y = __shfl_up_sync(0xffffffffu, x, d);
            if (lane >= d) x += y;
        }
        if (lane == 31) warpsum[w] = x;
        __syncthreads();
        if (w == 0) {
            int ws = warpsum[lane];
#pragma unroll
            for (int d = 1; d < 32; d <<= 1) {
                int y = __shfl_up_sync(0xffffffffu, ws, d);
                if (lane >= d) ws += y;
            }
            warpsum[lane] = ws;
        }
        __syncthreads();
        int inc = x + (w ? warpsum[w - 1] : 0) + s_carry;
        if (i < n) offs[i + 1] = inc;
        __syncthreads();
        if (t == 1023) s_carry = inc;
        __syncthreads();
    }
}

// atomic-free scatter using precomputed ranks
__global__ void k_scatter(const int* __restrict__ eu, const int* __restrict__ ei,
                          const float* __restrict__ vui, const float* __restrict__ viu) {
    int i = blockIdx.x * blockDim.x + threadIdx.x;
    int st = gridDim.x * blockDim.x;
    for (int e = i; e < NE; e += st) {
        int u = eu[e], it = ei[e];
        int p = g_offs_u[u] + (int)g_rank_u[e];
        g_src_u[p] = it;
        g_val_u[p] = vui[e];
        int q = g_offs_i[it] + (int)g_rank_i[e];
        g_src_i[q] = u;
        g_val_i[q] = viu[e];
    }
}

// ----------------------------- dense linear (M x K @ K x 64 + b) ------------
template <int K, int WHICH>
__global__ __launch_bounds__(256) void k_linear(const float* __restrict__ A,
                                                const float* __restrict__ W,
                                                const float* __restrict__ bias, int M) {
    __shared__ float sW[64 * 64];
    __shared__ float sA[32 * 68];
    float* out = WHICH ? g_txt_feat : g_img_feat;

    int tid = threadIdx.x;
    int m0 = blockIdx.x * 32;
    int row = tid >> 3, cg = tid & 7;
    unsigned long long acc0 = 0, acc1 = 0, acc2 = 0, acc3 = 0;

    for (int k0 = 0; k0 < K; k0 += 64) {
#pragma unroll
        for (int j = 0; j < 4; j++) {
            int idx = tid + j * 256;
            int r = idx >> 4, c4 = idx & 15;
            *(float4*)&sW[r * 64 + c4 * 4] = *(const float4*)&W[(size_t)(k0 + r) * 64 + c4 * 4];
        }
#pragma unroll
        for (int j = 0; j < 2; j++) {
            int idx = tid + j * 256;
            int r = idx >> 4, c4 = idx & 15;
            int m = m0 + r;
            float4 v = (m < M) ? *(const float4*)&A[(size_t)m * K + k0 + c4 * 4]
                               : make_float4(0.f, 0.f, 0.f, 0.f);
            *(float4*)&sA[r * 68 + c4 * 4] = v;
        }
        __syncthreads();
#pragma unroll 16
        for (int kk = 0; kk < 64; kk++) {
            float a = sA[row * 68 + kk];
            unsigned long long a2 = pk2(a, a);
            ulonglong2 q0 = *(const ulonglong2*)&sW[kk * 64 + cg * 8];
            ulonglong2 q1 = *(const ulonglong2*)&sW[kk * 64 + cg * 8 + 4];
            fma2(acc0, a2, q0.x);
            fma2(acc1, a2, q0.y);
            fma2(acc2, a2, q1.x);
            fma2(acc3, a2, q1.y);
        }
        __syncthreads();
    }

    int m = m0 + row;
    if (m < M) {
        float2 p0 = upk2(acc0), p1 = upk2(acc1), p2 = upk2(acc2), p3 = upk2(acc3);
        int c = cg * 8;
        float* o = &out[(size_t)m * 64 + c];
        o[0] = p0.x + bias[c + 0];
        o[1] = p0.y + bias[c + 1];
        o[2] = p1.x + bias[c + 2];
        o[3] = p1.y + bias[c + 3];
        o[4] = p2.x + bias[c + 4];
        o[5] = p2.y + bias[c + 5];
        o[6] = p3.x + bias[c + 6];
        o[7] = p3.y + bias[c + 7];
    }
}

// ----------------------------- single-pass stats -----------------------------
// per-column sums + total sum of squares; Σ(x-m)^2 = Σx^2 - N·Σm^2
__global__ __launch_bounds__(256) void k_stats(const float* __restrict__ ue,
                                               const float* __restrict__ ie) {
    int t = threadIdx.x, col = t & 63, rg = t >> 6;
    float s = 0.f, q = 0.f;
    for (int row = blockIdx.x * 4 + rg; row < NTOT; row += SPART * 4) {
        const float* p = (row < NU) ? ue + (size_t)row * 64 : ie + (size_t)(row - NU) * 64;
        float x = p[col];
        s += x;
        q += x * x;
    }
    __shared__ float sm[256];
    __shared__ float sq[256];
    sm[t] = s;
    sq[t] = q;
    __syncthreads();
    if (t < 64) g_part[blockIdx.x * 64 + t] = sm[t] + sm[t + 64] + sm[t + 128] + sm[t + 192];
    // block reduce q
    for (int o = 128; o >= 32; o >>= 1) {
        if (t < o) sq[t] += sq[t + o];
        __syncthreads();
    }
    if (t < 32) {
        float v = sq[t];
#pragma unroll
        for (int o = 16; o; o >>= 1) v += __shfl_xor_sync(0xffffffffu, v, o);
        if (t == 0) g_part1[blockIdx.x] = v;
    }
}

// one block, 128 threads: colmean + invrnm
__global__ void k_stats_fin() {
    __shared__ float smean[64];
    __shared__ float red[128];
    int t = threadIdx.x;
    if (t < 64) {
        float s = 0.f;
#pragma unroll 8
        for (int b = 0; b < SPART; b++) s += g_part[b * 64 + t];
        float m = s / (float)NTOT;
        g_colmean[t] = m;
        smean[t] = m;
    }
    __syncthreads();
    float v = g_part1[t];
    if (t < 64) v -= (float)NTOT * smean[t] * smean[t];
    red[t] = v;
    __syncthreads();
    for (int o = 64; o >= 32; o >>= 1) {
        if (t < o) red[t] += red[t + o];
        __syncthreads();
    }
    if (t < 32) {
        float x = red[t];
#pragma unroll
        for (int o = 16; o; o >>= 1) x += __shfl_xor_sync(0xffffffffu, x, o);
        if (t == 0) g_invrnm = rsqrtf(x / (float)NTOT + 1e-6f);
    }
}

// normalize ITEM embeddings into g_i_tmp (gather source for layer-1 user SpMM)
__global__ void k_norm_items(const float* __restrict__ ie) {
    float inv = g_invrnm;
    int st = gridDim.x * blockDim.x;
    int i0 = blockIdx.x * blockDim.x + threadIdx.x;
    const float4* i4 = (const float4*)ie;
    const float4* cm4 = (const float4*)g_colmean;
    for (int idx = i0; idx < NI * 16; idx += st) {
        float4 v = i4[idx];
        float4 cm = cm4[idx & 15];
        ((float4*)g_i_tmp)[idx] = make_float4((v.x - cm.x) * inv, (v.y - cm.y) * inv,
                                              (v.z - cm.z) * inv, (v.w - cm.w) * inv);
    }
}

// ----------------------------- fused triple SpMM ----------------------------
// USER side: per edge gather {img_feat, txt_feat, i_tmp} rows.
// Writes image_user, text_user, u_tmp (=u_g layer1), u_acc (=normed_u + u_g).
__global__ __launch_bounds__(256) void k_fused_u(const float* __restrict__ user_emb,
                                                 float* __restrict__ imgU,
                                                 float* __restrict__ txtU) {
    int w = (blockIdx.x * 256 + threadIdx.x) >> 5;
    if (w >= NU) return;
    int lane = threadIdx.x & 31;
    const float2* MI = (const float2*)g_img_feat;
    const float2* MT = (const float2*)g_txt_feat;
    const float2* ME = (const float2*)g_i_tmp;
    const int* __restrict__ src = g_src_u;
    const float* __restrict__ val = g_val_u;
    int s = g_offs_u[w], e = g_offs_u[w + 1];
    float2 aI = make_float2(0.f, 0.f), aT = aI, aE = aI;
    int k = s;
    for (; k + 4 <= e; k += 4) {
        int j0 = __ldg(&src[k]), j1 = __ldg(&src[k + 1]);
        int j2 = __ldg(&src[k + 2]), j3 = __ldg(&src[k + 3]);
        float v0 = __ldg(&val[k]), v1 = __ldg(&val[k + 1]);
        float v2 = __ldg(&val[k + 2]), v3 = __ldg(&val[k + 3]);
        float2 i0 = MI[j0 * 32 + lane], t0 = MT[j0 * 32 + lane], e0 = ME[j0 * 32 + lane];
        float2 i1 = MI[j1 * 32 + lane], t1 = MT[j1 * 32 + lane], e1 = ME[j1 * 32 + lane];
        float2 i2 = MI[j2 * 32 + lane], t2 = MT[j2 * 32 + lane], e2 = ME[j2 * 32 + lane];
        float2 i3 = MI[j3 * 32 + lane], t3 = MT[j3 * 32 + lane], e3 = ME[j3 * 32 + lane];
        aI.x += v0 * i0.x + v1 * i1.x + v2 * i2.x + v3 * i3.x;
        aI.y += v0 * i0.y + v1 * i1.y + v2 * i2.y + v3 * i3.y;
        aT.x += v0 * t0.x + v1 * t1.x + v2 * t2.x + v3 * t3.x;
        aT.y += v0 * t0.y + v1 * t1.y + v2 * t2.y + v3 * t3.y;
        aE.x += v0 * e0.x + v1 * e1.x + v2 * e2.x + v3 * e3.x;
        aE.y += v0 * e0.y + v1 * e1.y + v2 * e2.y + v3 * e3.y;
    }
    for (; k < e; k++) {
        int j = __ldg(&src[k]);
        float v = __ldg(&val[k]);
        float2 i0 = MI[j * 32 + lane], t0 = MT[j * 32 + lane], e0 = ME[j * 32 + lane];
        aI.x += v * i0.x; aI.y += v * i0.y;
        aT.x += v * t0.x; aT.y += v * t0.y;
        aE.x += v * e0.x; aE.y += v * e0.y;
    }
    int o = w * 32 + lane;
    ((float2*)imgU)[o] = aI;
    ((float2*)txtU)[o] = aT;
    ((float2*)g_u_tmp)[o] = aE;
    float inv = g_invrnm;
    float2 ue = ((const float2*)user_emb)[o];
    float2 cm = ((const float2*)g_colmean)[lane];
    float2 acc;
    acc.x = (ue.x - cm.x) * inv + aE.x;
    acc.y = (ue.y - cm.y) * inv + aE.y;
    ((float2*)g_u_acc)[o] = acc;
}

// ITEM side: per edge gather {image_user, text_user, u_tmp} rows.
// Writes image_item, text_item, i_tmp (=i_g layer1), i_acc (=normed_i + i_g).
__global__ __launch_bounds__(256) void k_fused_i(const float* __restrict__ item_emb,
                                                 const float* __restrict__ imgU,
                                                 const float* __restrict__ txtU,
                                                 float* __restrict__ imgI,
                                                 float* __restrict__ txtI) {
    int w = (blockIdx.x * 256 + threadIdx.x) >> 5;
    if (w >= NI) return;
    int lane = threadIdx.x & 31;
    const float2* MI = (const float2*)imgU;
    const float2* MT = (const float2*)txtU;
    const float2* ME = (const float2*)g_u_tmp;
    const int* __restrict__ src = g_src_i;
    const float* __restrict__ val = g_val_i;
    int s = g_offs_i[w], e = g_offs_i[w + 1];
    float2 aI = make_float2(0.f, 0.f), aT = aI, aE = aI;
    int k = s;
    for (; k + 4 <= e; k += 4) {
        int j0 = __ldg(&src[k]), j1 = __ldg(&src[k + 1]);
        int j2 = __ldg(&src[k + 2]), j3 = __ldg(&src[k + 3]);
        float v0 = __ldg(&val[k]), v1 = __ldg(&val[k + 1]);
        float v2 = __ldg(&val[k + 2]), v3 = __ldg(&val[k + 3]);
        float2 i0 = MI[j0 * 32 + lane], t0 = MT[j0 * 32 + lane], e0 = ME[j0 * 32 + lane];
        float2 i1 = MI[j1 * 32 + lane], t1 = MT[j1 * 32 + lane], e1 = ME[j1 * 32 + lane];
        float2 i2 = MI[j2 * 32 + lane], t2 = MT[j2 * 32 + lane], e2 = ME[j2 * 32 + lane];
        float2 i3 = MI[j3 * 32 + lane], t3 = MT[j3 * 32 + lane], e3 = ME[j3 * 32 + lane];
        aI.x += v0 * i0.x + v1 * i1.x + v2 * i2.x + v3 * i3.x;
        aI.y += v0 * i0.y + v1 * i1.y + v2 * i2.y + v3 * i3.y;
        aT.x += v0 * t0.x + v1 * t1.x + v2 * t2.x + v3 * t3.x;
        aT.y += v0 * t0.y + v1 * t1.y + v2 * t2.y + v3 * t3.y;
        aE.x += v0 * e0.x + v1 * e1.x + v2 * e2.x + v3 * e3.x;
        aE.y += v0 * e0.y + v1 * e1.y + v2 * e2.y + v3 * e3.y;
    }
    for (; k < e; k++) {
        int j = __ldg(&src[k]);
        float v = __ldg(&val[k]);
        float2 i0 = MI[j * 32 + lane], t0 = MT[j * 32 + lane], e0 = ME[j * 32 + lane];
        aI.x += v * i0.x; aI.y += v * i0.y;
        aT.x += v * t0.x; aT.y += v * t0.y;
        aE.x += v * e0.x; aE.y += v * e0.y;
    }
    int o = w * 32 + lane;
    ((float2*)imgI)[o] = aI;
    ((float2*)txtI)[o] = aT;
    ((float2*)g_i_tmp)[o] = aE;
    float inv = g_invrnm;
    float2 ie = ((const float2*)item_emb)[o];
    float2 cm = ((const float2*)g_colmean)[lane];
    float2 acc;
    acc.x = (ie.x - cm.x) * inv + aE.x;
    acc.y = (ie.y - cm.y) * inv + aE.y;
    ((float2*)g_i_acc)[o] = acc;
}

// ----------------------------- layer-2 GNN fused with final combine ---------
// USER: y2 = CSR_u * i_tmp; u_tmp=y2; u_out=(u_acc+y2)/3 + 0.55*n(imgU)+0.55*n(txtU)
__global__ __launch_bounds__(256) void k_gnn_u2(const float* __restrict__ imgU,
                                                const float* __restrict__ txtU,
                                                float* __restrict__ u_out) {
    int w = (blockIdx.x * 256 + threadIdx.x) >> 5;
    if (w >= NU) return;
    int lane = threadIdx.x & 31;
    const float2* X2 = (const float2*)g_i_tmp;
    const int* __restrict__ src = g_src_u;
    const float* __restrict__ val = g_val_u;
    int s = g_offs_u[w], e = g_offs_u[w + 1];
    float2 acc = make_float2(0.f, 0.f);
    int k = s;
    for (; k + 8 <= e; k += 8) {
        float2 xs[8];
        float vs[8];
#pragma unroll
        for (int t = 0; t < 8; t++) {
            int j = __ldg(&src[k + t]);
            vs[t] = __ldg(&val[k + t]);
            xs[t] = X2[j * 32 + lane];
        }
#pragma unroll
        for (int t = 0; t < 8; t++) {
            acc.x += vs[t] * xs[t].x;
            acc.y += vs[t] * xs[t].y;
        }
    }
    for (; k < e; k++) {
        int j = __ldg(&src[k]);
        float v = __ldg(&val[k]);
        float2 x = X2[j * 32 + lane];
        acc.x += v * x.x;
        acc.y += v * x.y;
    }
    int o = w * 32 + lane;
    ((float2*)g_u_tmp)[o] = acc;
    float2 g = ((const float2*)g_u_acc)[o];
    float2 a = ((const float2*)imgU)[o];
    float2 b = ((const float2*)txtU)[o];
    float sa = a.x * a.x + a.y * a.y;
    float sb = b.x * b.x + b.y * b.y;
#pragma unroll
    for (int of = 16; of; of >>= 1) {
        sa += __shfl_xor_sync(0xffffffffu, sa, of);
        sb += __shfl_xor_sync(0xffffffffu, sb, of);
    }
    float ia = 0.55f / fmaxf(sqrtf(sa), 1e-12f);
    float ib = 0.55f / fmaxf(sqrtf(sb), 1e-12f);
    float2 r;
    r.x = (g.x + acc.x) * (1.0f / 3.0f) + a.x * ia + b.x * ib;
    r.y = (g.y + acc.y) * (1.0f / 3.0f) + a.y * ia + b.y * ib;
    ((float2*)u_out)[o] = r;
}

// ITEM: y2 = CSR_i * u_tmp; i_out=(i_acc+y2)/3 + 0.55*n(imgI)+0.55*n(txtI)
__global__ __launch_bounds__(256) void k_gnn_i2(const float* __restrict__ imgI,
                                                const float* __restrict__ txtI,
                                                float* __restrict__ i_out) {
    int w = (blockIdx.x * 256 + threadIdx.x) >> 5;
    if (w >= NI) return;
    int lane = threadIdx.x & 31;
    const float2* X2 = (const float2*)g_u_tmp;
    const int* __restrict__ src = g_src_i;
    const float* __restrict__ val = g_val_i;
    int s = g_offs_i[w], e = g_offs_i[w + 1];
    float2 acc = make_float2(0.f, 0.f);
    int k = s;
    for (; k + 8 <= e; k += 8) {
        float2 xs[8];
        float vs[8];
#pragma unroll
        for (int t = 0; t < 8; t++) {
            int j = __ldg(&src[k + t]);
            vs[t] = __ldg(&val[k + t]);
            xs[t] = X2[j * 32 + lane];
        }
#pragma unroll
        for (int t = 0; t < 8; t++) {
            acc.x += vs[t] * xs[t].x;
            acc.y += vs[t] * xs[t].y;
        }
    }
    for (; k < e; k++) {
        int j = __ldg(&src[k]);
        float v = __ldg(&val[k]);
        float2 x = X2[j * 32 + lane];
        acc.x += v * x.x;
        acc.y += v * x.y;
    }
    int o = w * 32 + lane;
    float2 g = ((const float2*)g_i_acc)[o];
    float2 a = ((const float2*)imgI)[o];
    float2 b = ((const float2*)txtI)[o];
    float sa = a.x * a.x + a.y * a.y;
    float sb = b.x * b.x + b.y * b.y;
#pragma unroll
    for (int of = 16; of; of >>= 1) {
        sa += __shfl_xor_sync(0xffffffffu, sa, of);
        sb += __shfl_xor_sync(0xffffffffu, sb, of);
    }
    float ia = 0.55f / fmaxf(sqrtf(sa), 1e-12f);
    float ib = 0.55f / fmaxf(sqrtf(sb), 1e-12f);
    float2 r;
    r.x = (g.x + acc.x) * (1.0f / 3.0f) + a.x * ia + b.x * ib;
    r.y = (g.y + acc.y) * (1.0f / 3.0f) + a.y * ia + b.y * ib;
    ((float2*)i_out)[o] = r;
}

// ----------------------------- launch ---------------------------------------
extern "C" void kernel_launch(void* const* d_in, const int* in_sizes, int n_in,
                              void* d_out, int out_size) {
    const float* image_feats = (const float*)d_in[0];
    const float* text_feats  = (const float*)d_in[1];
    const float* user_emb    = (const float*)d_in[2];
    const float* item_emb    = (const float*)d_in[3];
    const float* W_img       = (const float*)d_in[4];
    const float* b_img       = (const float*)d_in[5];
    const float* W_txt       = (const float*)d_in[6];
    const float* b_txt       = (const float*)d_in[7];
    const float* val_ui      = (const float*)d_in[8];
    const float* val_iu      = (const float*)d_in[9];
    const int*   edge_u      = (const int*)d_in[10];
    const int*   edge_i      = (const int*)d_in[11];

    float* out        = (float*)d_out;
    float* u_out      = out;
    float* i_out      = u_out + (size_t)NU * DD;
    float* image_item = i_out + (size_t)NI * DD;
    float* text_item  = image_item + (size_t)NI * DD;
    float* image_user = text_item + (size_t)NI * DD;
    float* text_user  = image_user + (size_t)NU * DD;

    const int WU = (NU + 7) / 8;
    const int WI = (NI + 7) / 8;

    // CSR build (rank trick: scatter is atomic-free)
    k_init<<<256, 256>>>();
    k_hist<<<512, 256>>>(edge_u, edge_i);
    k_scan<<<2, 1024>>>();
    k_scatter<<<1024, 256>>>(edge_u, edge_i, val_ui, val_iu);

    // dense projections
    k_linear<1024, 0><<<(NI + 31) / 32, 256>>>(image_feats, W_img, b_img, NI);
    k_linear<384, 1><<<(NI + 31) / 32, 256>>>(text_feats, W_txt, b_txt, NI);

    // single-pass stats + parallel finalize + item normalize
    k_stats<<<SPART, 256>>>(user_emb, item_emb);
    k_stats_fin<<<1, 128>>>();
    k_norm_items<<<512, 256>>>(item_emb);

    // fused modal + GNN layer-1
    k_fused_u<<<WU, 256>>>(user_emb, image_user, text_user);
    k_fused_i<<<WI, 256>>>(item_emb, image_user, text_user, image_item, text_item);

    // GNN layer-2 fused with final combine
    k_gnn_u2<<<WU, 256>>>(image_user, text_user, u_out);
    k_gnn_i2<<<WI, 256>>>(image_item, text_item, i_out);
}

// round 3
// speedup vs baseline: 1.8481x; 1.8481x over previous
#include <cuda_runtime.h>
#include <math.h>

#define NU 100000
#define NI 50000
#define DD 64
#define NE 2000000
#define NTOT (NU + NI)
#define SPART 128

// ----------------------------- scratch --------------------------------------
__device__ float g_img_feat[NI * DD];
__device__ float g_txt_feat[NI * DD];
__device__ float g_u_tmp[NU * DD];
__device__ float g_u_acc[NU * DD];
__device__ float g_i_tmp[NI * DD];
__device__ float g_i_acc[NI * DD];

__device__ int   g_cnt_u[NU];
__device__ int   g_offs_u[NU + 1];
__device__ int   g_cnt_i[NI];
__device__ int   g_offs_i[NI + 1];
__device__ unsigned short g_rank_u[NE];
__device__ unsigned short g_rank_i[NE];

__device__ int   g_src_u[NE];
__device__ float g_val_u[NE];
__device__ int   g_src_i[NE];
__device__ float g_val_i[NE];

__device__ float g_part[SPART * DD];
__device__ float g_part1[SPART];
__device__ float g_colmean[DD];
__device__ float g_invrnm;

// ----------------------------- f32x2 packed helpers -------------------------
__device__ __forceinline__ unsigned long long pk2(float x, float y) {
    unsigned long long r;
    asm("mov.b64 %0, {%1, %2};" : "=l"(r) : "f"(x), "f"(y));
    return r;
}
__device__ __forceinline__ void fma2(unsigned long long& d, unsigned long long a,
                                     unsigned long long b) {
    asm("fma.rn.f32x2 %0, %1, %2, %3;" : "=l"(d) : "l"(a), "l"(b), "l"(d));
}
__device__ __forceinline__ float2 upk2(unsigned long long v) {
    float2 f;
    asm("mov.b64 {%0, %1}, %2;" : "=f"(f.x), "=f"(f.y) : "l"(v));
    return f;
}

// ----------------------------- CSR build ------------------------------------
__global__ void k_init() {
    int i = blockIdx.x * blockDim.x + threadIdx.x;
    int st = gridDim.x * blockDim.x;
    for (int k = i; k < NU; k += st) g_cnt_u[k] = 0;
    for (int k = i; k < NI; k += st) g_cnt_i[k] = 0;
}

__global__ void k_hist(const int* __restrict__ eu, const int* __restrict__ ei) {
    int i = blockIdx.x * blockDim.x + threadIdx.x;
    int st = gridDim.x * blockDim.x;
    for (int e = i; e < NE; e += st) {
        g_rank_u[e] = (unsigned short)atomicAdd(&g_cnt_u[eu[e]], 1);
        g_rank_i[e] = (unsigned short)atomicAdd(&g_cnt_i[ei[e]], 1);
    }
}

__global__ void k_scan() {
    const int* cnt;
    int* offs;
    int n;
    if (blockIdx.x == 0) { cnt = g_cnt_u; offs = g_offs_u; n = NU; }
    else                 { cnt = g_cnt_i; offs = g_offs_i; n = NI; }

    __shared__ int warpsum[32];
    __shared__ int s_carry;
    int t = threadIdx.x, lane = t & 31, w = t >> 5;
    if (t == 0) { s_carry = 0; offs[0] = 0; }
    __syncthreads();

    for (int base = 0; base < n; base += 1024) {
        int i = base + t;
        int v = (i < n) ? cnt[i] : 0;
        int x = v;
#pragma unroll
        for (int d = 1; d < 32; d <<= 1) {
            int y = __shfl_up_sync(0xffffffffu, x, d);
            if (lane >= d) x += y;
        }
        if (lane == 31) warpsum[w] = x;
        __syncthreads();
        if (w == 0) {
            int ws = warpsum[lane];
#pragma unroll
            for (int d = 1; d < 32; d <<= 1) {
                int y = __shfl_up_sync(0xffffffffu, ws, d);
                if (lane >= d) ws += y;
            }
            warpsum[lane] = ws;
        }
        __syncthreads();
        int inc = x + (w ? warpsum[w - 1] : 0) + s_carry;
        if (i < n) offs[i + 1] = inc;
        __syncthreads();
        if (t == 1023) s_carry = inc;
        __syncthreads();
    }
}

__global__ void k_scatter(const int* __restrict__ eu, const int* __restrict__ ei,
                          const float* __restrict__ vui, const float* __restrict__ viu) {
    int i = blockIdx.x * blockDim.x + threadIdx.x;
    int st = gridDim.x * blockDim.x;
    for (int e = i; e < NE; e += st) {
        int u = eu[e], it = ei[e];
        int p = g_offs_u[u] + (int)g_rank_u[e];
        g_src_u[p] = it;
        g_val_u[p] = vui[e];
        int q = g_offs_i[it] + (int)g_rank_i[e];
        g_src_i[q] = u;
        g_val_i[q] = viu[e];
    }
}

// ----------------------------- dense linear (register-tiled) ----------------
// Tile: 128 rows x 64 cols, 256 threads, 8x4 outputs/thread, K-step 16,
// global->reg prefetch double buffering. f32x2 accumulators.
template <int K, int WHICH>
__global__ __launch_bounds__(256) void k_linear(const float* __restrict__ A,
                                                const float* __restrict__ W,
                                                const float* __restrict__ bias, int M) {
    __shared__ float sA[128 * 20];  // [row][k] padded stride 20 (16B aligned)
    __shared__ float sW[16 * 64];   // [k][col]
    float* out = WHICH ? g_txt_feat : g_img_feat;

    int t = threadIdx.x;
    int m0 = blockIdx.x * 128;
    int tx = t & 15;         // 16 col-groups of 4
    int ty = t >> 4;         // 16 row-groups of 8
    int ar = t >> 2;         // A loader: rows ar, ar+64
    int ac4 = (t & 3) * 4;   // A loader: k columns
    int wr = t >> 4;         // W loader row (k)
    int wc4 = (t & 15) * 4;  // W loader col

    unsigned long long acc[8][2];
#pragma unroll
    for (int i = 0; i < 8; i++) { acc[i][0] = 0ull; acc[i][1] = 0ull; }

    float4 pa0, pa1, pw;
    {
        int m = m0 + ar;
        pa0 = (m < M) ? *(const float4*)&A[(size_t)m * K + ac4] : make_float4(0.f, 0.f, 0.f, 0.f);
        int m2 = m0 + ar + 64;
        pa1 = (m2 < M) ? *(const float4*)&A[(size_t)m2 * K + ac4] : make_float4(0.f, 0.f, 0.f, 0.f);
        pw = *(const float4*)&W[(size_t)wr * 64 + wc4];
    }

    for (int k0 = 0; k0 < K; k0 += 16) {
        *(float4*)&sA[ar * 20 + ac4] = pa0;
        *(float4*)&sA[(ar + 64) * 20 + ac4] = pa1;
        *(float4*)&sW[wr * 64 + wc4] = pw;
        __syncthreads();

        if (k0 + 16 < K) {
            int kn = k0 + 16;
            int m = m0 + ar;
            pa0 = (m < M) ? *(const float4*)&A[(size_t)m * K + kn + ac4]
                          : make_float4(0.f, 0.f, 0.f, 0.f);
            int m2 = m0 + ar + 64;
            pa1 = (m2 < M) ? *(const float4*)&A[(size_t)m2 * K + kn + ac4]
                           : make_float4(0.f, 0.f, 0.f, 0.f);
            pw = *(const float4*)&W[(size_t)(kn + wr) * 64 + wc4];
        }

#pragma unroll
        for (int kk = 0; kk < 16; kk++) {
            float4 w4 = *(const float4*)&sW[kk * 64 + tx * 4];
            unsigned long long wx = pk2(w4.x, w4.y);
            unsigned long long wy = pk2(w4.z, w4.w);
#pragma unroll
            for (int i = 0; i < 8; i++) {
                float a = sA[(ty * 8 + i) * 20 + kk];
                unsigned long long a2 = pk2(a, a);
                fma2(acc[i][0], a2, wx);
                fma2(acc[i][1], a2, wy);
            }
        }
        __syncthreads();
    }

    float4 bv = *(const float4*)&bias[tx * 4];
#pragma unroll
    for (int i = 0; i < 8; i++) {
        int m = m0 + ty * 8 + i;
        if (m < M) {
            float2 p0 = upk2(acc[i][0]), p1 = upk2(acc[i][1]);
            float4 r = make_float4(p0.x + bv.x, p0.y + bv.y, p1.x + bv.z, p1.y + bv.w);
            *(float4*)&out[(size_t)m * 64 + tx * 4] = r;
        }
    }
}

// ----------------------------- single-pass stats -----------------------------
__global__ __launch_bounds__(256) void k_stats(const float* __restrict__ ue,
                                               const float* __restrict__ ie) {
    int t = threadIdx.x, col = t & 63, rg = t >> 6;
    float s = 0.f, q = 0.f;
    for (int row = blockIdx.x * 4 + rg; row < NTOT; row += SPART * 4) {
        const float* p = (row < NU) ? ue + (size_t)row * 64 : ie + (size_t)(row - NU) * 64;
        float x = p[col];
        s += x;
        q += x * x;
    }
    __shared__ float sm[256];
    __shared__ float sq[256];
    sm[t] = s;
    sq[t] = q;
    __syncthreads();
    if (t < 64) g_part[blockIdx.x * 64 + t] = sm[t] + sm[t + 64] + sm[t + 128] + sm[t + 192];
    for (int o = 128; o >= 32; o >>= 1) {
        if (t < o) sq[t] += sq[t + o];
        __syncthreads();
    }
    if (t < 32) {
        float v = sq[t];
#pragma unroll
        for (int o = 16; o; o >>= 1) v += __shfl_xor_sync(0xffffffffu, v, o);
        if (t == 0) g_part1[blockIdx.x] = v;
    }
}

__global__ void k_stats_fin() {
    __shared__ float smean[64];
    __shared__ float red[128];
    int t = threadIdx.x;
    if (t < 64) {
        float s = 0.f;
#pragma unroll 8
        for (int b = 0; b < SPART; b++) s += g_part[b * 64 + t];
        float m = s / (float)NTOT;
        g_colmean[t] = m;
        smean[t] = m;
    }
    __syncthreads();
    float v = g_part1[t];
    if (t < 64) v -= (float)NTOT * smean[t] * smean[t];
    red[t] = v;
    __syncthreads();
    for (int o = 64; o >= 32; o >>= 1) {
        if (t < o) red[t] += red[t + o];
        __syncthreads();
    }
    if (t < 32) {
        float x = red[t];
#pragma unroll
        for (int o = 16; o; o >>= 1) x += __shfl_xor_sync(0xffffffffu, x, o);
        if (t == 0) g_invrnm = rsqrtf(x / (float)NTOT + 1e-6f);
    }
}

__global__ void k_norm_items(const float* __restrict__ ie) {
    float inv = g_invrnm;
    int st = gridDim.x * blockDim.x;
    int i0 = blockIdx.x * blockDim.x + threadIdx.x;
    const float4* i4 = (const float4*)ie;
    const float4* cm4 = (const float4*)g_colmean;
    for (int idx = i0; idx < NI * 16; idx += st) {
        float4 v = i4[idx];
        float4 cm = cm4[idx & 15];
        ((float4*)g_i_tmp)[idx] = make_float4((v.x - cm.x) * inv, (v.y - cm.y) * inv,
                                              (v.z - cm.z) * inv, (v.w - cm.w) * inv);
    }
}

// ----------------------------- fused triple SpMM (unroll 8) -----------------
__global__ __launch_bounds__(256) void k_fused_u(const float* __restrict__ user_emb,
                                                 float* __restrict__ imgU,
                                                 float* __restrict__ txtU) {
    int w = (blockIdx.x * 256 + threadIdx.x) >> 5;
    if (w >= NU) return;
    int lane = threadIdx.x & 31;
    const float2* __restrict__ MI = (const float2*)g_img_feat;
    const float2* __restrict__ MT = (const float2*)g_txt_feat;
    const float2* __restrict__ ME = (const float2*)g_i_tmp;
    const int* __restrict__ src = g_src_u;
    const float* __restrict__ val = g_val_u;
    int s = g_offs_u[w], e = g_offs_u[w + 1];
    float2 aI = make_float2(0.f, 0.f), aT = aI, aE = aI;
    int k = s;
    for (; k + 8 <= e; k += 8) {
        int js[8];
        float vs[8];
        float2 xi[8], xt[8], xe[8];
#pragma unroll
        for (int u = 0; u < 8; u++) {
            js[u] = __ldg(&src[k + u]);
            vs[u] = __ldg(&val[k + u]);
        }
#pragma unroll
        for (int u = 0; u < 8; u++) {
            int b = js[u] * 32 + lane;
            xi[u] = MI[b];
            xt[u] = MT[b];
            xe[u] = ME[b];
        }
#pragma unroll
        for (int u = 0; u < 8; u++) {
            aI.x += vs[u] * xi[u].x; aI.y += vs[u] * xi[u].y;
            aT.x += vs[u] * xt[u].x; aT.y += vs[u] * xt[u].y;
            aE.x += vs[u] * xe[u].x; aE.y += vs[u] * xe[u].y;
        }
    }
    for (; k < e; k++) {
        int j = __ldg(&src[k]);
        float v = __ldg(&val[k]);
        int b = j * 32 + lane;
        float2 i0 = MI[b], t0 = MT[b], e0 = ME[b];
        aI.x += v * i0.x; aI.y += v * i0.y;
        aT.x += v * t0.x; aT.y += v * t0.y;
        aE.x += v * e0.x; aE.y += v * e0.y;
    }
    int o = w * 32 + lane;
    ((float2*)imgU)[o] = aI;
    ((float2*)txtU)[o] = aT;
    ((float2*)g_u_tmp)[o] = aE;
    float inv = g_invrnm;
    float2 ue = ((const float2*)user_emb)[o];
    float2 cm = ((const float2*)g_colmean)[lane];
    float2 acc;
    acc.x = (ue.x - cm.x) * inv + aE.x;
    acc.y = (ue.y - cm.y) * inv + aE.y;
    ((float2*)g_u_acc)[o] = acc;
}

__global__ __launch_bounds__(256) void k_fused_i(const float* __restrict__ item_emb,
                                                 const float* __restrict__ imgU,
                                                 const float* __restrict__ txtU,
                                                 float* __restrict__ imgI,
                                                 float* __restrict__ txtI) {
    int w = (blockIdx.x * 256 + threadIdx.x) >> 5;
    if (w >= NI) return;
    int lane = threadIdx.x & 31;
    const float2* __restrict__ MI = (const float2*)imgU;
    const float2* __restrict__ MT = (const float2*)txtU;
    const float2* __restrict__ ME = (const float2*)g_u_tmp;
    const int* __restrict__ src = g_src_i;
    const float* __restrict__ val = g_val_i;
    int s = g_offs_i[w], e = g_offs_i[w + 1];
    float2 aI = make_float2(0.f, 0.f), aT = aI, aE = aI;
    int k = s;
    for (; k + 8 <= e; k += 8) {
        int js[8];
        float vs[8];
        float2 xi[8], xt[8], xe[8];
#pragma unroll
        for (int u = 0; u < 8; u++) {
            js[u] = __ldg(&src[k + u]);
            vs[u] = __ldg(&val[k + u]);
        }
#pragma unroll
        for (int u = 0; u < 8; u++) {
            int b = js[u] * 32 + lane;
            xi[u] = MI[b];
            xt[u] = MT[b];
            xe[u] = ME[b];
        }
#pragma unroll
        for (int u = 0; u < 8; u++) {
            aI.x += vs[u] * xi[u].x; aI.y += vs[u] * xi[u].y;
            aT.x += vs[u] * xt[u].x; aT.y += vs[u] * xt[u].y;
            aE.x += vs[u] * xe[u].x; aE.y += vs[u] * xe[u].y;
        }
    }
    for (; k < e; k++) {
        int j = __ldg(&src[k]);
        float v = __ldg(&val[k]);
        int b = j * 32 + lane;
        float2 i0 = MI[b], t0 = MT[b], e0 = ME[b];
        aI.x += v * i0.x; aI.y += v * i0.y;
        aT.x += v * t0.x; aT.y += v * t0.y;
        aE.x += v * e0.x; aE.y += v * e0.y;
    }
    int o = w * 32 + lane;
    ((float2*)imgI)[o] = aI;
    ((float2*)txtI)[o] = aT;
    ((float2*)g_i_tmp)[o] = aE;
    float inv = g_invrnm;
    float2 ie = ((const float2*)item_emb)[o];
    float2 cm = ((const float2*)g_colmean)[lane];
    float2 acc;
    acc.x = (ie.x - cm.x) * inv + aE.x;
    acc.y = (ie.y - cm.y) * inv + aE.y;
    ((float2*)g_i_acc)[o] = acc;
}

// ----------------------------- layer-2 GNN + final combine -------------------
// 2 rows per warp, float4 per lane over 16 lanes.
__global__ __launch_bounds__(256) void k_gnn_u2(const float* __restrict__ imgU,
                                                const float* __restrict__ txtU,
                                                float* __restrict__ u_out) {
    int warp = (blockIdx.x * 256 + threadIdx.x) >> 5;
    int lane = threadIdx.x & 31;
    int row = warp * 2 + (lane >> 4);
    if (row >= NU) return;
    int c = lane & 15;
    const float4* __restrict__ X4 = (const float4*)g_i_tmp;
    const int* __restrict__ src = g_src_u;
    const float* __restrict__ val = g_val_u;
    int s = g_offs_u[row], e = g_offs_u[row + 1];
    float4 acc = make_float4(0.f, 0.f, 0.f, 0.f);
    int k = s;
    for (; k + 8 <= e; k += 8) {
        int js[8];
        float vs[8];
        float4 xs[8];
#pragma unroll
        for (int u = 0; u < 8; u++) {
            js[u] = __ldg(&src[k + u]);
            vs[u] = __ldg(&val[k + u]);
        }
#pragma unroll
        for (int u = 0; u < 8; u++) xs[u] = X4[js[u] * 16 + c];
#pragma unroll
        for (int u = 0; u < 8; u++) {
            acc.x += vs[u] * xs[u].x; acc.y += vs[u] * xs[u].y;
            acc.z += vs[u] * xs[u].z; acc.w += vs[u] * xs[u].w;
        }
    }
    for (; k < e; k++) {
        int j = __ldg(&src[k]);
        float v = __ldg(&val[k]);
        float4 x = X4[j * 16 + c];
        acc.x += v * x.x; acc.y += v * x.y; acc.z += v * x.z; acc.w += v * x.w;
    }
    int o = row * 16 + c;
    ((float4*)g_u_tmp)[o] = acc;
    float4 g = ((const float4*)g_u_acc)[o];
    float4 a = ((const float4*)imgU)[o];
    float4 b = ((const float4*)txtU)[o];
    float sa = a.x * a.x + a.y * a.y + a.z * a.z + a.w * a.w;
    float sb = b.x * b.x + b.y * b.y + b.z * b.z + b.w * b.w;
#pragma unroll
    for (int of = 8; of; of >>= 1) {
        sa += __shfl_xor_sync(0xffffffffu, sa, of);
        sb += __shfl_xor_sync(0xffffffffu, sb, of);
    }
    float ia = 0.55f / fmaxf(sqrtf(sa), 1e-12f);
    float ib = 0.55f / fmaxf(sqrtf(sb), 1e-12f);
    float4 r;
    r.x = (g.x + acc.x) * (1.0f / 3.0f) + a.x * ia + b.x * ib;
    r.y = (g.y + acc.y) * (1.0f / 3.0f) + a.y * ia + b.y * ib;
    r.z = (g.z + acc.z) * (1.0f / 3.0f) + a.z * ia + b.z * ib;
    r.w = (g.w + acc.w) * (1.0f / 3.0f) + a.w * ia + b.w * ib;
    ((float4*)u_out)[o] = r;
}

__global__ __launch_bounds__(256) void k_gnn_i2(const float* __restrict__ imgI,
                                                const float* __restrict__ txtI,
                                                float* __restrict__ i_out) {
    int warp = (blockIdx.x * 256 + threadIdx.x) >> 5;
    int lane = threadIdx.x & 31;
    int row = warp * 2 + (lane >> 4);
    if (row >= NI) return;
    int c = lane & 15;
    const float4* __restrict__ X4 = (const float4*)g_u_tmp;
    const int* __restrict__ src = g_src_i;
    const float* __restrict__ val = g_val_i;
    int s = g_offs_i[row], e = g_offs_i[row + 1];
    float4 acc = make_float4(0.f, 0.f, 0.f, 0.f);
    int k = s;
    for (; k + 8 <= e; k += 8) {
        int js[8];
        float vs[8];
        float4 xs[8];
#pragma unroll
        for (int u = 0; u < 8; u++) {
            js[u] = __ldg(&src[k + u]);
            vs[u] = __ldg(&val[k + u]);
        }
#pragma unroll
        for (int u = 0; u < 8; u++) xs[u] = X4[js[u] * 16 + c];
#pragma unroll
        for (int u = 0; u < 8; u++) {
            acc.x += vs[u] * xs[u].x; acc.y += vs[u] * xs[u].y;
            acc.z += vs[u] * xs[u].z; acc.w += vs[u] * xs[u].w;
        }
    }
    for (; k < e; k++) {
        int j = __ldg(&src[k]);
        float v = __ldg(&val[k]);
        float4 x = X4[j * 16 + c];
        acc.x += v * x.x; acc.y += v * x.y; acc.z += v * x.z; acc.w += v * x.w;
    }
    int o = row * 16 + c;
    float4 g = ((const float4*)g_i_acc)[o];
    float4 a = ((const float4*)imgI)[o];
    float4 b = ((const float4*)txtI)[o];
    float sa = a.x * a.x + a.y * a.y + a.z * a.z + a.w * a.w;
    float sb = b.x * b.x + b.y * b.y + b.z * b.z + b.w * b.w;
#pragma unroll
    for (int of = 8; of; of >>= 1) {
        sa += __shfl_xor_sync(0xffffffffu, sa, of);
        sb += __shfl_xor_sync(0xffffffffu, sb, of);
    }
    float ia = 0.55f / fmaxf(sqrtf(sa), 1e-12f);
    float ib = 0.55f / fmaxf(sqrtf(sb), 1e-12f);
    float4 r;
    r.x = (g.x + acc.x) * (1.0f / 3.0f) + a.x * ia + b.x * ib;
    r.y = (g.y + acc.y) * (1.0f / 3.0f) + a.y * ia + b.y * ib;
    r.z = (g.z + acc.z) * (1.0f / 3.0f) + a.z * ia + b.z * ib;
    r.w = (g.w + acc.w) * (1.0f / 3.0f) + a.w * ia + b.w * ib;
    ((float4*)i_out)[o] = r;
}

// ----------------------------- launch ---------------------------------------
extern "C" void kernel_launch(void* const* d_in, const int* in_sizes, int n_in,
                              void* d_out, int out_size) {
    const float* image_feats = (const float*)d_in[0];
    const float* text_feats  = (const float*)d_in[1];
    const float* user_emb    = (const float*)d_in[2];
    const float* item_emb    = (const float*)d_in[3];
    const float* W_img       = (const float*)d_in[4];
    const float* b_img       = (const float*)d_in[5];
    const float* W_txt       = (const float*)d_in[6];
    const float* b_txt       = (const float*)d_in[7];
    const float* val_ui      = (const float*)d_in[8];
    const float* val_iu      = (const float*)d_in[9];
    const int*   edge_u      = (const int*)d_in[10];
    const int*   edge_i      = (const int*)d_in[11];

    float* out        = (float*)d_out;
    float* u_out      = out;
    float* i_out      = u_out + (size_t)NU * DD;
    float* image_item = i_out + (size_t)NI * DD;
    float* text_item  = image_item + (size_t)NI * DD;
    float* image_user = text_item + (size_t)NI * DD;
    float* text_user  = image_user + (size_t)NU * DD;

    const int WU = (NU + 7) / 8;
    const int WI = (NI + 7) / 8;

    // CSR build
    k_init<<<256, 256>>>();
    k_hist<<<512, 256>>>(edge_u, edge_i);
    k_scan<<<2, 1024>>>();
    k_scatter<<<1024, 256>>>(edge_u, edge_i, val_ui, val_iu);

    // dense projections (register-tiled)
    k_linear<1024, 0><<<(NI + 127) / 128, 256>>>(image_feats, W_img, b_img, NI);
    k_linear<384, 1><<<(NI + 127) / 128, 256>>>(text_feats, W_txt, b_txt, NI);

    // stats + item normalize
    k_stats<<<SPART, 256>>>(user_emb, item_emb);
    k_stats_fin<<<1, 128>>>();
    k_norm_items<<<512, 256>>>(item_emb);

    // fused modal + GNN layer-1
    k_fused_u<<<WU, 256>>>(user_emb, image_user, text_user);
    k_fused_i<<<WI, 256>>>(item_emb, image_user, text_user, image_item, text_item);

    // GNN layer-2 fused with final combine (2 rows/warp)
    k_gnn_u2<<<(NU + 15) / 16, 256>>>(image_user, text_user, u_out);
    k_gnn_i2<<<(NI + 15) / 16, 256>>>(image_item, text_item, i_out);
}

// round 4
// speedup vs baseline: 2.1038x; 1.1383x over previous
#include <cuda_runtime.h>
#include <cuda_fp16.h>
#include <math.h>

#define NU 100000
#define NI 50000
#define DD 64
#define NE 2000000
#define NTOT (NU + NI)
#define SPART 128

// ----------------------------- scratch --------------------------------------
// fp16 gather tables (half2-packed, row = 32 half2 = 64 halves = 128B)
__device__ __half2 g_img_h[NI * 32];   // projected image feats
__device__ __half2 g_txt_h[NI * 32];   // projected text feats
__device__ __half2 g_in_h[NI * 32];    // normed item emb (layer-1 gather src)
__device__ __half2 g_imgU_h[NU * 32];  // image_user fp16 copy
__device__ __half2 g_txtU_h[NU * 32];  // text_user fp16 copy
__device__ __half2 g_ue1_h[NU * 32];   // u_g layer1 fp16
__device__ __half2 g_ie1_h[NI * 32];   // i_g layer1 fp16
__device__ __half2 g_ue2_h[NU * 32];   // u_g layer2 fp16

// fp32 accumulators (feed outputs)
__device__ float g_u_acc[NU * DD];
__device__ float g_i_acc[NI * DD];

__device__ int   g_cnt_u[NU];
__device__ int   g_offs_u[NU + 1];
__device__ int   g_cnt_i[NI];
__device__ int   g_offs_i[NI + 1];
__device__ unsigned short g_rank_u[NE];
__device__ unsigned short g_rank_i[NE];

__device__ int2  g_edge_u[NE];  // (src_item, val_ui) packed
__device__ int2  g_edge_i[NE];  // (src_user, val_iu) packed

__device__ float g_part[SPART * DD];
__device__ float g_part1[SPART];
__device__ float g_colmean[DD];
__device__ float g_invrnm;

// ----------------------------- f32x2 packed helpers -------------------------
__device__ __forceinline__ unsigned long long pk2(float x, float y) {
    unsigned long long r;
    asm("mov.b64 %0, {%1, %2};" : "=l"(r) : "f"(x), "f"(y));
    return r;
}
__device__ __forceinline__ void fma2(unsigned long long& d, unsigned long long a,
                                     unsigned long long b) {
    asm("fma.rn.f32x2 %0, %1, %2, %3;" : "=l"(d) : "l"(a), "l"(b), "l"(d));
}
__device__ __forceinline__ float2 upk2(unsigned long long v) {
    float2 f;
    asm("mov.b64 {%0, %1}, %2;" : "=f"(f.x), "=f"(f.y) : "l"(v));
    return f;
}

// ----------------------------- CSR build ------------------------------------
__global__ void k_init() {
    int i = blockIdx.x * blockDim.x + threadIdx.x;
    int st = gridDim.x * blockDim.x;
    for (int k = i; k < NU; k += st) g_cnt_u[k] = 0;
    for (int k = i; k < NI; k += st) g_cnt_i[k] = 0;
}

__global__ void k_hist(const int* __restrict__ eu, const int* __restrict__ ei) {
    int i = blockIdx.x * blockDim.x + threadIdx.x;
    int st = gridDim.x * blockDim.x;
    for (int e = i; e < NE; e += st) {
        g_rank_u[e] = (unsigned short)atomicAdd(&g_cnt_u[eu[e]], 1);
        g_rank_i[e] = (unsigned short)atomicAdd(&g_cnt_i[ei[e]], 1);
    }
}

__global__ void k_scan() {
    const int* cnt;
    int* offs;
    int n;
    if (blockIdx.x == 0) { cnt = g_cnt_u; offs = g_offs_u; n = NU; }
    else                 { cnt = g_cnt_i; offs = g_offs_i; n = NI; }

    __shared__ int warpsum[32];
    __shared__ int s_carry;
    int t = threadIdx.x, lane = t & 31, w = t >> 5;
    if (t == 0) { s_carry = 0; offs[0] = 0; }
    __syncthreads();

    for (int base = 0; base < n; base += 1024) {
        int i = base + t;
        int v = (i < n) ? cnt[i] : 0;
        int x = v;
#pragma unroll
        for (int d = 1; d < 32; d <<= 1) {
            int y = __shfl_up_sync(0xffffffffu, x, d);
            if (lane >= d) x += y;
        }
        if (lane == 31) warpsum[w] = x;
        __syncthreads();
        if (w == 0) {
            int ws = warpsum[lane];
#pragma unroll
            for (int d = 1; d < 32; d <<= 1) {
                int y = __shfl_up_sync(0xffffffffu, ws, d);
                if (lane >= d) ws += y;
            }
            warpsum[lane] = ws;
        }
        __syncthreads();
        int inc = x + (w ? warpsum[w - 1] : 0) + s_carry;
        if (i < n) offs[i + 1] = inc;
        __syncthreads();
        if (t == 1023) s_carry = inc;
        __syncthreads();
    }
}

__global__ void k_scatter(const int* __restrict__ eu, const int* __restrict__ ei,
                          const float* __restrict__ vui, const float* __restrict__ viu) {
    int i = blockIdx.x * blockDim.x + threadIdx.x;
    int st = gridDim.x * blockDim.x;
    for (int e = i; e < NE; e += st) {
        int u = eu[e], it = ei[e];
        int p = g_offs_u[u] + (int)g_rank_u[e];
        g_edge_u[p] = make_int2(it, __float_as_int(vui[e]));
        int q = g_offs_i[it] + (int)g_rank_i[e];
        g_edge_i[q] = make_int2(u, __float_as_int(viu[e]));
    }
}

// ----------------------------- dense linear (register-tiled, fp16 out) ------
template <int K, int WHICH>
__global__ __launch_bounds__(256) void k_linear(const float* __restrict__ A,
                                                const float* __restrict__ W,
                                                const float* __restrict__ bias, int M) {
    __shared__ float sA[128 * 20];
    __shared__ float sW[16 * 64];
    __half* out = (__half*)(WHICH ? g_txt_h : g_img_h);

    int t = threadIdx.x;
    int m0 = blockIdx.x * 128;
    int tx = t & 15;
    int ty = t >> 4;
    int ar = t >> 2;
    int ac4 = (t & 3) * 4;
    int wr = t >> 4;
    int wc4 = (t & 15) * 4;

    unsigned long long acc[8][2];
#pragma unroll
    for (int i = 0; i < 8; i++) { acc[i][0] = 0ull; acc[i][1] = 0ull; }

    float4 pa0, pa1, pw;
    {
        int m = m0 + ar;
        pa0 = (m < M) ? *(const float4*)&A[(size_t)m * K + ac4] : make_float4(0.f, 0.f, 0.f, 0.f);
        int m2 = m0 + ar + 64;
        pa1 = (m2 < M) ? *(const float4*)&A[(size_t)m2 * K + ac4] : make_float4(0.f, 0.f, 0.f, 0.f);
        pw = *(const float4*)&W[(size_t)wr * 64 + wc4];
    }

    for (int k0 = 0; k0 < K; k0 += 16) {
        *(float4*)&sA[ar * 20 + ac4] = pa0;
        *(float4*)&sA[(ar + 64) * 20 + ac4] = pa1;
        *(float4*)&sW[wr * 64 + wc4] = pw;
        __syncthreads();

        if (k0 + 16 < K) {
            int kn = k0 + 16;
            int m = m0 + ar;
            pa0 = (m < M) ? *(const float4*)&A[(size_t)m * K + kn + ac4]
                          : make_float4(0.f, 0.f, 0.f, 0.f);
            int m2 = m0 + ar + 64;
            pa1 = (m2 < M) ? *(const float4*)&A[(size_t)m2 * K + kn + ac4]
                           : make_float4(0.f, 0.f, 0.f, 0.f);
            pw = *(const float4*)&W[(size_t)(kn + wr) * 64 + wc4];
        }

#pragma unroll
        for (int kk = 0; kk < 16; kk++) {
            float4 w4 = *(const float4*)&sW[kk * 64 + tx * 4];
            unsigned long long wx = pk2(w4.x, w4.y);
            unsigned long long wy = pk2(w4.z, w4.w);
#pragma unroll
            for (int i = 0; i < 8; i++) {
                float a = sA[(ty * 8 + i) * 20 + kk];
                unsigned long long a2 = pk2(a, a);
                fma2(acc[i][0], a2, wx);
                fma2(acc[i][1], a2, wy);
            }
        }
        __syncthreads();
    }

    float4 bv = *(const float4*)&bias[tx * 4];
#pragma unroll
    for (int i = 0; i < 8; i++) {
        int m = m0 + ty * 8 + i;
        if (m < M) {
            float2 p0 = upk2(acc[i][0]), p1 = upk2(acc[i][1]);
            __half2 h0 = __floats2half2_rn(p0.x + bv.x, p0.y + bv.y);
            __half2 h1 = __floats2half2_rn(p1.x + bv.z, p1.y + bv.w);
            uint2 st;
            st.x = *reinterpret_cast<unsigned*>(&h0);
            st.y = *reinterpret_cast<unsigned*>(&h1);
            *(uint2*)&out[(size_t)m * 64 + tx * 4] = st;
        }
    }
}

// ----------------------------- single-pass stats -----------------------------
__global__ __launch_bounds__(256) void k_stats(const float* __restrict__ ue,
                                               const float* __restrict__ ie) {
    int t = threadIdx.x, col = t & 63, rg = t >> 6;
    float s = 0.f, q = 0.f;
    for (int row = blockIdx.x * 4 + rg; row < NTOT; row += SPART * 4) {
        const float* p = (row < NU) ? ue + (size_t)row * 64 : ie + (size_t)(row - NU) * 64;
        float x = p[col];
        s += x;
        q += x * x;
    }
    __shared__ float sm[256];
    __shared__ float sq[256];
    sm[t] = s;
    sq[t] = q;
    __syncthreads();
    if (t < 64) g_part[blockIdx.x * 64 + t] = sm[t] + sm[t + 64] + sm[t + 128] + sm[t + 192];
    for (int o = 128; o >= 32; o >>= 1) {
        if (t < o) sq[t] += sq[t + o];
        __syncthreads();
    }
    if (t < 32) {
        float v = sq[t];
#pragma unroll
        for (int o = 16; o; o >>= 1) v += __shfl_xor_sync(0xffffffffu, v, o);
        if (t == 0) g_part1[blockIdx.x] = v;
    }
}

__global__ void k_stats_fin() {
    __shared__ float smean[64];
    __shared__ float red[128];
    int t = threadIdx.x;
    if (t < 64) {
        float s = 0.f;
#pragma unroll 8
        for (int b = 0; b < SPART; b++) s += g_part[b * 64 + t];
        float m = s / (float)NTOT;
        g_colmean[t] = m;
        smean[t] = m;
    }
    __syncthreads();
    float v = g_part1[t];
    if (t < 64) v -= (float)NTOT * smean[t] * smean[t];
    red[t] = v;
    __syncthreads();
    for (int o = 64; o >= 32; o >>= 1) {
        if (t < o) red[t] += red[t + o];
        __syncthreads();
    }
    if (t < 32) {
        float x = red[t];
#pragma unroll
        for (int o = 16; o; o >>= 1) x += __shfl_xor_sync(0xffffffffu, x, o);
        if (t == 0) g_invrnm = rsqrtf(x / (float)NTOT + 1e-6f);
    }
}

// normalize ITEM embeddings -> fp16 table g_in_h
__global__ void k_norm_items(const float* __restrict__ ie) {
    float inv = g_invrnm;
    int st = gridDim.x * blockDim.x;
    int i0 = blockIdx.x * blockDim.x + threadIdx.x;
    const float4* i4 = (const float4*)ie;
    const float4* cm4 = (const float4*)g_colmean;
    __half* oh = (__half*)g_in_h;
    for (int idx = i0; idx < NI * 16; idx += st) {
        float4 v = i4[idx];
        float4 cm = cm4[idx & 15];
        __half2 h0 = __floats2half2_rn((v.x - cm.x) * inv, (v.y - cm.y) * inv);
        __half2 h1 = __floats2half2_rn((v.z - cm.z) * inv, (v.w - cm.w) * inv);
        uint2 s;
        s.x = *reinterpret_cast<unsigned*>(&h0);
        s.y = *reinterpret_cast<unsigned*>(&h1);
        *(uint2*)&oh[(size_t)idx * 4] = s;
    }
}

// ----------------------------- fused triple SpMM (fp16 gathers) -------------
__global__ __launch_bounds__(256) void k_fused_u(const float* __restrict__ user_emb,
                                                 float* __restrict__ imgU,
                                                 float* __restrict__ txtU) {
    int w = (blockIdx.x * 256 + threadIdx.x) >> 5;
    if (w >= NU) return;
    int lane = threadIdx.x & 31;
    const __half2* __restrict__ MI = g_img_h;
    const __half2* __restrict__ MT = g_txt_h;
    const __half2* __restrict__ ME = g_in_h;
    const int2* __restrict__ E = g_edge_u;
    int s = g_offs_u[w], e = g_offs_u[w + 1];
    float2 aI = make_float2(0.f, 0.f), aT = aI, aE = aI;
    int k = s;
    for (; k + 8 <= e; k += 8) {
        int2 ev[8];
        float2 xi[8], xt[8], xe[8];
#pragma unroll
        for (int u = 0; u < 8; u++) ev[u] = __ldg(&E[k + u]);
#pragma unroll
        for (int u = 0; u < 8; u++) {
            int b = ev[u].x * 32 + lane;
            xi[u] = __half22float2(MI[b]);
            xt[u] = __half22float2(MT[b]);
            xe[u] = __half22float2(ME[b]);
        }
#pragma unroll
        for (int u = 0; u < 8; u++) {
            float v = __int_as_float(ev[u].y);
            aI.x += v * xi[u].x; aI.y += v * xi[u].y;
            aT.x += v * xt[u].x; aT.y += v * xt[u].y;
            aE.x += v * xe[u].x; aE.y += v * xe[u].y;
        }
    }
    for (; k < e; k++) {
        int2 ev = __ldg(&E[k]);
        float v = __int_as_float(ev.y);
        int b = ev.x * 32 + lane;
        float2 i0 = __half22float2(MI[b]);
        float2 t0 = __half22float2(MT[b]);
        float2 e0 = __half22float2(ME[b]);
        aI.x += v * i0.x; aI.y += v * i0.y;
        aT.x += v * t0.x; aT.y += v * t0.y;
        aE.x += v * e0.x; aE.y += v * e0.y;
    }
    int o = w * 32 + lane;
    ((float2*)imgU)[o] = aI;
    ((float2*)txtU)[o] = aT;
    g_imgU_h[o] = __floats2half2_rn(aI.x, aI.y);
    g_txtU_h[o] = __floats2half2_rn(aT.x, aT.y);
    g_ue1_h[o] = __floats2half2_rn(aE.x, aE.y);
    float inv = g_invrnm;
    float2 ue = ((const float2*)user_emb)[o];
    float2 cm = ((const float2*)g_colmean)[lane];
    float2 acc;
    acc.x = (ue.x - cm.x) * inv + aE.x;
    acc.y = (ue.y - cm.y) * inv + aE.y;
    ((float2*)g_u_acc)[o] = acc;
}

__global__ __launch_bounds__(256) void k_fused_i(const float* __restrict__ item_emb,
                                                 float* __restrict__ imgI,
                                                 float* __restrict__ txtI) {
    int w = (blockIdx.x * 256 + threadIdx.x) >> 5;
    if (w >= NI) return;
    int lane = threadIdx.x & 31;
    const __half2* __restrict__ MI = g_imgU_h;
    const __half2* __restrict__ MT = g_txtU_h;
    const __half2* __restrict__ ME = g_ue1_h;
    const int2* __restrict__ E = g_edge_i;
    int s = g_offs_i[w], e = g_offs_i[w + 1];
    float2 aI = make_float2(0.f, 0.f), aT = aI, aE = aI;
    int k = s;
    for (; k + 8 <= e; k += 8) {
        int2 ev[8];
        float2 xi[8], xt[8], xe[8];
#pragma unroll
        for (int u = 0; u < 8; u++) ev[u] = __ldg(&E[k + u]);
#pragma unroll
        for (int u = 0; u < 8; u++) {
            int b = ev[u].x * 32 + lane;
            xi[u] = __half22float2(MI[b]);
            xt[u] = __half22float2(MT[b]);
            xe[u] = __half22float2(ME[b]);
        }
#pragma unroll
        for (int u = 0; u < 8; u++) {
            float v = __int_as_float(ev[u].y);
            aI.x += v * xi[u].x; aI.y += v * xi[u].y;
            aT.x += v * xt[u].x; aT.y += v * xt[u].y;
            aE.x += v * xe[u].x; aE.y += v * xe[u].y;
        }
    }
    for (; k < e; k++) {
        int2 ev = __ldg(&E[k]);
        float v = __int_as_float(ev.y);
        int b = ev.x * 32 + lane;
        float2 i0 = __half22float2(MI[b]);
        float2 t0 = __half22float2(MT[b]);
        float2 e0 = __half22float2(ME[b]);
        aI.x += v * i0.x; aI.y += v * i0.y;
        aT.x += v * t0.x; aT.y += v * t0.y;
        aE.x += v * e0.x; aE.y += v * e0.y;
    }
    int o = w * 32 + lane;
    ((float2*)imgI)[o] = aI;
    ((float2*)txtI)[o] = aT;
    g_ie1_h[o] = __floats2half2_rn(aE.x, aE.y);
    float inv = g_invrnm;
    float2 ie = ((const float2*)item_emb)[o];
    float2 cm = ((const float2*)g_colmean)[lane];
    float2 acc;
    acc.x = (ie.x - cm.x) * inv + aE.x;
    acc.y = (ie.y - cm.y) * inv + aE.y;
    ((float2*)g_i_acc)[o] = acc;
}

// ----------------------------- layer-2 GNN + final combine -------------------
// 2 rows per warp; 16 lanes x 4 cols via uint2 (2x half2) loads.
__global__ __launch_bounds__(256) void k_gnn_u2(const float* __restrict__ imgU,
                                                const float* __restrict__ txtU,
                                                float* __restrict__ u_out) {
    int warp = (blockIdx.x * 256 + threadIdx.x) >> 5;
    int lane = threadIdx.x & 31;
    int row = warp * 2 + (lane >> 4);
    if (row >= NU) return;
    int c = lane & 15;
    const __half* __restrict__ Xh = (const __half*)g_ie1_h;
    const int2* __restrict__ E = g_edge_u;
    int s = g_offs_u[row], e = g_offs_u[row + 1];
    float4 acc = make_float4(0.f, 0.f, 0.f, 0.f);
    int k = s;
    for (; k + 8 <= e; k += 8) {
        int2 ev[8];
        uint2 raw[8];
#pragma unroll
        for (int u = 0; u < 8; u++) ev[u] = __ldg(&E[k + u]);
#pragma unroll
        for (int u = 0; u < 8; u++) raw[u] = *(const uint2*)&Xh[(size_t)ev[u].x * 64 + c * 4];
#pragma unroll
        for (int u = 0; u < 8; u++) {
            float v = __int_as_float(ev[u].y);
            float2 x0 = __half22float2(*reinterpret_cast<__half2*>(&raw[u].x));
            float2 x1 = __half22float2(*reinterpret_cast<__half2*>(&raw[u].y));
            acc.x += v * x0.x; acc.y += v * x0.y;
            acc.z += v * x1.x; acc.w += v * x1.y;
        }
    }
    for (; k < e; k++) {
        int2 ev = __ldg(&E[k]);
        float v = __int_as_float(ev.y);
        uint2 raw = *(const uint2*)&Xh[(size_t)ev.x * 64 + c * 4];
        float2 x0 = __half22float2(*reinterpret_cast<__half2*>(&raw.x));
        float2 x1 = __half22float2(*reinterpret_cast<__half2*>(&raw.y));
        acc.x += v * x0.x; acc.y += v * x0.y;
        acc.z += v * x1.x; acc.w += v * x1.y;
    }
    int o = row * 16 + c;
    {
        __half2 h0 = __floats2half2_rn(acc.x, acc.y);
        __half2 h1 = __floats2half2_rn(acc.z, acc.w);
        uint2 st;
        st.x = *reinterpret_cast<unsigned*>(&h0);
        st.y = *reinterpret_cast<unsigned*>(&h1);
        *(uint2*)&((__half*)g_ue2_h)[(size_t)row * 64 + c * 4] = st;
    }
    float4 g = ((const float4*)g_u_acc)[o];
    float4 a = ((const float4*)imgU)[o];
    float4 b = ((const float4*)txtU)[o];
    float sa = a.x * a.x + a.y * a.y + a.z * a.z + a.w * a.w;
    float sb = b.x * b.x + b.y * b.y + b.z * b.z + b.w * b.w;
#pragma unroll
    for (int of = 8; of; of >>= 1) {
        sa += __shfl_xor_sync(0xffffffffu, sa, of);
        sb += __shfl_xor_sync(0xffffffffu, sb, of);
    }
    float ia = 0.55f / fmaxf(sqrtf(sa), 1e-12f);
    float ib = 0.55f / fmaxf(sqrtf(sb), 1e-12f);
    float4 r;
    r.x = (g.x + acc.x) * (1.0f / 3.0f) + a.x * ia + b.x * ib;
    r.y = (g.y + acc.y) * (1.0f / 3.0f) + a.y * ia + b.y * ib;
    r.z = (g.z + acc.z) * (1.0f / 3.0f) + a.z * ia + b.z * ib;
    r.w = (g.w + acc.w) * (1.0f / 3.0f) + a.w * ia + b.w * ib;
    ((float4*)u_out)[o] = r;
}

__global__ __launch_bounds__(256) void k_gnn_i2(const float* __restrict__ imgI,
                                                const float* __restrict__ txtI,
                                                float* __restrict__ i_out) {
    int warp = (blockIdx.x * 256 + threadIdx.x) >> 5;
    int lane = threadIdx.x & 31;
    int row = warp * 2 + (lane >> 4);
    if (row >= NI) return;
    int c = lane & 15;
    const __half* __restrict__ Xh = (const __half*)g_ue2_h;
    const int2* __restrict__ E = g_edge_i;
    int s = g_offs_i[row], e = g_offs_i[row + 1];
    float4 acc = make_float4(0.f, 0.f, 0.f, 0.f);
    int k = s;
    for (; k + 8 <= e; k += 8) {
        int2 ev[8];
        uint2 raw[8];
#pragma unroll
        for (int u = 0; u < 8; u++) ev[u] = __ldg(&E[k + u]);
#pragma unroll
        for (int u = 0; u < 8; u++) raw[u] = *(const uint2*)&Xh[(size_t)ev[u].x * 64 + c * 4];
#pragma unroll
        for (int u = 0; u < 8; u++) {
            float v = __int_as_float(ev[u].y);
            float2 x0 = __half22float2(*reinterpret_cast<__half2*>(&raw[u].x));
            float2 x1 = __half22float2(*reinterpret_cast<__half2*>(&raw[u].y));
            acc.x += v * x0.x; acc.y += v * x0.y;
            acc.z += v * x1.x; acc.w += v * x1.y;
        }
    }
    for (; k < e; k++) {
        int2 ev = __ldg(&E[k]);
        float v = __int_as_float(ev.y);
        uint2 raw = *(const uint2*)&Xh[(size_t)ev.x * 64 + c * 4];
        float2 x0 = __half22float2(*reinterpret_cast<__half2*>(&raw.x));
        float2 x1 = __half22float2(*reinterpret_cast<__half2*>(&raw.y));
        acc.x += v * x0.x; acc.y += v * x0.y;
        acc.z += v * x1.x; acc.w += v * x1.y;
    }
    int o = row * 16 + c;
    float4 g = ((const float4*)g_i_acc)[o];
    float4 a = ((const float4*)imgI)[o];
    float4 b = ((const float4*)txtI)[o];
    float sa = a.x * a.x + a.y * a.y + a.z * a.z + a.w * a.w;
    float sb = b.x * b.x + b.y * b.y + b.z * b.z + b.w * b.w;
#pragma unroll
    for (int of = 8; of; of >>= 1) {
        sa += __shfl_xor_sync(0xffffffffu, sa, of);
        sb += __shfl_xor_sync(0xffffffffu, sb, of);
    }
    float ia = 0.55f / fmaxf(sqrtf(sa), 1e-12f);
    float ib = 0.55f / fmaxf(sqrtf(sb), 1e-12f);
    float4 r;
    r.x = (g.x + acc.x) * (1.0f / 3.0f) + a.x * ia + b.x * ib;
    r.y = (g.y + acc.y) * (1.0f / 3.0f) + a.y * ia + b.y * ib;
    r.z = (g.z + acc.z) * (1.0f / 3.0f) + a.z * ia + b.z * ib;
    r.w = (g.w + acc.w) * (1.0f / 3.0f) + a.w * ia + b.w * ib;
    ((float4*)i_out)[o] = r;
}

// ----------------------------- launch ---------------------------------------
extern "C" void kernel_launch(void* const* d_in, const int* in_sizes, int n_in,
                              void* d_out, int out_size) {
    const float* image_feats = (const float*)d_in[0];
    const float* text_feats  = (const float*)d_in[1];
    const float* user_emb    = (const float*)d_in[2];
    const float* item_emb    = (const float*)d_in[3];
    const float* W_img       = (const float*)d_in[4];
    const float* b_img       = (const float*)d_in[5];
    const float* W_txt       = (const float*)d_in[6];
    const float* b_txt       = (const float*)d_in[7];
    const float* val_ui      = (const float*)d_in[8];
    const float* val_iu      = (const float*)d_in[9];
    const int*   edge_u      = (const int*)d_in[10];
    const int*   edge_i      = (const int*)d_in[11];

    float* out        = (float*)d_out;
    float* u_out      = out;
    float* i_out      = u_out + (size_t)NU * DD;
    float* image_item = i_out + (size_t)NI * DD;
    float* text_item  = image_item + (size_t)NI * DD;
    float* image_user = text_item + (size_t)NI * DD;
    float* text_user  = image_user + (size_t)NU * DD;

    const int WU = (NU + 7) / 8;
    const int WI = (NI + 7) / 8;

    // CSR build + GEMM interleaved (image GEMM placed at launch #3 for ncu slot)
    k_init<<<256, 256>>>();
    k_hist<<<512, 256>>>(edge_u, edge_i);
    k_scan<<<2, 1024>>>();
    k_linear<1024, 0><<<(NI + 127) / 128, 256>>>(image_feats, W_img, b_img, NI);
    k_scatter<<<1024, 256>>>(edge_u, edge_i, val_ui, val_iu);
    k_linear<384, 1><<<(NI + 127) / 128, 256>>>(text_feats, W_txt, b_txt, NI);

    // stats + item normalize (fp16 table)
    k_stats<<<SPART, 256>>>(user_emb, item_emb);
    k_stats_fin<<<1, 128>>>();
    k_norm_items<<<512, 256>>>(item_emb);

    // fused modal + GNN layer-1 (fp16 gathers, fp32 outputs)
    k_fused_u<<<WU, 256>>>(user_emb, image_user, text_user);
    k_fused_i<<<WI, 256>>>(item_emb, image_item, text_item);

    // GNN layer-2 fused with final combine
    k_gnn_u2<<<(NU + 15) / 16, 256>>>(image_user, text_user, u_out);
    k_gnn_i2<<<(NI + 15) / 16, 256>>>(image_item, text_item, i_out);
}

// round 7
// speedup vs baseline: 2.5300x; 1.2026x over previous
#include <cuda_runtime.h>
#include <cuda_fp16.h>
#include <math.h>

#define NU 100000
#define NI 50000
#define DD 64
#define NE 2000000
#define NTOT (NU + NI)
#define SPART 128

// ----------------------------- scratch --------------------------------------
__device__ __half2 g_img_h[NI * 32];
__device__ __half2 g_txt_h[NI * 32];
__device__ __half2 g_in_h[NI * 32];
__device__ __half2 g_imgU_h[NU * 32];
__device__ __half2 g_txtU_h[NU * 32];
__device__ __half2 g_ue1_h[NU * 32];
__device__ __half2 g_ie1_h[NI * 32];
__device__ __half2 g_ue2_h[NU * 32];

__device__ float g_u_acc[NU * DD];
__device__ float g_i_acc[NI * DD];

__device__ int   g_cnt_u[NU];
__device__ int   g_offs_u[NU + 1];
__device__ int   g_cnt_i[NI];
__device__ int   g_offs_i[NI + 1];
__device__ unsigned short g_rank_u[NE];
__device__ unsigned short g_rank_i[NE];

__device__ int2  g_edge_u[NE];
__device__ int2  g_edge_i[NE];

__device__ float g_part[SPART * DD];
__device__ float g_part1[SPART];
__device__ float g_colmean[DD];
__device__ float g_invrnm;

// ----------------------------- CSR build ------------------------------------
__global__ void k_init() {
    int i = blockIdx.x * blockDim.x + threadIdx.x;
    int st = gridDim.x * blockDim.x;
    for (int k = i; k < NU; k += st) g_cnt_u[k] = 0;
    for (int k = i; k < NI; k += st) g_cnt_i[k] = 0;
}

__global__ void k_hist(const int* __restrict__ eu, const int* __restrict__ ei) {
    int i = blockIdx.x * blockDim.x + threadIdx.x;
    int st = gridDim.x * blockDim.x;
    for (int e = i; e < NE; e += st) {
        g_rank_u[e] = (unsigned short)atomicAdd(&g_cnt_u[eu[e]], 1);
        g_rank_i[e] = (unsigned short)atomicAdd(&g_cnt_i[ei[e]], 1);
    }
}

__global__ void k_scan() {
    const int* cnt;
    int* offs;
    int n;
    if (blockIdx.x == 0) { cnt = g_cnt_u; offs = g_offs_u; n = NU; }
    else                 { cnt = g_cnt_i; offs = g_offs_i; n = NI; }

    __shared__ int warpsum[32];
    __shared__ int s_carry;
    int t = threadIdx.x, lane = t & 31, w = t >> 5;
    if (t == 0) { s_carry = 0; offs[0] = 0; }
    __syncthreads();

    for (int base = 0; base < n; base += 1024) {
        int i = base + t;
        int v = (i < n) ? cnt[i] : 0;
        int x = v;
#pragma unroll
        for (int d = 1; d < 32; d <<= 1) {
            int y = __shfl_up_sync(0xffffffffu, x, d);
            if (lane >= d) x += y;
        }
        if (lane == 31) warpsum[w] = x;
        __syncthreads();
        if (w == 0) {
            int ws = warpsum[lane];
#pragma unroll
            for (int d = 1; d < 32; d <<= 1) {
                int y = __shfl_up_sync(0xffffffffu, ws, d);
                if (lane >= d) ws += y;
            }
            warpsum[lane] = ws;
        }
        __syncthreads();
        int inc = x + (w ? warpsum[w - 1] : 0) + s_carry;
        if (i < n) offs[i + 1] = inc;
        __syncthreads();
        if (t == 1023) s_carry = inc;
        __syncthreads();
    }
}

__global__ void k_scatter(const int* __restrict__ eu, const int* __restrict__ ei,
                          const float* __restrict__ vui, const float* __restrict__ viu) {
    int i = blockIdx.x * blockDim.x + threadIdx.x;
    int st = gridDim.x * blockDim.x;
    for (int e = i; e < NE; e += st) {
        int u = eu[e], it = ei[e];
        int p = g_offs_u[u] + (int)g_rank_u[e];
        g_edge_u[p] = make_int2(it, __float_as_int(vui[e]));
        int q = g_offs_i[it] + (int)g_rank_i[e];
        g_edge_i[q] = make_int2(u, __float_as_int(viu[e]));
    }
}

// ----------------------------- tensor-core linear ----------------------------
__device__ __forceinline__ void mma16816(float* c, unsigned a0, unsigned a1,
                                         unsigned a2, unsigned a3,
                                         unsigned b0, unsigned b1) {
    asm volatile(
        "mma.sync.aligned.m16n8k16.row.col.f32.f16.f16.f32 "
        "{%0,%1,%2,%3}, {%4,%5,%6,%7}, {%8,%9}, {%0,%1,%2,%3};"
        : "+f"(c[0]), "+f"(c[1]), "+f"(c[2]), "+f"(c[3])
        : "r"(a0), "r"(a1), "r"(a2), "r"(a3), "r"(b0), "r"(b1));
}

__device__ __forceinline__ unsigned h2u(float lo, float hi) {
    __half2 h = __floats2half2_rn(lo, hi);
    return *reinterpret_cast<unsigned*>(&h);
}

// WHICH: 0 -> g_img_h, 1 -> g_txt_h (selected in DEVICE code)
template <int K, int WHICH>
__global__ __launch_bounds__(512) void k_linear_mma(const float* __restrict__ A,
                                                    const float* __restrict__ W,
                                                    const float* __restrict__ bias,
                                                    int M) {
    constexpr int PS = K + 8;        // padded k-stride in halves
    extern __shared__ __half sWT[];  // [64][PS]
    __half* out = (__half*)(WHICH ? g_txt_h : g_img_h);

    int tid = threadIdx.x;
    for (int i = tid; i < K * 64; i += 512) {
        int k = i >> 6, n = i & 63;
        sWT[n * PS + k] = __float2half(W[(size_t)k * 64 + n]);
    }
    __syncthreads();

    int warp = tid >> 5, lane = tid & 31;
    int g = lane >> 2, q = lane & 3;
    int m_base = blockIdx.x * 256 + warp * 16;
    int row0 = m_base + g, row1 = row0 + 8;
    int r0 = min(row0, M - 1), r1 = min(row1, M - 1);
    const float* A0 = A + (size_t)r0 * K + q * 2;
    const float* A1 = A + (size_t)r1 * K + q * 2;

    float acc[8][4];
#pragma unroll
    for (int nt = 0; nt < 8; nt++)
#pragma unroll
        for (int j = 0; j < 4; j++) acc[nt][j] = 0.f;

#pragma unroll 2
    for (int kc = 0; kc < K; kc += 16) {
        float2 f0 = *(const float2*)(A0 + kc);
        float2 f1 = *(const float2*)(A1 + kc);
        float2 f2 = *(const float2*)(A0 + kc + 8);
        float2 f3 = *(const float2*)(A1 + kc + 8);
        unsigned a0 = h2u(f0.x, f0.y);
        unsigned a1 = h2u(f1.x, f1.y);
        unsigned a2 = h2u(f2.x, f2.y);
        unsigned a3 = h2u(f3.x, f3.y);
        int kb = kc + q * 2;
#pragma unroll
        for (int nt = 0; nt < 8; nt++) {
            int n = nt * 8 + g;
            unsigned b0 = *(const unsigned*)&sWT[n * PS + kb];
            unsigned b1 = *(const unsigned*)&sWT[n * PS + kb + 8];
            mma16816(acc[nt], a0, a1, a2, a3, b0, b1);
        }
    }

#pragma unroll
    for (int nt = 0; nt < 8; nt++) {
        int col = nt * 8 + q * 2;
        float bx = bias[col], by = bias[col + 1];
        if (row0 < M) {
            __half2 h = __floats2half2_rn(acc[nt][0] + bx, acc[nt][1] + by);
            *(unsigned*)&out[(size_t)row0 * 64 + col] = *reinterpret_cast<unsigned*>(&h);
        }
        if (row1 < M) {
            __half2 h = __floats2half2_rn(acc[nt][2] + bx, acc[nt][3] + by);
            *(unsigned*)&out[(size_t)row1 * 64 + col] = *reinterpret_cast<unsigned*>(&h);
        }
    }
}

// ----------------------------- single-pass stats -----------------------------
__global__ __launch_bounds__(256) void k_stats(const float* __restrict__ ue,
                                               const float* __restrict__ ie) {
    int t = threadIdx.x, col = t & 63, rg = t >> 6;
    float s = 0.f, q = 0.f;
    for (int row = blockIdx.x * 4 + rg; row < NTOT; row += SPART * 4) {
        const float* p = (row < NU) ? ue + (size_t)row * 64 : ie + (size_t)(row - NU) * 64;
        float x = p[col];
        s += x;
        q += x * x;
    }
    __shared__ float sm[256];
    __shared__ float sq[256];
    sm[t] = s;
    sq[t] = q;
    __syncthreads();
    if (t < 64) g_part[blockIdx.x * 64 + t] = sm[t] + sm[t + 64] + sm[t + 128] + sm[t + 192];
    for (int o = 128; o >= 32; o >>= 1) {
        if (t < o) sq[t] += sq[t + o];
        __syncthreads();
    }
    if (t < 32) {
        float v = sq[t];
#pragma unroll
        for (int o = 16; o; o >>= 1) v += __shfl_xor_sync(0xffffffffu, v, o);
        if (t == 0) g_part1[blockIdx.x] = v;
    }
}

__global__ void k_stats_fin() {
    __shared__ float smean[64];
    __shared__ float red[128];
    int t = threadIdx.x;
    if (t < 64) {
        float s = 0.f;
#pragma unroll 8
        for (int b = 0; b < SPART; b++) s += g_part[b * 64 + t];
        float m = s / (float)NTOT;
        g_colmean[t] = m;
        smean[t] = m;
    }
    __syncthreads();
    float v = g_part1[t];
    if (t < 64) v -= (float)NTOT * smean[t] * smean[t];
    red[t] = v;
    __syncthreads();
    for (int o = 64; o >= 32; o >>= 1) {
        if (t < o) red[t] += red[t + o];
        __syncthreads();
    }
    if (t < 32) {
        float x = red[t];
#pragma unroll
        for (int o = 16; o; o >>= 1) x += __shfl_xor_sync(0xffffffffu, x, o);
        if (t == 0) g_invrnm = rsqrtf(x / (float)NTOT + 1e-6f);
    }
}

__global__ void k_norm_items(const float* __restrict__ ie) {
    float inv = g_invrnm;
    int st = gridDim.x * blockDim.x;
    int i0 = blockIdx.x * blockDim.x + threadIdx.x;
    const float4* i4 = (const float4*)ie;
    const float4* cm4 = (const float4*)g_colmean;
    __half* oh = (__half*)g_in_h;
    for (int idx = i0; idx < NI * 16; idx += st) {
        float4 v = i4[idx];
        float4 cm = cm4[idx & 15];
        __half2 h0 = __floats2half2_rn((v.x - cm.x) * inv, (v.y - cm.y) * inv);
        __half2 h1 = __floats2half2_rn((v.z - cm.z) * inv, (v.w - cm.w) * inv);
        uint2 s;
        s.x = *reinterpret_cast<unsigned*>(&h0);
        s.y = *reinterpret_cast<unsigned*>(&h1);
        *(uint2*)&oh[(size_t)idx * 4] = s;
    }
}

// ----------------------------- fused triple SpMM (fp16 gathers) -------------
__global__ __launch_bounds__(256) void k_fused_u(const float* __restrict__ user_emb,
                                                 float* __restrict__ imgU,
                                                 float* __restrict__ txtU) {
    int w = (blockIdx.x * 256 + threadIdx.x) >> 5;
    if (w >= NU) return;
    int lane = threadIdx.x & 31;
    const __half2* __restrict__ MI = g_img_h;
    const __half2* __restrict__ MT = g_txt_h;
    const __half2* __restrict__ ME = g_in_h;
    const int2* __restrict__ E = g_edge_u;
    int s = g_offs_u[w], e = g_offs_u[w + 1];
    float2 aI = make_float2(0.f, 0.f), aT = aI, aE = aI;
    int k = s;
    for (; k + 8 <= e; k += 8) {
        int2 ev[8];
        float2 xi[8], xt[8], xe[8];
#pragma unroll
        for (int u = 0; u < 8; u++) ev[u] = __ldg(&E[k + u]);
#pragma unroll
        for (int u = 0; u < 8; u++) {
            int b = ev[u].x * 32 + lane;
            xi[u] = __half22float2(MI[b]);
            xt[u] = __half22float2(MT[b]);
            xe[u] = __half22float2(ME[b]);
        }
#pragma unroll
        for (int u = 0; u < 8; u++) {
            float v = __int_as_float(ev[u].y);
            aI.x += v * xi[u].x; aI.y += v * xi[u].y;
            aT.x += v * xt[u].x; aT.y += v * xt[u].y;
            aE.x += v * xe[u].x; aE.y += v * xe[u].y;
        }
    }
    for (; k < e; k++) {
        int2 ev = __ldg(&E[k]);
        float v = __int_as_float(ev.y);
        int b = ev.x * 32 + lane;
        float2 i0 = __half22float2(MI[b]);
        float2 t0 = __half22float2(MT[b]);
        float2 e0 = __half22float2(ME[b]);
        aI.x += v * i0.x; aI.y += v * i0.y;
        aT.x += v * t0.x; aT.y += v * t0.y;
        aE.x += v * e0.x; aE.y += v * e0.y;
    }
    int o = w * 32 + lane;
    ((float2*)imgU)[o] = aI;
    ((float2*)txtU)[o] = aT;
    g_imgU_h[o] = __floats2half2_rn(aI.x, aI.y);
    g_txtU_h[o] = __floats2half2_rn(aT.x, aT.y);
    g_ue1_h[o] = __floats2half2_rn(aE.x, aE.y);
    float inv = g_invrnm;
    float2 ue = ((const float2*)user_emb)[o];
    float2 cm = ((const float2*)g_colmean)[lane];
    float2 acc;
    acc.x = (ue.x - cm.x) * inv + aE.x;
    acc.y = (ue.y - cm.y) * inv + aE.y;
    ((float2*)g_u_acc)[o] = acc;
}

__global__ __launch_bounds__(256) void k_fused_i(const float* __restrict__ item_emb,
                                                 float* __restrict__ imgI,
                                                 float* __restrict__ txtI) {
    int w = (blockIdx.x * 256 + threadIdx.x) >> 5;
    if (w >= NI) return;
    int lane = threadIdx.x & 31;
    const __half2* __restrict__ MI = g_imgU_h;
    const __half2* __restrict__ MT = g_txtU_h;
    const __half2* __restrict__ ME = g_ue1_h;
    const int2* __restrict__ E = g_edge_i;
    int s = g_offs_i[w], e = g_offs_i[w + 1];
    float2 aI = make_float2(0.f, 0.f), aT = aI, aE = aI;
    int k = s;
    for (; k + 8 <= e; k += 8) {
        int2 ev[8];
        float2 xi[8], xt[8], xe[8];
#pragma unroll
        for (int u = 0; u < 8; u++) ev[u] = __ldg(&E[k + u]);
#pragma unroll
        for (int u = 0; u < 8; u++) {
            int b = ev[u].x * 32 + lane;
            xi[u] = __half22float2(MI[b]);
            xt[u] = __half22float2(MT[b]);
            xe[u] = __half22float2(ME[b]);
        }
#pragma unroll
        for (int u = 0; u < 8; u++) {
            float v = __int_as_float(ev[u].y);
            aI.x += v * xi[u].x; aI.y += v * xi[u].y;
            aT.x += v * xt[u].x; aT.y += v * xt[u].y;
            aE.x += v * xe[u].x; aE.y += v * xe[u].y;
        }
    }
    for (; k < e; k++) {
        int2 ev = __ldg(&E[k]);
        float v = __int_as_float(ev.y);
        int b = ev.x * 32 + lane;
        float2 i0 = __half22float2(MI[b]);
        float2 t0 = __half22float2(MT[b]);
        float2 e0 = __half22float2(ME[b]);
        aI.x += v * i0.x; aI.y += v * i0.y;
        aT.x += v * t0.x; aT.y += v * t0.y;
        aE.x += v * e0.x; aE.y += v * e0.y;
    }
    int o = w * 32 + lane;
    ((float2*)imgI)[o] = aI;
    ((float2*)txtI)[o] = aT;
    g_ie1_h[o] = __floats2half2_rn(aE.x, aE.y);
    float inv = g_invrnm;
    float2 ie = ((const float2*)item_emb)[o];
    float2 cm = ((const float2*)g_colmean)[lane];
    float2 acc;
    acc.x = (ie.x - cm.x) * inv + aE.x;
    acc.y = (ie.y - cm.y) * inv + aE.y;
    ((float2*)g_i_acc)[o] = acc;
}

// ----------------------------- layer-2 GNN + final combine -------------------
__global__ __launch_bounds__(256) void k_gnn_u2(const float* __restrict__ imgU,
                                                const float* __restrict__ txtU,
                                                float* __restrict__ u_out) {
    int warp = (blockIdx.x * 256 + threadIdx.x) >> 5;
    int lane = threadIdx.x & 31;
    int row = warp * 2 + (lane >> 4);
    if (row >= NU) return;
    int c = lane & 15;
    const __half* __restrict__ Xh = (const __half*)g_ie1_h;
    const int2* __restrict__ E = g_edge_u;
    int s = g_offs_u[row], e = g_offs_u[row + 1];
    float4 acc = make_float4(0.f, 0.f, 0.f, 0.f);
    int k = s;
    for (; k + 8 <= e; k += 8) {
        int2 ev[8];
        uint2 raw[8];
#pragma unroll
        for (int u = 0; u < 8; u++) ev[u] = __ldg(&E[k + u]);
#pragma unroll
        for (int u = 0; u < 8; u++) raw[u] = *(const uint2*)&Xh[(size_t)ev[u].x * 64 + c * 4];
#pragma unroll
        for (int u = 0; u < 8; u++) {
            float v = __int_as_float(ev[u].y);
            float2 x0 = __half22float2(*reinterpret_cast<__half2*>(&raw[u].x));
            float2 x1 = __half22float2(*reinterpret_cast<__half2*>(&raw[u].y));
            acc.x += v * x0.x; acc.y += v * x0.y;
            acc.z += v * x1.x; acc.w += v * x1.y;
        }
    }
    for (; k < e; k++) {
        int2 ev = __ldg(&E[k]);
        float v = __int_as_float(ev.y);
        uint2 raw = *(const uint2*)&Xh[(size_t)ev.x * 64 + c * 4];
        float2 x0 = __half22float2(*reinterpret_cast<__half2*>(&raw.x));
        float2 x1 = __half22float2(*reinterpret_cast<__half2*>(&raw.y));
        acc.x += v * x0.x; acc.y += v * x0.y;
        acc.z += v * x1.x; acc.w += v * x1.y;
    }
    int o = row * 16 + c;
    {
        __half2 h0 = __floats2half2_rn(acc.x, acc.y);
        __half2 h1 = __floats2half2_rn(acc.z, acc.w);
        uint2 st;
        st.x = *reinterpret_cast<unsigned*>(&h0);
        st.y = *reinterpret_cast<unsigned*>(&h1);
        *(uint2*)&((__half*)g_ue2_h)[(size_t)row * 64 + c * 4] = st;
    }
    float4 g = ((const float4*)g_u_acc)[o];
    float4 a = ((const float4*)imgU)[o];
    float4 b = ((const float4*)txtU)[o];
    float sa = a.x * a.x + a.y * a.y + a.z * a.z + a.w * a.w;
    float sb = b.x * b.x + b.y * b.y + b.z * b.z + b.w * b.w;
#pragma unroll
    for (int of = 8; of; of >>= 1) {
        sa += __shfl_xor_sync(0xffffffffu, sa, of);
        sb += __shfl_xor_sync(0xffffffffu, sb, of);
    }
    float ia = 0.55f / fmaxf(sqrtf(sa), 1e-12f);
    float ib = 0.55f / fmaxf(sqrtf(sb), 1e-12f);
    float4 r;
    r.x = (g.x + acc.x) * (1.0f / 3.0f) + a.x * ia + b.x * ib;
    r.y = (g.y + acc.y) * (1.0f / 3.0f) + a.y * ia + b.y * ib;
    r.z = (g.z + acc.z) * (1.0f / 3.0f) + a.z * ia + b.z * ib;
    r.w = (g.w + acc.w) * (1.0f / 3.0f) + a.w * ia + b.w * ib;
    ((float4*)u_out)[o] = r;
}

__global__ __launch_bounds__(256) void k_gnn_i2(const float* __restrict__ imgI,
                                                const float* __restrict__ txtI,
                                                float* __restrict__ i_out) {
    int warp = (blockIdx.x * 256 + threadIdx.x) >> 5;
    int lane = threadIdx.x & 31;
    int row = warp * 2 + (lane >> 4);
    if (row >= NI) return;
    int c = lane & 15;
    const __half* __restrict__ Xh = (const __half*)g_ue2_h;
    const int2* __restrict__ E = g_edge_i;
    int s = g_offs_i[row], e = g_offs_i[row + 1];
    float4 acc = make_float4(0.f, 0.f, 0.f, 0.f);
    int k = s;
    for (; k + 8 <= e; k += 8) {
        int2 ev[8];
        uint2 raw[8];
#pragma unroll
        for (int u = 0; u < 8; u++) ev[u] = __ldg(&E[k + u]);
#pragma unroll
        for (int u = 0; u < 8; u++) raw[u] = *(const uint2*)&Xh[(size_t)ev[u].x * 64 + c * 4];
#pragma unroll
        for (int u = 0; u < 8; u++) {
            float v = __int_as_float(ev[u].y);
            float2 x0 = __half22float2(*reinterpret_cast<__half2*>(&raw[u].x));
            float2 x1 = __half22float2(*reinterpret_cast<__half2*>(&raw[u].y));
            acc.x += v * x0.x; acc.y += v * x0.y;
            acc.z += v * x1.x; acc.w += v * x1.y;
        }
    }
    for (; k < e; k++) {
        int2 ev = __ldg(&E[k]);
        float v = __int_as_float(ev.y);
        uint2 raw = *(const uint2*)&Xh[(size_t)ev.x * 64 + c * 4];
        float2 x0 = __half22float2(*reinterpret_cast<__half2*>(&raw.x));
        float2 x1 = __half22float2(*reinterpret_cast<__half2*>(&raw.y));
        acc.x += v * x0.x; acc.y += v * x0.y;
        acc.z += v * x1.x; acc.w += v * x1.y;
    }
    int o = row * 16 + c;
    float4 g = ((const float4*)g_i_acc)[o];
    float4 a = ((const float4*)imgI)[o];
    float4 b = ((const float4*)txtI)[o];
    float sa = a.x * a.x + a.y * a.y + a.z * a.z + a.w * a.w;
    float sb = b.x * b.x + b.y * b.y + b.z * b.z + b.w * b.w;
#pragma unroll
    for (int of = 8; of; of >>= 1) {
        sa += __shfl_xor_sync(0xffffffffu, sa, of);
        sb += __shfl_xor_sync(0xffffffffu, sb, of);
    }
    float ia = 0.55f / fmaxf(sqrtf(sa), 1e-12f);
    float ib = 0.55f / fmaxf(sqrtf(sb), 1e-12f);
    float4 r;
    r.x = (g.x + acc.x) * (1.0f / 3.0f) + a.x * ia + b.x * ib;
    r.y = (g.y + acc.y) * (1.0f / 3.0f) + a.y * ia + b.y * ib;
    r.z = (g.z + acc.z) * (1.0f / 3.0f) + a.z * ia + b.z * ib;
    r.w = (g.w + acc.w) * (1.0f / 3.0f) + a.w * ia + b.w * ib;
    ((float4*)i_out)[o] = r;
}

// ----------------------------- launch ---------------------------------------
extern "C" void kernel_launch(void* const* d_in, const int* in_sizes, int n_in,
                              void* d_out, int out_size) {
    const float* image_feats = (const float*)d_in[0];
    const float* text_feats  = (const float*)d_in[1];
    const float* user_emb    = (const float*)d_in[2];
    const float* item_emb    = (const float*)d_in[3];
    const float* W_img       = (const float*)d_in[4];
    const float* b_img       = (const float*)d_in[5];
    const float* W_txt       = (const float*)d_in[6];
    const float* b_txt       = (const float*)d_in[7];
    const float* val_ui      = (const float*)d_in[8];
    const float* val_iu      = (const float*)d_in[9];
    const int*   edge_u      = (const int*)d_in[10];
    const int*   edge_i      = (const int*)d_in[11];

    float* out        = (float*)d_out;
    float* u_out      = out;
    float* i_out      = u_out + (size_t)NU * DD;
    float* image_item = i_out + (size_t)NI * DD;
    float* text_item  = image_item + (size_t)NI * DD;
    float* image_user = text_item + (size_t)NI * DD;
    float* text_user  = image_user + (size_t)NU * DD;

    const int WU = (NU + 7) / 8;
    const int WI = (NI + 7) / 8;

    const int SM_IMG = 64 * (1024 + 8) * 2;  // 132096 B
    const int SM_TXT = 64 * (384 + 8) * 2;   // 50176 B
    cudaFuncSetAttribute(k_linear_mma<1024, 0>,
                         cudaFuncAttributeMaxDynamicSharedMemorySize, SM_IMG);
    cudaFuncSetAttribute(k_linear_mma<384, 1>,
                         cudaFuncAttributeMaxDynamicSharedMemorySize, SM_TXT);

    // CSR build + tensor-core GEMMs interleaved
    k_init<<<256, 256>>>();
    k_hist<<<512, 256>>>(edge_u, edge_i);
    k_scan<<<2, 1024>>>();
    k_linear_mma<1024, 0><<<(NI + 255) / 256, 512, SM_IMG>>>(image_feats, W_img, b_img, NI);
    k_scatter<<<1024, 256>>>(edge_u, edge_i, val_ui, val_iu);
    k_linear_mma<384, 1><<<(NI + 255) / 256, 512, SM_TXT>>>(text_feats, W_txt, b_txt, NI);

    // stats + item normalize
    k_stats<<<SPART, 256>>>(user_emb, item_emb);
    k_stats_fin<<<1, 128>>>();
    k_norm_items<<<512, 256>>>(item_emb);

    // fused modal + GNN layer-1
    k_fused_u<<<WU, 256>>>(user_emb, image_user, text_user);
    k_fused_i<<<WI, 256>>>(item_emb, image_item, text_item);

    // GNN layer-2 fused with final combine
    k_gnn_u2<<<(NU + 15) / 16, 256>>>(image_user, text_user, u_out);
    k_gnn_i2<<<(NI + 15) / 16, 256>>>(image_item, text_item, i_out);
}

// round 8
// speedup vs baseline: 2.5778x; 1.0189x over previous
#include <cuda_runtime.h>
#include <cuda_fp16.h>
#include <math.h>

#define NU 100000
#define NI 50000
#define DD 64
#define NE 2000000
#define NTOT (NU + NI)
#define SPART 128

// ----------------------------- scratch --------------------------------------
__device__ __half2 g_img_h[NI * 32];
__device__ __half2 g_txt_h[NI * 32];
__device__ __half2 g_in_h[NI * 32];
__device__ __half2 g_imgU_h[NU * 32];
__device__ __half2 g_txtU_h[NU * 32];
__device__ __half2 g_ue1_h[NU * 32];
__device__ __half2 g_ie1_h[NI * 32];
__device__ __half2 g_ue2_h[NU * 32];

__device__ float g_u_acc[NU * DD];
__device__ float g_i_acc[NI * DD];

__device__ int   g_cnt_u[NU];
__device__ int   g_offs_u[NU + 1];
__device__ int   g_cnt_i[NI];
__device__ int   g_offs_i[NI + 1];
__device__ unsigned short g_rank_u[NE];
__device__ unsigned short g_rank_i[NE];

__device__ int2  g_edge_u[NE];
__device__ int2  g_edge_i[NE];

__device__ float g_part[SPART * DD];
__device__ float g_part1[SPART];
__device__ float g_colmean[DD];
__device__ float g_invrnm;

// ----------------------------- CSR build ------------------------------------
__global__ void k_hist(const int* __restrict__ eu, const int* __restrict__ ei) {
    int i = blockIdx.x * blockDim.x + threadIdx.x;
    int st = gridDim.x * blockDim.x;
    for (int e = i; e < NE; e += st) {
        g_rank_u[e] = (unsigned short)atomicAdd(&g_cnt_u[eu[e]], 1);
        g_rank_i[e] = (unsigned short)atomicAdd(&g_cnt_i[ei[e]], 1);
    }
}

__global__ void k_scan() {
    const int* cnt;
    int* offs;
    int n;
    if (blockIdx.x == 0) { cnt = g_cnt_u; offs = g_offs_u; n = NU; }
    else                 { cnt = g_cnt_i; offs = g_offs_i; n = NI; }

    __shared__ int warpsum[32];
    __shared__ int s_carry;
    int t = threadIdx.x, lane = t & 31, w = t >> 5;
    if (t == 0) { s_carry = 0; offs[0] = 0; }
    __syncthreads();

    for (int base = 0; base < n; base += 1024) {
        int i = base + t;
        int v = (i < n) ? cnt[i] : 0;
        int x = v;
#pragma unroll
        for (int d = 1; d < 32; d <<= 1) {
            int y = __shfl_up_sync(0xffffffffu, x, d);
            if (lane >= d) x += y;
        }
        if (lane == 31) warpsum[w] = x;
        __syncthreads();
        if (w == 0) {
            int ws = warpsum[lane];
#pragma unroll
            for (int d = 1; d < 32; d <<= 1) {
                int y = __shfl_up_sync(0xffffffffu, ws, d);
                if (lane >= d) ws += y;
            }
            warpsum[lane] = ws;
        }
        __syncthreads();
        int inc = x + (w ? warpsum[w - 1] : 0) + s_carry;
        if (i < n) offs[i + 1] = inc;
        __syncthreads();
        if (t == 1023) s_carry = inc;
        __syncthreads();
    }
}

__global__ void k_scatter(const int* __restrict__ eu, const int* __restrict__ ei,
                          const float* __restrict__ vui, const float* __restrict__ viu) {
    int i = blockIdx.x * blockDim.x + threadIdx.x;
    int st = gridDim.x * blockDim.x;
    for (int e = i; e < NE; e += st) {
        int u = eu[e], it = ei[e];
        int p = g_offs_u[u] + (int)g_rank_u[e];
        g_edge_u[p] = make_int2(it, __float_as_int(vui[e]));
        int q = g_offs_i[it] + (int)g_rank_i[e];
        g_edge_i[q] = make_int2(u, __float_as_int(viu[e]));
    }
}

// ----------------------------- tensor-core linear ----------------------------
__device__ __forceinline__ void mma16816(float* c, unsigned a0, unsigned a1,
                                         unsigned a2, unsigned a3,
                                         unsigned b0, unsigned b1) {
    asm volatile(
        "mma.sync.aligned.m16n8k16.row.col.f32.f16.f16.f32 "
        "{%0,%1,%2,%3}, {%4,%5,%6,%7}, {%8,%9}, {%0,%1,%2,%3};"
        : "+f"(c[0]), "+f"(c[1]), "+f"(c[2]), "+f"(c[3])
        : "r"(a0), "r"(a1), "r"(a2), "r"(a3), "r"(b0), "r"(b1));
}

__device__ __forceinline__ unsigned h2u(float lo, float hi) {
    __half2 h = __floats2half2_rn(lo, hi);
    return *reinterpret_cast<unsigned*>(&h);
}

// WHICH: 0 -> g_img_h, 1 -> g_txt_h. 4 k-chunks per iter: 16 batched LDG.64.
template <int K, int WHICH>
__global__ __launch_bounds__(512) void k_linear_mma(const float* __restrict__ A,
                                                    const float* __restrict__ W,
                                                    const float* __restrict__ bias,
                                                    int M) {
    constexpr int PS = K + 8;        // padded k-stride in halves
    extern __shared__ __half sWT[];  // [64][PS]
    __half* out = (__half*)(WHICH ? g_txt_h : g_img_h);

    int tid = threadIdx.x;
    for (int i = tid; i < K * 64; i += 512) {
        int k = i >> 6, n = i & 63;
        sWT[n * PS + k] = __float2half(W[(size_t)k * 64 + n]);
    }
    __syncthreads();

    int warp = tid >> 5, lane = tid & 31;
    int g = lane >> 2, q = lane & 3;
    int m_base = blockIdx.x * 256 + warp * 16;
    int row0 = m_base + g, row1 = row0 + 8;
    int r0 = min(row0, M - 1), r1 = min(row1, M - 1);
    const float* A0 = A + (size_t)r0 * K + q * 2;
    const float* A1 = A + (size_t)r1 * K + q * 2;

    float acc[8][4];
#pragma unroll
    for (int nt = 0; nt < 8; nt++)
#pragma unroll
        for (int j = 0; j < 4; j++) acc[nt][j] = 0.f;

#pragma unroll 2
    for (int kc = 0; kc < K; kc += 64) {
        float2 fa[4][4];
#pragma unroll
        for (int c = 0; c < 4; c++) {
            int kb = kc + c * 16;
            fa[c][0] = *(const float2*)(A0 + kb);
            fa[c][1] = *(const float2*)(A1 + kb);
            fa[c][2] = *(const float2*)(A0 + kb + 8);
            fa[c][3] = *(const float2*)(A1 + kb + 8);
        }
#pragma unroll
        for (int c = 0; c < 4; c++) {
            unsigned a0 = h2u(fa[c][0].x, fa[c][0].y);
            unsigned a1 = h2u(fa[c][1].x, fa[c][1].y);
            unsigned a2 = h2u(fa[c][2].x, fa[c][2].y);
            unsigned a3 = h2u(fa[c][3].x, fa[c][3].y);
            int kb = kc + c * 16 + q * 2;
#pragma unroll
            for (int nt = 0; nt < 8; nt++) {
                int n = nt * 8 + g;
                unsigned b0 = *(const unsigned*)&sWT[n * PS + kb];
                unsigned b1 = *(const unsigned*)&sWT[n * PS + kb + 8];
                mma16816(acc[nt], a0, a1, a2, a3, b0, b1);
            }
        }
    }

#pragma unroll
    for (int nt = 0; nt < 8; nt++) {
        int col = nt * 8 + q * 2;
        float bx = bias[col], by = bias[col + 1];
        if (row0 < M) {
            __half2 h = __floats2half2_rn(acc[nt][0] + bx, acc[nt][1] + by);
            *(unsigned*)&out[(size_t)row0 * 64 + col] = *reinterpret_cast<unsigned*>(&h);
        }
        if (row1 < M) {
            __half2 h = __floats2half2_rn(acc[nt][2] + bx, acc[nt][3] + by);
            *(unsigned*)&out[(size_t)row1 * 64 + col] = *reinterpret_cast<unsigned*>(&h);
        }
    }
}

// ----------------------------- single-pass stats -----------------------------
__global__ __launch_bounds__(256) void k_stats(const float* __restrict__ ue,
                                               const float* __restrict__ ie) {
    int t = threadIdx.x, col = t & 63, rg = t >> 6;
    float s = 0.f, q = 0.f;
    for (int row = blockIdx.x * 4 + rg; row < NTOT; row += SPART * 4) {
        const float* p = (row < NU) ? ue + (size_t)row * 64 : ie + (size_t)(row - NU) * 64;
        float x = p[col];
        s += x;
        q += x * x;
    }
    __shared__ float sm[256];
    __shared__ float sq[256];
    sm[t] = s;
    sq[t] = q;
    __syncthreads();
    if (t < 64) g_part[blockIdx.x * 64 + t] = sm[t] + sm[t + 64] + sm[t + 128] + sm[t + 192];
    for (int o = 128; o >= 32; o >>= 1) {
        if (t < o) sq[t] += sq[t + o];
        __syncthreads();
    }
    if (t < 32) {
        float v = sq[t];
#pragma unroll
        for (int o = 16; o; o >>= 1) v += __shfl_xor_sync(0xffffffffu, v, o);
        if (t == 0) g_part1[blockIdx.x] = v;
    }
}

__global__ void k_stats_fin() {
    __shared__ float smean[64];
    __shared__ float red[128];
    int t = threadIdx.x;
    if (t < 64) {
        float s = 0.f;
#pragma unroll 8
        for (int b = 0; b < SPART; b++) s += g_part[b * 64 + t];
        float m = s / (float)NTOT;
        g_colmean[t] = m;
        smean[t] = m;
    }
    __syncthreads();
    float v = g_part1[t];
    if (t < 64) v -= (float)NTOT * smean[t] * smean[t];
    red[t] = v;
    __syncthreads();
    for (int o = 64; o >= 32; o >>= 1) {
        if (t < o) red[t] += red[t + o];
        __syncthreads();
    }
    if (t < 32) {
        float x = red[t];
#pragma unroll
        for (int o = 16; o; o >>= 1) x += __shfl_xor_sync(0xffffffffu, x, o);
        if (t == 0) g_invrnm = rsqrtf(x / (float)NTOT + 1e-6f);
    }
}

__global__ void k_norm_items(const float* __restrict__ ie) {
    float inv = g_invrnm;
    int st = gridDim.x * blockDim.x;
    int i0 = blockIdx.x * blockDim.x + threadIdx.x;
    const float4* i4 = (const float4*)ie;
    const float4* cm4 = (const float4*)g_colmean;
    __half* oh = (__half*)g_in_h;
    for (int idx = i0; idx < NI * 16; idx += st) {
        float4 v = i4[idx];
        float4 cm = cm4[idx & 15];
        __half2 h0 = __floats2half2_rn((v.x - cm.x) * inv, (v.y - cm.y) * inv);
        __half2 h1 = __floats2half2_rn((v.z - cm.z) * inv, (v.w - cm.w) * inv);
        uint2 s;
        s.x = *reinterpret_cast<unsigned*>(&h0);
        s.y = *reinterpret_cast<unsigned*>(&h1);
        *(uint2*)&oh[(size_t)idx * 4] = s;
    }
}

// ----------------------------- fused triple SpMM (fp16 gathers) -------------
__global__ __launch_bounds__(256) void k_fused_u(const float* __restrict__ user_emb,
                                                 float* __restrict__ imgU,
                                                 float* __restrict__ txtU) {
    int w = (blockIdx.x * 256 + threadIdx.x) >> 5;
    if (w >= NU) return;
    int lane = threadIdx.x & 31;
    const __half2* __restrict__ MI = g_img_h;
    const __half2* __restrict__ MT = g_txt_h;
    const __half2* __restrict__ ME = g_in_h;
    const int2* __restrict__ E = g_edge_u;
    int s = g_offs_u[w], e = g_offs_u[w + 1];
    float2 aI = make_float2(0.f, 0.f), aT = aI, aE = aI;
    int k = s;
    for (; k + 8 <= e; k += 8) {
        int2 ev[8];
        float2 xi[8], xt[8], xe[8];
#pragma unroll
        for (int u = 0; u < 8; u++) ev[u] = __ldg(&E[k + u]);
#pragma unroll
        for (int u = 0; u < 8; u++) {
            int b = ev[u].x * 32 + lane;
            xi[u] = __half22float2(MI[b]);
            xt[u] = __half22float2(MT[b]);
            xe[u] = __half22float2(ME[b]);
        }
#pragma unroll
        for (int u = 0; u < 8; u++) {
            float v = __int_as_float(ev[u].y);
            aI.x += v * xi[u].x; aI.y += v * xi[u].y;
            aT.x += v * xt[u].x; aT.y += v * xt[u].y;
            aE.x += v * xe[u].x; aE.y += v * xe[u].y;
        }
    }
    for (; k < e; k++) {
        int2 ev = __ldg(&E[k]);
        float v = __int_as_float(ev.y);
        int b = ev.x * 32 + lane;
        float2 i0 = __half22float2(MI[b]);
        float2 t0 = __half22float2(MT[b]);
        float2 e0 = __half22float2(ME[b]);
        aI.x += v * i0.x; aI.y += v * i0.y;
        aT.x += v * t0.x; aT.y += v * t0.y;
        aE.x += v * e0.x; aE.y += v * e0.y;
    }
    int o = w * 32 + lane;
    ((float2*)imgU)[o] = aI;
    ((float2*)txtU)[o] = aT;
    g_imgU_h[o] = __floats2half2_rn(aI.x, aI.y);
    g_txtU_h[o] = __floats2half2_rn(aT.x, aT.y);
    g_ue1_h[o] = __floats2half2_rn(aE.x, aE.y);
    float inv = g_invrnm;
    float2 ue = ((const float2*)user_emb)[o];
    float2 cm = ((const float2*)g_colmean)[lane];
    float2 acc;
    acc.x = (ue.x - cm.x) * inv + aE.x;
    acc.y = (ue.y - cm.y) * inv + aE.y;
    ((float2*)g_u_acc)[o] = acc;
}

__global__ __launch_bounds__(256) void k_fused_i(const float* __restrict__ item_emb,
                                                 float* __restrict__ imgI,
                                                 float* __restrict__ txtI) {
    int w = (blockIdx.x * 256 + threadIdx.x) >> 5;
    if (w >= NI) return;
    int lane = threadIdx.x & 31;
    const __half2* __restrict__ MI = g_imgU_h;
    const __half2* __restrict__ MT = g_txtU_h;
    const __half2* __restrict__ ME = g_ue1_h;
    const int2* __restrict__ E = g_edge_i;
    int s = g_offs_i[w], e = g_offs_i[w + 1];
    float2 aI = make_float2(0.f, 0.f), aT = aI, aE = aI;
    int k = s;
    for (; k + 8 <= e; k += 8) {
        int2 ev[8];
        float2 xi[8], xt[8], xe[8];
#pragma unroll
        for (int u = 0; u < 8; u++) ev[u] = __ldg(&E[k + u]);
#pragma unroll
        for (int u = 0; u < 8; u++) {
            int b = ev[u].x * 32 + lane;
            xi[u] = __half22float2(MI[b]);
            xt[u] = __half22float2(MT[b]);
            xe[u] = __half22float2(ME[b]);
        }
#pragma unroll
        for (int u = 0; u < 8; u++) {
            float v = __int_as_float(ev[u].y);
            aI.x += v * xi[u].x; aI.y += v * xi[u].y;
            aT.x += v * xt[u].x; aT.y += v * xt[u].y;
            aE.x += v * xe[u].x; aE.y += v * xe[u].y;
        }
    }
    for (; k < e; k++) {
        int2 ev = __ldg(&E[k]);
        float v = __int_as_float(ev.y);
        int b = ev.x * 32 + lane;
        float2 i0 = __half22float2(MI[b]);
        float2 t0 = __half22float2(MT[b]);
        float2 e0 = __half22float2(ME[b]);
        aI.x += v * i0.x; aI.y += v * i0.y;
        aT.x += v * t0.x; aT.y += v * t0.y;
        aE.x += v * e0.x; aE.y += v * e0.y;
    }
    int o = w * 32 + lane;
    ((float2*)imgI)[o] = aI;
    ((float2*)txtI)[o] = aT;
    g_ie1_h[o] = __floats2half2_rn(aE.x, aE.y);
    float inv = g_invrnm;
    float2 ie = ((const float2*)item_emb)[o];
    float2 cm = ((const float2*)g_colmean)[lane];
    float2 acc;
    acc.x = (ie.x - cm.x) * inv + aE.x;
    acc.y = (ie.y - cm.y) * inv + aE.y;
    ((float2*)g_i_acc)[o] = acc;
}

// ----------------------------- layer-2 GNN + final combine -------------------
__global__ __launch_bounds__(256) void k_gnn_u2(const float* __restrict__ imgU,
                                                const float* __restrict__ txtU,
                                                float* __restrict__ u_out) {
    int warp = (blockIdx.x * 256 + threadIdx.x) >> 5;
    int lane = threadIdx.x & 31;
    int row = warp * 2 + (lane >> 4);
    if (row >= NU) return;
    int c = lane & 15;
    const __half* __restrict__ Xh = (const __half*)g_ie1_h;
    const int2* __restrict__ E = g_edge_u;
    int s = g_offs_u[row], e = g_offs_u[row + 1];
    float4 acc = make_float4(0.f, 0.f, 0.f, 0.f);
    int k = s;
    for (; k + 8 <= e; k += 8) {
        int2 ev[8];
        uint2 raw[8];
#pragma unroll
        for (int u = 0; u < 8; u++) ev[u] = __ldg(&E[k + u]);
#pragma unroll
        for (int u = 0; u < 8; u++) raw[u] = *(const uint2*)&Xh[(size_t)ev[u].x * 64 + c * 4];
#pragma unroll
        for (int u = 0; u < 8; u++) {
            float v = __int_as_float(ev[u].y);
            float2 x0 = __half22float2(*reinterpret_cast<__half2*>(&raw[u].x));
            float2 x1 = __half22float2(*reinterpret_cast<__half2*>(&raw[u].y));
            acc.x += v * x0.x; acc.y += v * x0.y;
            acc.z += v * x1.x; acc.w += v * x1.y;
        }
    }
    for (; k < e; k++) {
        int2 ev = __ldg(&E[k]);
        float v = __int_as_float(ev.y);
        uint2 raw = *(const uint2*)&Xh[(size_t)ev.x * 64 + c * 4];
        float2 x0 = __half22float2(*reinterpret_cast<__half2*>(&raw.x));
        float2 x1 = __half22float2(*reinterpret_cast<__half2*>(&raw.y));
        acc.x += v * x0.x; acc.y += v * x0.y;
        acc.z += v * x1.x; acc.w += v * x1.y;
    }
    int o = row * 16 + c;
    {
        __half2 h0 = __floats2half2_rn(acc.x, acc.y);
        __half2 h1 = __floats2half2_rn(acc.z, acc.w);
        uint2 st;
        st.x = *reinterpret_cast<unsigned*>(&h0);
        st.y = *reinterpret_cast<unsigned*>(&h1);
        *(uint2*)&((__half*)g_ue2_h)[(size_t)row * 64 + c * 4] = st;
    }
    float4 g = ((const float4*)g_u_acc)[o];
    float4 a = ((const float4*)imgU)[o];
    float4 b = ((const float4*)txtU)[o];
    float sa = a.x * a.x + a.y * a.y + a.z * a.z + a.w * a.w;
    float sb = b.x * b.x + b.y * b.y + b.z * b.z + b.w * b.w;
#pragma unroll
    for (int of = 8; of; of >>= 1) {
        sa += __shfl_xor_sync(0xffffffffu, sa, of);
        sb += __shfl_xor_sync(0xffffffffu, sb, of);
    }
    float ia = 0.55f / fmaxf(sqrtf(sa), 1e-12f);
    float ib = 0.55f / fmaxf(sqrtf(sb), 1e-12f);
    float4 r;
    r.x = (g.x + acc.x) * (1.0f / 3.0f) + a.x * ia + b.x * ib;
    r.y = (g.y + acc.y) * (1.0f / 3.0f) + a.y * ia + b.y * ib;
    r.z = (g.z + acc.z) * (1.0f / 3.0f) + a.z * ia + b.z * ib;
    r.w = (g.w + acc.w) * (1.0f / 3.0f) + a.w * ia + b.w * ib;
    ((float4*)u_out)[o] = r;
}

__global__ __launch_bounds__(256) void k_gnn_i2(const float* __restrict__ imgI,
                                                const float* __restrict__ txtI,
                                                float* __restrict__ i_out) {
    int warp = (blockIdx.x * 256 + threadIdx.x) >> 5;
    int lane = threadIdx.x & 31;
    int row = warp * 2 + (lane >> 4);
    if (row >= NI) return;
    int c = lane & 15;
    const __half* __restrict__ Xh = (const __half*)g_ue2_h;
    const int2* __restrict__ E = g_edge_i;
    int s = g_offs_i[row], e = g_offs_i[row + 1];
    float4 acc = make_float4(0.f, 0.f, 0.f, 0.f);
    int k = s;
    for (; k + 8 <= e; k += 8) {
        int2 ev[8];
        uint2 raw[8];
#pragma unroll
        for (int u = 0; u < 8; u++) ev[u] = __ldg(&E[k + u]);
#pragma unroll
        for (int u = 0; u < 8; u++) raw[u] = *(const uint2*)&Xh[(size_t)ev[u].x * 64 + c * 4];
#pragma unroll
        for (int u = 0; u < 8; u++) {
            float v = __int_as_float(ev[u].y);
            float2 x0 = __half22float2(*reinterpret_cast<__half2*>(&raw[u].x));
            float2 x1 = __half22float2(*reinterpret_cast<__half2*>(&raw[u].y));
            acc.x += v * x0.x; acc.y += v * x0.y;
            acc.z += v * x1.x; acc.w += v * x1.y;
        }
    }
    for (; k < e; k++) {
        int2 ev = __ldg(&E[k]);
        float v = __int_as_float(ev.y);
        uint2 raw = *(const uint2*)&Xh[(size_t)ev.x * 64 + c * 4];
        float2 x0 = __half22float2(*reinterpret_cast<__half2*>(&raw.x));
        float2 x1 = __half22float2(*reinterpret_cast<__half2*>(&raw.y));
        acc.x += v * x0.x; acc.y += v * x0.y;
        acc.z += v * x1.x; acc.w += v * x1.y;
    }
    int o = row * 16 + c;
    float4 g = ((const float4*)g_i_acc)[o];
    float4 a = ((const float4*)imgI)[o];
    float4 b = ((const float4*)txtI)[o];
    float sa = a.x * a.x + a.y * a.y + a.z * a.z + a.w * a.w;
    float sb = b.x * b.x + b.y * b.y + b.z * b.z + b.w * b.w;
#pragma unroll
    for (int of = 8; of; of >>= 1) {
        sa += __shfl_xor_sync(0xffffffffu, sa, of);
        sb += __shfl_xor_sync(0xffffffffu, sb, of);
    }
    float ia = 0.55f / fmaxf(sqrtf(sa), 1e-12f);
    float ib = 0.55f / fmaxf(sqrtf(sb), 1e-12f);
    float4 r;
    r.x = (g.x + acc.x) * (1.0f / 3.0f) + a.x * ia + b.x * ib;
    r.y = (g.y + acc.y) * (1.0f / 3.0f) + a.y * ia + b.y * ib;
    r.z = (g.z + acc.z) * (1.0f / 3.0f) + a.z * ia + b.z * ib;
    r.w = (g.w + acc.w) * (1.0f / 3.0f) + a.w * ia + b.w * ib;
    ((float4*)i_out)[o] = r;
}

// ----------------------------- launch ---------------------------------------
extern "C" void kernel_launch(void* const* d_in, const int* in_sizes, int n_in,
                              void* d_out, int out_size) {
    const float* image_feats = (const float*)d_in[0];
    const float* text_feats  = (const float*)d_in[1];
    const float* user_emb    = (const float*)d_in[2];
    const float* item_emb    = (const float*)d_in[3];
    const float* W_img       = (const float*)d_in[4];
    const float* b_img       = (const float*)d_in[5];
    const float* W_txt       = (const float*)d_in[6];
    const float* b_txt       = (const float*)d_in[7];
    const float* val_ui      = (const float*)d_in[8];
    const float* val_iu      = (const float*)d_in[9];
    const int*   edge_u      = (const int*)d_in[10];
    const int*   edge_i      = (const int*)d_in[11];

    float* out        = (float*)d_out;
    float* u_out      = out;
    float* i_out      = u_out + (size_t)NU * DD;
    float* image_item = i_out + (size_t)NI * DD;
    float* text_item  = image_item + (size_t)NI * DD;
    float* image_user = text_item + (size_t)NI * DD;
    float* text_user  = image_user + (size_t)NU * DD;

    const int WU = (NU + 7) / 8;
    const int WI = (NI + 7) / 8;

    const int SM_IMG = 64 * (1024 + 8) * 2;  // 132096 B
    const int SM_TXT = 64 * (384 + 8) * 2;   // 50176 B
    cudaFuncSetAttribute(k_linear_mma<1024, 0>,
                         cudaFuncAttributeMaxDynamicSharedMemorySize, SM_IMG);
    cudaFuncSetAttribute(k_linear_mma<384, 1>,
                         cudaFuncAttributeMaxDynamicSharedMemorySize, SM_TXT);

    // counter zeroing via memset (replaces k_init launch)
    void* cnt_u_ptr = nullptr;
    void* cnt_i_ptr = nullptr;
    cudaGetSymbolAddress(&cnt_u_ptr, g_cnt_u);
    cudaGetSymbolAddress(&cnt_i_ptr, g_cnt_i);
    cudaMemsetAsync(cnt_u_ptr, 0, NU * sizeof(int));
    cudaMemsetAsync(cnt_i_ptr, 0, NI * sizeof(int));

    // CSR build + tensor-core GEMMs interleaved (linear<1024> stays 4th launch)
    k_hist<<<512, 256>>>(edge_u, edge_i);
    k_scan<<<2, 1024>>>();
    k_linear_mma<1024, 0><<<(NI + 255) / 256, 512, SM_IMG>>>(image_feats, W_img, b_img, NI);
    k_scatter<<<1024, 256>>>(edge_u, edge_i, val_ui, val_iu);
    k_linear_mma<384, 1><<<(NI + 255) / 256, 512, SM_TXT>>>(text_feats, W_txt, b_txt, NI);

    // stats + item normalize
    k_stats<<<SPART, 256>>>(user_emb, item_emb);
    k_stats_fin<<<1, 128>>>();
    k_norm_items<<<512, 256>>>(item_emb);

    // fused modal + GNN layer-1
    k_fused_u<<<WU, 256>>>(user_emb, image_user, text_user);
    k_fused_i<<<WI, 256>>>(item_emb, image_item, text_item);

    // GNN layer-2 fused with final combine
    k_gnn_u2<<<(NU + 15) / 16, 256>>>(image_user, text_user, u_out);
    k_gnn_i2<<<(NI + 15) / 16, 256>>>(image_item, text_item, i_out);
}

// round 10
// speedup vs baseline: 3.2977x; 1.2793x over previous
#include <cuda_runtime.h>
#include <cuda_fp16.h>
#include <math.h>

#define NU 100000
#define NI 50000
#define DD 64
#define NE 2000000
#define NTOT (NU + NI)
#define SPART 128

// ----------------------------- scratch --------------------------------------
__device__ __half2 g_img_h[NI * 32];
__device__ __half2 g_txt_h[NI * 32];
__device__ __half2 g_in_h[NI * 32];
__device__ __half2 g_imgU_h[NU * 32];
__device__ __half2 g_txtU_h[NU * 32];
__device__ __half2 g_ue1_h[NU * 32];
__device__ __half2 g_ie1_h[NI * 32];
__device__ __half2 g_ue2_h[NU * 32];

__device__ float g_u_acc[NU * DD];
__device__ float g_i_acc[NI * DD];

__device__ int   g_cnt_u[NU];
__device__ int   g_offs_u[NU + 1];
__device__ int   g_cnt_i[NI];
__device__ int   g_offs_i[NI + 1];
__device__ unsigned short g_rank_u[NE];
__device__ unsigned short g_rank_i[NE];

__device__ int2  g_edge_u[NE];
__device__ int2  g_edge_i[NE];

__device__ float g_part[SPART * DD];
__device__ float g_part1[SPART];
__device__ float g_colmean[DD];
__device__ float g_invrnm;
__device__ int   g_ctr[2];   // persistent-GEMM chunk counters

// ----------------------------- CSR build ------------------------------------
__global__ void k_hist(const int* __restrict__ eu, const int* __restrict__ ei) {
    int i = blockIdx.x * blockDim.x + threadIdx.x;
    int st = gridDim.x * blockDim.x;
    for (int e = i; e < NE; e += st) {
        g_rank_u[e] = (unsigned short)atomicAdd(&g_cnt_u[eu[e]], 1);
        g_rank_i[e] = (unsigned short)atomicAdd(&g_cnt_i[ei[e]], 1);
    }
}

__global__ void k_scan() {
    const int* cnt;
    int* offs;
    int n;
    if (blockIdx.x == 0) { cnt = g_cnt_u; offs = g_offs_u; n = NU; }
    else                 { cnt = g_cnt_i; offs = g_offs_i; n = NI; }

    __shared__ int warpsum[32];
    __shared__ int s_carry;
    int t = threadIdx.x, lane = t & 31, w = t >> 5;
    if (t == 0) { s_carry = 0; offs[0] = 0; }
    __syncthreads();

    for (int base = 0; base < n; base += 1024) {
        int i = base + t;
        int v = (i < n) ? cnt[i] : 0;
        int x = v;
#pragma unroll
        for (int d = 1; d < 32; d <<= 1) {
            int y = __shfl_up_sync(0xffffffffu, x, d);
            if (lane >= d) x += y;
        }
        if (lane == 31) warpsum[w] = x;
        __syncthreads();
        if (w == 0) {
            int ws = warpsum[lane];
#pragma unroll
            for (int d = 1; d < 32; d <<= 1) {
                int y = __shfl_up_sync(0xffffffffu, ws, d);
                if (lane >= d) ws += y;
            }
            warpsum[lane] = ws;
        }
        __syncthreads();
        int inc = x + (w ? warpsum[w - 1] : 0) + s_carry;
        if (i < n) offs[i + 1] = inc;
        __syncthreads();
        if (t == 1023) s_carry = inc;
        __syncthreads();
    }
}

__global__ void k_scatter(const int* __restrict__ eu, const int* __restrict__ ei,
                          const float* __restrict__ vui, const float* __restrict__ viu) {
    int i = blockIdx.x * blockDim.x + threadIdx.x;
    int st = gridDim.x * blockDim.x;
    for (int e = i; e < NE; e += st) {
        int u = eu[e], it = ei[e];
        int p = g_offs_u[u] + (int)g_rank_u[e];
        g_edge_u[p] = make_int2(it, __float_as_int(vui[e]));
        int q = g_offs_i[it] + (int)g_rank_i[e];
        g_edge_i[q] = make_int2(u, __float_as_int(viu[e]));
    }
}

// ----------------------------- tensor-core linear (persistent) --------------
__device__ __forceinline__ void mma16816(float* c, unsigned a0, unsigned a1,
                                         unsigned a2, unsigned a3,
                                         unsigned b0, unsigned b1) {
    asm volatile(
        "mma.sync.aligned.m16n8k16.row.col.f32.f16.f16.f32 "
        "{%0,%1,%2,%3}, {%4,%5,%6,%7}, {%8,%9}, {%0,%1,%2,%3};"
        : "+f"(c[0]), "+f"(c[1]), "+f"(c[2]), "+f"(c[3])
        : "r"(a0), "r"(a1), "r"(a2), "r"(a3), "r"(b0), "r"(b1));
}

__device__ __forceinline__ unsigned h2u(float lo, float hi) {
    __half2 h = __floats2half2_rn(lo, hi);
    return *reinterpret_cast<unsigned*>(&h);
}

// Persistent: grid=148, 512 threads. Warps self-schedule 16-row chunks via
// atomic counter. Requires M % 16 == 0 (50000 = 3125*16).
template <int K, int WHICH>
__global__ __launch_bounds__(512) void k_linear_mma(const float* __restrict__ A,
                                                    const float* __restrict__ W,
                                                    const float* __restrict__ bias,
                                                    int M) {
    constexpr int PS = K + 8;        // padded k-stride in halves
    extern __shared__ __half sWT[];  // [64][PS]
    __half* out = (__half*)(WHICH ? g_txt_h : g_img_h);

    int tid = threadIdx.x;
    for (int i = tid; i < K * 64; i += 512) {
        int k = i >> 6, n = i & 63;
        sWT[n * PS + k] = __float2half(W[(size_t)k * 64 + n]);
    }
    __syncthreads();

    int lane = tid & 31;
    int g = lane >> 2, q = lane & 3;

    for (;;) {
        int chunk = 0;
        if (lane == 0) chunk = atomicAdd(&g_ctr[WHICH], 1);
        chunk = __shfl_sync(0xffffffffu, chunk, 0);
        int m_base = chunk << 4;
        if (m_base >= M) break;

        int row0 = m_base + g, row1 = row0 + 8;
        const float* A0 = A + (size_t)row0 * K + q * 2;
        const float* A1 = A + (size_t)row1 * K + q * 2;

        float acc[8][4];
#pragma unroll
        for (int nt = 0; nt < 8; nt++)
#pragma unroll
            for (int j = 0; j < 4; j++) acc[nt][j] = 0.f;

#pragma unroll 2
        for (int kc = 0; kc < K; kc += 64) {
            float2 fa[4][4];
#pragma unroll
            for (int c = 0; c < 4; c++) {
                int kb = kc + c * 16;
                fa[c][0] = *(const float2*)(A0 + kb);
                fa[c][1] = *(const float2*)(A1 + kb);
                fa[c][2] = *(const float2*)(A0 + kb + 8);
                fa[c][3] = *(const float2*)(A1 + kb + 8);
            }
#pragma unroll
            for (int c = 0; c < 4; c++) {
                unsigned a0 = h2u(fa[c][0].x, fa[c][0].y);
                unsigned a1 = h2u(fa[c][1].x, fa[c][1].y);
                unsigned a2 = h2u(fa[c][2].x, fa[c][2].y);
                unsigned a3 = h2u(fa[c][3].x, fa[c][3].y);
                int kb = kc + c * 16 + q * 2;
#pragma unroll
                for (int nt = 0; nt < 8; nt++) {
                    int n = nt * 8 + g;
                    unsigned b0 = *(const unsigned*)&sWT[n * PS + kb];
                    unsigned b1 = *(const unsigned*)&sWT[n * PS + kb + 8];
                    mma16816(acc[nt], a0, a1, a2, a3, b0, b1);
                }
            }
        }

#pragma unroll
        for (int nt = 0; nt < 8; nt++) {
            int col = nt * 8 + q * 2;
            float bx = bias[col], by = bias[col + 1];
            __half2 h0 = __floats2half2_rn(acc[nt][0] + bx, acc[nt][1] + by);
            __half2 h1 = __floats2half2_rn(acc[nt][2] + bx, acc[nt][3] + by);
            *(unsigned*)&out[(size_t)row0 * 64 + col] = *reinterpret_cast<unsigned*>(&h0);
            *(unsigned*)&out[(size_t)row1 * 64 + col] = *reinterpret_cast<unsigned*>(&h1);
        }
    }
}

// ----------------------------- single-pass stats -----------------------------
__global__ __launch_bounds__(256) void k_stats(const float* __restrict__ ue,
                                               const float* __restrict__ ie) {
    int t = threadIdx.x, col = t & 63, rg = t >> 6;
    float s = 0.f, q = 0.f;
    for (int row = blockIdx.x * 4 + rg; row < NTOT; row += SPART * 4) {
        const float* p = (row < NU) ? ue + (size_t)row * 64 : ie + (size_t)(row - NU) * 64;
        float x = p[col];
        s += x;
        q += x * x;
    }
    __shared__ float sm[256];
    __shared__ float sq[256];
    sm[t] = s;
    sq[t] = q;
    __syncthreads();
    if (t < 64) g_part[blockIdx.x * 64 + t] = sm[t] + sm[t + 64] + sm[t + 128] + sm[t + 192];
    for (int o = 128; o >= 32; o >>= 1) {
        if (t < o) sq[t] += sq[t + o];
        __syncthreads();
    }
    if (t < 32) {
        float v = sq[t];
#pragma unroll
        for (int o = 16; o; o >>= 1) v += __shfl_xor_sync(0xffffffffu, v, o);
        if (t == 0) g_part1[blockIdx.x] = v;
    }
}

__global__ void k_stats_fin() {
    __shared__ float smean[64];
    __shared__ float red[128];
    int t = threadIdx.x;
    if (t < 64) {
        float s = 0.f;
#pragma unroll 8
        for (int b = 0; b < SPART; b++) s += g_part[b * 64 + t];
        float m = s / (float)NTOT;
        g_colmean[t] = m;
        smean[t] = m;
    }
    __syncthreads();
    float v = g_part1[t];
    if (t < 64) v -= (float)NTOT * smean[t] * smean[t];
    red[t] = v;
    __syncthreads();
    for (int o = 64; o >= 32; o >>= 1) {
        if (t < o) red[t] += red[t + o];
        __syncthreads();
    }
    if (t < 32) {
        float x = red[t];
#pragma unroll
        for (int o = 16; o; o >>= 1) x += __shfl_xor_sync(0xffffffffu, x, o);
        if (t == 0) g_invrnm = rsqrtf(x / (float)NTOT + 1e-6f);
    }
}

__global__ void k_norm_items(const float* __restrict__ ie) {
    float inv = g_invrnm;
    int st = gridDim.x * blockDim.x;
    int i0 = blockIdx.x * blockDim.x + threadIdx.x;
    const float4* i4 = (const float4*)ie;
    const float4* cm4 = (const float4*)g_colmean;
    __half* oh = (__half*)g_in_h;
    for (int idx = i0; idx < NI * 16; idx += st) {
        float4 v = i4[idx];
        float4 cm = cm4[idx & 15];
        __half2 h0 = __floats2half2_rn((v.x - cm.x) * inv, (v.y - cm.y) * inv);
        __half2 h1 = __floats2half2_rn((v.z - cm.z) * inv, (v.w - cm.w) * inv);
        uint2 s;
        s.x = *reinterpret_cast<unsigned*>(&h0);
        s.y = *reinterpret_cast<unsigned*>(&h1);
        *(uint2*)&oh[(size_t)idx * 4] = s;
    }
}

// ----------------------------- fused triple SpMM (fp16 gathers) -------------
__global__ __launch_bounds__(256) void k_fused_u(const float* __restrict__ user_emb,
                                                 float* __restrict__ imgU,
                                                 float* __restrict__ txtU) {
    int w = (blockIdx.x * 256 + threadIdx.x) >> 5;
    if (w >= NU) return;
    int lane = threadIdx.x & 31;
    const __half2* __restrict__ MI = g_img_h;
    const __half2* __restrict__ MT = g_txt_h;
    const __half2* __restrict__ ME = g_in_h;
    const int2* __restrict__ E = g_edge_u;
    int s = g_offs_u[w], e = g_offs_u[w + 1];
    float2 aI = make_float2(0.f, 0.f), aT = aI, aE = aI;
    int k = s;
    for (; k + 8 <= e; k += 8) {
        int2 ev[8];
        float2 xi[8], xt[8], xe[8];
#pragma unroll
        for (int u = 0; u < 8; u++) ev[u] = __ldg(&E[k + u]);
#pragma unroll
        for (int u = 0; u < 8; u++) {
            int b = ev[u].x * 32 + lane;
            xi[u] = __half22float2(MI[b]);
            xt[u] = __half22float2(MT[b]);
            xe[u] = __half22float2(ME[b]);
        }
#pragma unroll
        for (int u = 0; u < 8; u++) {
            float v = __int_as_float(ev[u].y);
            aI.x += v * xi[u].x; aI.y += v * xi[u].y;
            aT.x += v * xt[u].x; aT.y += v * xt[u].y;
            aE.x += v * xe[u].x; aE.y += v * xe[u].y;
        }
    }
    for (; k < e; k++) {
        int2 ev = __ldg(&E[k]);
        float v = __int_as_float(ev.y);
        int b = ev.x * 32 + lane;
        float2 i0 = __half22float2(MI[b]);
        float2 t0 = __half22float2(MT[b]);
        float2 e0 = __half22float2(ME[b]);
        aI.x += v * i0.x; aI.y += v * i0.y;
        aT.x += v * t0.x; aT.y += v * t0.y;
        aE.x += v * e0.x; aE.y += v * e0.y;
    }
    int o = w * 32 + lane;
    ((float2*)imgU)[o] = aI;
    ((float2*)txtU)[o] = aT;
    g_imgU_h[o] = __floats2half2_rn(aI.x, aI.y);
    g_txtU_h[o] = __floats2half2_rn(aT.x, aT.y);
    g_ue1_h[o] = __floats2half2_rn(aE.x, aE.y);
    float inv = g_invrnm;
    float2 ue = ((const float2*)user_emb)[o];
    float2 cm = ((const float2*)g_colmean)[lane];
    float2 acc;
    acc.x = (ue.x - cm.x) * inv + aE.x;
    acc.y = (ue.y - cm.y) * inv + aE.y;
    ((float2*)g_u_acc)[o] = acc;
}

__global__ __launch_bounds__(256) void k_fused_i(const float* __restrict__ item_emb,
                                                 float* __restrict__ imgI,
                                                 float* __restrict__ txtI) {
    int w = (blockIdx.x * 256 + threadIdx.x) >> 5;
    if (w >= NI) return;
    int lane = threadIdx.x & 31;
    const __half2* __restrict__ MI = g_imgU_h;
    const __half2* __restrict__ MT = g_txtU_h;
    const __half2* __restrict__ ME = g_ue1_h;
    const int2* __restrict__ E = g_edge_i;
    int s = g_offs_i[w], e = g_offs_i[w + 1];
    float2 aI = make_float2(0.f, 0.f), aT = aI, aE = aI;
    int k = s;
    for (; k + 8 <= e; k += 8) {
        int2 ev[8];
        float2 xi[8], xt[8], xe[8];
#pragma unroll
        for (int u = 0; u < 8; u++) ev[u] = __ldg(&E[k + u]);
#pragma unroll
        for (int u = 0; u < 8; u++) {
            int b = ev[u].x * 32 + lane;
            xi[u] = __half22float2(MI[b]);
            xt[u] = __half22float2(MT[b]);
            xe[u] = __half22float2(ME[b]);
        }
#pragma unroll
        for (int u = 0; u < 8; u++) {
            float v = __int_as_float(ev[u].y);
            aI.x += v * xi[u].x; aI.y += v * xi[u].y;
            aT.x += v * xt[u].x; aT.y += v * xt[u].y;
            aE.x += v * xe[u].x; aE.y += v * xe[u].y;
        }
    }
    for (; k < e; k++) {
        int2 ev = __ldg(&E[k]);
        float v = __int_as_float(ev.y);
        int b = ev.x * 32 + lane;
        float2 i0 = __half22float2(MI[b]);
        float2 t0 = __half22float2(MT[b]);
        float2 e0 = __half22float2(ME[b]);
        aI.x += v * i0.x; aI.y += v * i0.y;
        aT.x += v * t0.x; aT.y += v * t0.y;
        aE.x += v * e0.x; aE.y += v * e0.y;
    }
    int o = w * 32 + lane;
    ((float2*)imgI)[o] = aI;
    ((float2*)txtI)[o] = aT;
    g_ie1_h[o] = __floats2half2_rn(aE.x, aE.y);
    float inv = g_invrnm;
    float2 ie = ((const float2*)item_emb)[o];
    float2 cm = ((const float2*)g_colmean)[lane];
    float2 acc;
    acc.x = (ie.x - cm.x) * inv + aE.x;
    acc.y = (ie.y - cm.y) * inv + aE.y;
    ((float2*)g_i_acc)[o] = acc;
}

// ----------------------------- layer-2 GNN + final combine -------------------
__global__ __launch_bounds__(256) void k_gnn_u2(const float* __restrict__ imgU,
                                                const float* __restrict__ txtU,
                                                float* __restrict__ u_out) {
    int warp = (blockIdx.x * 256 + threadIdx.x) >> 5;
    int lane = threadIdx.x & 31;
    int row = warp * 2 + (lane >> 4);
    if (row >= NU) return;
    int c = lane & 15;
    const __half* __restrict__ Xh = (const __half*)g_ie1_h;
    const int2* __restrict__ E = g_edge_u;
    int s = g_offs_u[row], e = g_offs_u[row + 1];
    float4 acc = make_float4(0.f, 0.f, 0.f, 0.f);
    int k = s;
    for (; k + 8 <= e; k += 8) {
        int2 ev[8];
        uint2 raw[8];
#pragma unroll
        for (int u = 0; u < 8; u++) ev[u] = __ldg(&E[k + u]);
#pragma unroll
        for (int u = 0; u < 8; u++) raw[u] = *(const uint2*)&Xh[(size_t)ev[u].x * 64 + c * 4];
#pragma unroll
        for (int u = 0; u < 8; u++) {
            float v = __int_as_float(ev[u].y);
            float2 x0 = __half22float2(*reinterpret_cast<__half2*>(&raw[u].x));
            float2 x1 = __half22float2(*reinterpret_cast<__half2*>(&raw[u].y));
            acc.x += v * x0.x; acc.y += v * x0.y;
            acc.z += v * x1.x; acc.w += v * x1.y;
        }
    }
    for (; k < e; k++) {
        int2 ev = __ldg(&E[k]);
        float v = __int_as_float(ev.y);
        uint2 raw = *(const uint2*)&Xh[(size_t)ev.x * 64 + c * 4];
        float2 x0 = __half22float2(*reinterpret_cast<__half2*>(&raw.x));
        float2 x1 = __half22float2(*reinterpret_cast<__half2*>(&raw.y));
        acc.x += v * x0.x; acc.y += v * x0.y;
        acc.z += v * x1.x; acc.w += v * x1.y;
    }
    int o = row * 16 + c;
    {
        __half2 h0 = __floats2half2_rn(acc.x, acc.y);
        __half2 h1 = __floats2half2_rn(acc.z, acc.w);
        uint2 st;
        st.x = *reinterpret_cast<unsigned*>(&h0);
        st.y = *reinterpret_cast<unsigned*>(&h1);
        *(uint2*)&((__half*)g_ue2_h)[(size_t)row * 64 + c * 4] = st;
    }
    float4 g = ((const float4*)g_u_acc)[o];
    float4 a = ((const float4*)imgU)[o];
    float4 b = ((const float4*)txtU)[o];
    float sa = a.x * a.x + a.y * a.y + a.z * a.z + a.w * a.w;
    float sb = b.x * b.x + b.y * b.y + b.z * b.z + b.w * b.w;
#pragma unroll
    for (int of = 8; of; of >>= 1) {
        sa += __shfl_xor_sync(0xffffffffu, sa, of);
        sb += __shfl_xor_sync(0xffffffffu, sb, of);
    }
    float ia = 0.55f / fmaxf(sqrtf(sa), 1e-12f);
    float ib = 0.55f / fmaxf(sqrtf(sb), 1e-12f);
    float4 r;
    r.x = (g.x + acc.x) * (1.0f / 3.0f) + a.x * ia + b.x * ib;
    r.y = (g.y + acc.y) * (1.0f / 3.0f) + a.y * ia + b.y * ib;
    r.z = (g.z + acc.z) * (1.0f / 3.0f) + a.z * ia + b.z * ib;
    r.w = (g.w + acc.w) * (1.0f / 3.0f) + a.w * ia + b.w * ib;
    ((float4*)u_out)[o] = r;
}

__global__ __launch_bounds__(256) void k_gnn_i2(const float* __restrict__ imgI,
                                                const float* __restrict__ txtI,
                                                float* __restrict__ i_out) {
    int warp = (blockIdx.x * 256 + threadIdx.x) >> 5;
    int lane = threadIdx.x & 31;
    int row = warp * 2 + (lane >> 4);
    if (row >= NI) return;
    int c = lane & 15;
    const __half* __restrict__ Xh = (const __half*)g_ue2_h;
    const int2* __restrict__ E = g_edge_i;
    int s = g_offs_i[row], e = g_offs_i[row + 1];
    float4 acc = make_float4(0.f, 0.f, 0.f, 0.f);
    int k = s;
    for (; k + 8 <= e; k += 8) {
        int2 ev[8];
        uint2 raw[8];
#pragma unroll
        for (int u = 0; u < 8; u++) ev[u] = __ldg(&E[k + u]);
#pragma unroll
        for (int u = 0; u < 8; u++) raw[u] = *(const uint2*)&Xh[(size_t)ev[u].x * 64 + c * 4];
#pragma unroll
        for (int u = 0; u < 8; u++) {
            float v = __int_as_float(ev[u].y);
            float2 x0 = __half22float2(*reinterpret_cast<__half2*>(&raw[u].x));
            float2 x1 = __half22float2(*reinterpret_cast<__half2*>(&raw[u].y));
            acc.x += v * x0.x; acc.y += v * x0.y;
            acc.z += v * x1.x; acc.w += v * x1.y;
        }
    }
    for (; k < e; k++) {
        int2 ev = __ldg(&E[k]);
        float v = __int_as_float(ev.y);
        uint2 raw = *(const uint2*)&Xh[(size_t)ev.x * 64 + c * 4];
        float2 x0 = __half22float2(*reinterpret_cast<__half2*>(&raw.x));
        float2 x1 = __half22float2(*reinterpret_cast<__half2*>(&raw.y));
        acc.x += v * x0.x; acc.y += v * x0.y;
        acc.z += v * x1.x; acc.w += v * x1.y;
    }
    int o = row * 16 + c;
    float4 g = ((const float4*)g_i_acc)[o];
    float4 a = ((const float4*)imgI)[o];
    float4 b = ((const float4*)txtI)[o];
    float sa = a.x * a.x + a.y * a.y + a.z * a.z + a.w * a.w;
    float sb = b.x * b.x + b.y * b.y + b.z * b.z + b.w * b.w;
#pragma unroll
    for (int of = 8; of; of >>= 1) {
        sa += __shfl_xor_sync(0xffffffffu, sa, of);
        sb += __shfl_xor_sync(0xffffffffu, sb, of);
    }
    float ia = 0.55f / fmaxf(sqrtf(sa), 1e-12f);
    float ib = 0.55f / fmaxf(sqrtf(sb), 1e-12f);
    float4 r;
    r.x = (g.x + acc.x) * (1.0f / 3.0f) + a.x * ia + b.x * ib;
    r.y = (g.y + acc.y) * (1.0f / 3.0f) + a.y * ia + b.y * ib;
    r.z = (g.z + acc.z) * (1.0f / 3.0f) + a.z * ia + b.z * ib;
    r.w = (g.w + acc.w) * (1.0f / 3.0f) + a.w * ia + b.w * ib;
    ((float4*)i_out)[o] = r;
}

// ----------------------------- launch ---------------------------------------
// Streams/events are created ONCE (first call = uncaptured correctness run,
// before the harness takes its pre-capture memory baseline) and reused by
// every subsequent call/capture. They are never destroyed, so the graph can
// safely reference them; no per-capture device allocation occurs. The GPU
// work issued per call is identical every time.
static cudaStream_t s_sB = 0, s_sC = 0;
static cudaEvent_t s_evFork = 0, s_evB = 0, s_evC = 0;

extern "C" void kernel_launch(void* const* d_in, const int* in_sizes, int n_in,
                              void* d_out, int out_size) {
    const float* image_feats = (const float*)d_in[0];
    const float* text_feats  = (const float*)d_in[1];
    const float* user_emb    = (const float*)d_in[2];
    const float* item_emb    = (const float*)d_in[3];
    const float* W_img       = (const float*)d_in[4];
    const float* b_img       = (const float*)d_in[5];
    const float* W_txt       = (const float*)d_in[6];
    const float* b_txt       = (const float*)d_in[7];
    const float* val_ui      = (const float*)d_in[8];
    const float* val_iu      = (const float*)d_in[9];
    const int*   edge_u      = (const int*)d_in[10];
    const int*   edge_i      = (const int*)d_in[11];

    float* out        = (float*)d_out;
    float* u_out      = out;
    float* i_out      = u_out + (size_t)NU * DD;
    float* image_item = i_out + (size_t)NI * DD;
    float* text_item  = image_item + (size_t)NI * DD;
    float* image_user = text_item + (size_t)NI * DD;
    float* text_user  = image_user + (size_t)NU * DD;

    const int WU = (NU + 7) / 8;
    const int WI = (NI + 7) / 8;

    const int SM_IMG = 64 * (1024 + 8) * 2;  // 132096 B
    const int SM_TXT = 64 * (384 + 8) * 2;   // 50176 B
    cudaFuncSetAttribute(k_linear_mma<1024, 0>,
                         cudaFuncAttributeMaxDynamicSharedMemorySize, SM_IMG);
    cudaFuncSetAttribute(k_linear_mma<384, 1>,
                         cudaFuncAttributeMaxDynamicSharedMemorySize, SM_TXT);

    if (s_sB == 0) {  // one-time resource creation (outside capture, 1st call)
        cudaStreamCreateWithFlags(&s_sB, cudaStreamNonBlocking);
        cudaStreamCreateWithFlags(&s_sC, cudaStreamNonBlocking);
        cudaEventCreateWithFlags(&s_evFork, cudaEventDisableTiming);
        cudaEventCreateWithFlags(&s_evB, cudaEventDisableTiming);
        cudaEventCreateWithFlags(&s_evC, cudaEventDisableTiming);
    }

    // zero CSR counters + GEMM chunk counters (capture stream)
    void* cnt_u_ptr = nullptr;
    void* cnt_i_ptr = nullptr;
    void* ctr_ptr = nullptr;
    cudaGetSymbolAddress(&cnt_u_ptr, g_cnt_u);
    cudaGetSymbolAddress(&cnt_i_ptr, g_cnt_i);
    cudaGetSymbolAddress(&ctr_ptr, g_ctr);
    cudaMemsetAsync(cnt_u_ptr, 0, NU * sizeof(int));
    cudaMemsetAsync(cnt_i_ptr, 0, NI * sizeof(int));
    cudaMemsetAsync(ctr_ptr, 0, 2 * sizeof(int));

    // fork two side streams off the capture stream
    cudaEventRecord(s_evFork, 0);
    cudaStreamWaitEvent(s_sB, s_evFork, 0);
    cudaStreamWaitEvent(s_sC, s_evFork, 0);

    // branch B: tensor-core GEMMs (persistent, one wave)
    k_linear_mma<1024, 0><<<148, 512, SM_IMG, s_sB>>>(image_feats, W_img, b_img, NI);
    k_linear_mma<384, 1><<<148, 512, SM_TXT, s_sB>>>(text_feats, W_txt, b_txt, NI);

    // branch C: stats chain
    k_stats<<<SPART, 256, 0, s_sC>>>(user_emb, item_emb);
    k_stats_fin<<<1, 128, 0, s_sC>>>();
    k_norm_items<<<512, 256, 0, s_sC>>>(item_emb);

    // main branch: CSR build
    k_hist<<<512, 256>>>(edge_u, edge_i);
    k_scan<<<2, 1024>>>();
    k_scatter<<<1024, 256>>>(edge_u, edge_i, val_ui, val_iu);

    // join
    cudaEventRecord(s_evB, s_sB);
    cudaEventRecord(s_evC, s_sC);
    cudaStreamWaitEvent(0, s_evB, 0);
    cudaStreamWaitEvent(0, s_evC, 0);

    // fused modal + GNN layer-1
    k_fused_u<<<WU, 256>>>(user_emb, image_user, text_user);
    k_fused_i<<<WI, 256>>>(item_emb, image_item, text_item);

    // GNN layer-2 fused with final combine
    k_gnn_u2<<<(NU + 15) / 16, 256>>>(image_user, text_user, u_out);
    k_gnn_i2<<<(NI + 15) / 16, 256>>>(image_item, text_item, i_out);
}

// round 11
// speedup vs baseline: 3.4350x; 1.0416x over previous
#include <cuda_runtime.h>
#include <cuda_fp16.h>
#include <math.h>

#define NU 100000
#define NI 50000
#define DD 64
#define NE 2000000
#define NTOT (NU + NI)
#define SPART 128

// ----------------------------- scratch --------------------------------------
__device__ __half2 g_img_h[NI * 32];
__device__ __half2 g_txt_h[NI * 32];
__device__ __half2 g_in_h[NI * 32];
__device__ __half2 g_imgU_h[NU * 32];
__device__ __half2 g_txtU_h[NU * 32];
__device__ __half2 g_ue1_h[NU * 32];
__device__ __half2 g_ie1_h[NI * 32];
__device__ __half2 g_ue2_h[NU * 32];

__device__ float g_u_acc[NU * DD];
__device__ float g_i_acc[NI * DD];

__device__ int   g_cnt_u[NU];
__device__ int   g_offs_u[NU + 1];
__device__ int   g_cnt_i[NI];
__device__ int   g_offs_i[NI + 1];
__device__ unsigned short g_rank_u[NE];
__device__ unsigned short g_rank_i[NE];

__device__ int2  g_edge_u[NE];
__device__ int2  g_edge_i[NE];

__device__ float g_part[SPART * DD];
__device__ float g_part1[SPART];
__device__ float g_colmean[DD];
__device__ float g_invrnm;
__device__ int   g_ctr[2];   // persistent-GEMM chunk counters

// ----------------------------- CSR build (per side) --------------------------
__global__ void k_hist_u(const int* __restrict__ eu) {
    int i = blockIdx.x * blockDim.x + threadIdx.x;
    int st = gridDim.x * blockDim.x;
    for (int e = i; e < NE; e += st)
        g_rank_u[e] = (unsigned short)atomicAdd(&g_cnt_u[eu[e]], 1);
}

__global__ void k_hist_i(const int* __restrict__ ei) {
    int i = blockIdx.x * blockDim.x + threadIdx.x;
    int st = gridDim.x * blockDim.x;
    for (int e = i; e < NE; e += st)
        g_rank_i[e] = (unsigned short)atomicAdd(&g_cnt_i[ei[e]], 1);
}

// SIDE: 0 -> user counters, 1 -> item counters. One block, 1024 threads.
template <int SIDE>
__global__ void k_scan() {
    const int* cnt = SIDE ? g_cnt_i : g_cnt_u;
    int* offs      = SIDE ? g_offs_i : g_offs_u;
    const int n    = SIDE ? NI : NU;

    __shared__ int warpsum[32];
    __shared__ int s_carry;
    int t = threadIdx.x, lane = t & 31, w = t >> 5;
    if (t == 0) { s_carry = 0; offs[0] = 0; }
    __syncthreads();

    for (int base = 0; base < n; base += 1024) {
        int i = base + t;
        int v = (i < n) ? cnt[i] : 0;
        int x = v;
#pragma unroll
        for (int d = 1; d < 32; d <<= 1) {
            int y = __shfl_up_sync(0xffffffffu, x, d);
            if (lane >= d) x += y;
        }
        if (lane == 31) warpsum[w] = x;
        __syncthreads();
        if (w == 0) {
            int ws = warpsum[lane];
#pragma unroll
            for (int d = 1; d < 32; d <<= 1) {
                int y = __shfl_up_sync(0xffffffffu, ws, d);
                if (lane >= d) ws += y;
            }
            warpsum[lane] = ws;
        }
        __syncthreads();
        int inc = x + (w ? warpsum[w - 1] : 0) + s_carry;
        if (i < n) offs[i + 1] = inc;
        __syncthreads();
        if (t == 1023) s_carry = inc;
        __syncthreads();
    }
}

__global__ void k_scatter_u(const int* __restrict__ eu, const int* __restrict__ ei,
                            const float* __restrict__ vui) {
    int i = blockIdx.x * blockDim.x + threadIdx.x;
    int st = gridDim.x * blockDim.x;
    for (int e = i; e < NE; e += st) {
        int u = eu[e];
        int p = g_offs_u[u] + (int)g_rank_u[e];
        g_edge_u[p] = make_int2(ei[e], __float_as_int(vui[e]));
    }
}

__global__ void k_scatter_i(const int* __restrict__ eu, const int* __restrict__ ei,
                            const float* __restrict__ viu) {
    int i = blockIdx.x * blockDim.x + threadIdx.x;
    int st = gridDim.x * blockDim.x;
    for (int e = i; e < NE; e += st) {
        int it = ei[e];
        int q = g_offs_i[it] + (int)g_rank_i[e];
        g_edge_i[q] = make_int2(eu[e], __float_as_int(viu[e]));
    }
}

// ----------------------------- tensor-core linear (persistent) --------------
__device__ __forceinline__ void mma16816(float* c, unsigned a0, unsigned a1,
                                         unsigned a2, unsigned a3,
                                         unsigned b0, unsigned b1) {
    asm volatile(
        "mma.sync.aligned.m16n8k16.row.col.f32.f16.f16.f32 "
        "{%0,%1,%2,%3}, {%4,%5,%6,%7}, {%8,%9}, {%0,%1,%2,%3};"
        : "+f"(c[0]), "+f"(c[1]), "+f"(c[2]), "+f"(c[3])
        : "r"(a0), "r"(a1), "r"(a2), "r"(a3), "r"(b0), "r"(b1));
}

__device__ __forceinline__ unsigned h2u(float lo, float hi) {
    __half2 h = __floats2half2_rn(lo, hi);
    return *reinterpret_cast<unsigned*>(&h);
}

// Persistent: grid=148, 512 threads. Warps self-schedule 16-row chunks.
template <int K, int WHICH>
__global__ __launch_bounds__(512) void k_linear_mma(const float* __restrict__ A,
                                                    const float* __restrict__ W,
                                                    const float* __restrict__ bias,
                                                    int M) {
    constexpr int PS = K + 8;
    extern __shared__ __half sWT[];
    __half* out = (__half*)(WHICH ? g_txt_h : g_img_h);

    int tid = threadIdx.x;
    for (int i = tid; i < K * 64; i += 512) {
        int k = i >> 6, n = i & 63;
        sWT[n * PS + k] = __float2half(W[(size_t)k * 64 + n]);
    }
    __syncthreads();

    int lane = tid & 31;
    int g = lane >> 2, q = lane & 3;

    for (;;) {
        int chunk = 0;
        if (lane == 0) chunk = atomicAdd(&g_ctr[WHICH], 1);
        chunk = __shfl_sync(0xffffffffu, chunk, 0);
        int m_base = chunk << 4;
        if (m_base >= M) break;

        int row0 = m_base + g, row1 = row0 + 8;
        const float* A0 = A + (size_t)row0 * K + q * 2;
        const float* A1 = A + (size_t)row1 * K + q * 2;

        float acc[8][4];
#pragma unroll
        for (int nt = 0; nt < 8; nt++)
#pragma unroll
            for (int j = 0; j < 4; j++) acc[nt][j] = 0.f;

#pragma unroll 2
        for (int kc = 0; kc < K; kc += 64) {
            float2 fa[4][4];
#pragma unroll
            for (int c = 0; c < 4; c++) {
                int kb = kc + c * 16;
                fa[c][0] = *(const float2*)(A0 + kb);
                fa[c][1] = *(const float2*)(A1 + kb);
                fa[c][2] = *(const float2*)(A0 + kb + 8);
                fa[c][3] = *(const float2*)(A1 + kb + 8);
            }
#pragma unroll
            for (int c = 0; c < 4; c++) {
                unsigned a0 = h2u(fa[c][0].x, fa[c][0].y);
                unsigned a1 = h2u(fa[c][1].x, fa[c][1].y);
                unsigned a2 = h2u(fa[c][2].x, fa[c][2].y);
                unsigned a3 = h2u(fa[c][3].x, fa[c][3].y);
                int kb = kc + c * 16 + q * 2;
#pragma unroll
                for (int nt = 0; nt < 8; nt++) {
                    int n = nt * 8 + g;
                    unsigned b0 = *(const unsigned*)&sWT[n * PS + kb];
                    unsigned b1 = *(const unsigned*)&sWT[n * PS + kb + 8];
                    mma16816(acc[nt], a0, a1, a2, a3, b0, b1);
                }
            }
        }

#pragma unroll
        for (int nt = 0; nt < 8; nt++) {
            int col = nt * 8 + q * 2;
            float bx = bias[col], by = bias[col + 1];
            __half2 h0 = __floats2half2_rn(acc[nt][0] + bx, acc[nt][1] + by);
            __half2 h1 = __floats2half2_rn(acc[nt][2] + bx, acc[nt][3] + by);
            *(unsigned*)&out[(size_t)row0 * 64 + col] = *reinterpret_cast<unsigned*>(&h0);
            *(unsigned*)&out[(size_t)row1 * 64 + col] = *reinterpret_cast<unsigned*>(&h1);
        }
    }
}

// ----------------------------- single-pass stats -----------------------------
__global__ __launch_bounds__(256) void k_stats(const float* __restrict__ ue,
                                               const float* __restrict__ ie) {
    int t = threadIdx.x, col = t & 63, rg = t >> 6;
    float s = 0.f, q = 0.f;
    for (int row = blockIdx.x * 4 + rg; row < NTOT; row += SPART * 4) {
        const float* p = (row < NU) ? ue + (size_t)row * 64 : ie + (size_t)(row - NU) * 64;
        float x = p[col];
        s += x;
        q += x * x;
    }
    __shared__ float sm[256];
    __shared__ float sq[256];
    sm[t] = s;
    sq[t] = q;
    __syncthreads();
    if (t < 64) g_part[blockIdx.x * 64 + t] = sm[t] + sm[t + 64] + sm[t + 128] + sm[t + 192];
    for (int o = 128; o >= 32; o >>= 1) {
        if (t < o) sq[t] += sq[t + o];
        __syncthreads();
    }
    if (t < 32) {
        float v = sq[t];
#pragma unroll
        for (int o = 16; o; o >>= 1) v += __shfl_xor_sync(0xffffffffu, v, o);
        if (t == 0) g_part1[blockIdx.x] = v;
    }
}

__global__ void k_stats_fin() {
    __shared__ float smean[64];
    __shared__ float red[128];
    int t = threadIdx.x;
    if (t < 64) {
        float s = 0.f;
#pragma unroll 8
        for (int b = 0; b < SPART; b++) s += g_part[b * 64 + t];
        float m = s / (float)NTOT;
        g_colmean[t] = m;
        smean[t] = m;
    }
    __syncthreads();
    float v = g_part1[t];
    if (t < 64) v -= (float)NTOT * smean[t] * smean[t];
    red[t] = v;
    __syncthreads();
    for (int o = 64; o >= 32; o >>= 1) {
        if (t < o) red[t] += red[t + o];
        __syncthreads();
    }
    if (t < 32) {
        float x = red[t];
#pragma unroll
        for (int o = 16; o; o >>= 1) x += __shfl_xor_sync(0xffffffffu, x, o);
        if (t == 0) g_invrnm = rsqrtf(x / (float)NTOT + 1e-6f);
    }
}

__global__ void k_norm_items(const float* __restrict__ ie) {
    float inv = g_invrnm;
    int st = gridDim.x * blockDim.x;
    int i0 = blockIdx.x * blockDim.x + threadIdx.x;
    const float4* i4 = (const float4*)ie;
    const float4* cm4 = (const float4*)g_colmean;
    __half* oh = (__half*)g_in_h;
    for (int idx = i0; idx < NI * 16; idx += st) {
        float4 v = i4[idx];
        float4 cm = cm4[idx & 15];
        __half2 h0 = __floats2half2_rn((v.x - cm.x) * inv, (v.y - cm.y) * inv);
        __half2 h1 = __floats2half2_rn((v.z - cm.z) * inv, (v.w - cm.w) * inv);
        uint2 s;
        s.x = *reinterpret_cast<unsigned*>(&h0);
        s.y = *reinterpret_cast<unsigned*>(&h1);
        *(uint2*)&oh[(size_t)idx * 4] = s;
    }
}

// ----------------------------- fused triple SpMM (fp16 gathers) -------------
__global__ __launch_bounds__(256) void k_fused_u(const float* __restrict__ user_emb,
                                                 float* __restrict__ imgU,
                                                 float* __restrict__ txtU) {
    int w = (blockIdx.x * 256 + threadIdx.x) >> 5;
    if (w >= NU) return;
    int lane = threadIdx.x & 31;
    const __half2* __restrict__ MI = g_img_h;
    const __half2* __restrict__ MT = g_txt_h;
    const __half2* __restrict__ ME = g_in_h;
    const int2* __restrict__ E = g_edge_u;
    int s = g_offs_u[w], e = g_offs_u[w + 1];
    float2 aI = make_float2(0.f, 0.f), aT = aI, aE = aI;
    int k = s;
    for (; k + 8 <= e; k += 8) {
        int2 ev[8];
        float2 xi[8], xt[8], xe[8];
#pragma unroll
        for (int u = 0; u < 8; u++) ev[u] = __ldg(&E[k + u]);
#pragma unroll
        for (int u = 0; u < 8; u++) {
            int b = ev[u].x * 32 + lane;
            xi[u] = __half22float2(MI[b]);
            xt[u] = __half22float2(MT[b]);
            xe[u] = __half22float2(ME[b]);
        }
#pragma unroll
        for (int u = 0; u < 8; u++) {
            float v = __int_as_float(ev[u].y);
            aI.x += v * xi[u].x; aI.y += v * xi[u].y;
            aT.x += v * xt[u].x; aT.y += v * xt[u].y;
            aE.x += v * xe[u].x; aE.y += v * xe[u].y;
        }
    }
    for (; k < e; k++) {
        int2 ev = __ldg(&E[k]);
        float v = __int_as_float(ev.y);
        int b = ev.x * 32 + lane;
        float2 i0 = __half22float2(MI[b]);
        float2 t0 = __half22float2(MT[b]);
        float2 e0 = __half22float2(ME[b]);
        aI.x += v * i0.x; aI.y += v * i0.y;
        aT.x += v * t0.x; aT.y += v * t0.y;
        aE.x += v * e0.x; aE.y += v * e0.y;
    }
    int o = w * 32 + lane;
    ((float2*)imgU)[o] = aI;
    ((float2*)txtU)[o] = aT;
    g_imgU_h[o] = __floats2half2_rn(aI.x, aI.y);
    g_txtU_h[o] = __floats2half2_rn(aT.x, aT.y);
    g_ue1_h[o] = __floats2half2_rn(aE.x, aE.y);
    float inv = g_invrnm;
    float2 ue = ((const float2*)user_emb)[o];
    float2 cm = ((const float2*)g_colmean)[lane];
    float2 acc;
    acc.x = (ue.x - cm.x) * inv + aE.x;
    acc.y = (ue.y - cm.y) * inv + aE.y;
    ((float2*)g_u_acc)[o] = acc;
}

__global__ __launch_bounds__(256) void k_fused_i(const float* __restrict__ item_emb,
                                                 float* __restrict__ imgI,
                                                 float* __restrict__ txtI) {
    int w = (blockIdx.x * 256 + threadIdx.x) >> 5;
    if (w >= NI) return;
    int lane = threadIdx.x & 31;
    const __half2* __restrict__ MI = g_imgU_h;
    const __half2* __restrict__ MT = g_txtU_h;
    const __half2* __restrict__ ME = g_ue1_h;
    const int2* __restrict__ E = g_edge_i;
    int s = g_offs_i[w], e = g_offs_i[w + 1];
    float2 aI = make_float2(0.f, 0.f), aT = aI, aE = aI;
    int k = s;
    for (; k + 8 <= e; k += 8) {
        int2 ev[8];
        float2 xi[8], xt[8], xe[8];
#pragma unroll
        for (int u = 0; u < 8; u++) ev[u] = __ldg(&E[k + u]);
#pragma unroll
        for (int u = 0; u < 8; u++) {
            int b = ev[u].x * 32 + lane;
            xi[u] = __half22float2(MI[b]);
            xt[u] = __half22float2(MT[b]);
            xe[u] = __half22float2(ME[b]);
        }
#pragma unroll
        for (int u = 0; u < 8; u++) {
            float v = __int_as_float(ev[u].y);
            aI.x += v * xi[u].x; aI.y += v * xi[u].y;
            aT.x += v * xt[u].x; aT.y += v * xt[u].y;
            aE.x += v * xe[u].x; aE.y += v * xe[u].y;
        }
    }
    for (; k < e; k++) {
        int2 ev = __ldg(&E[k]);
        float v = __int_as_float(ev.y);
        int b = ev.x * 32 + lane;
        float2 i0 = __half22float2(MI[b]);
        float2 t0 = __half22float2(MT[b]);
        float2 e0 = __half22float2(ME[b]);
        aI.x += v * i0.x; aI.y += v * i0.y;
        aT.x += v * t0.x; aT.y += v * t0.y;
        aE.x += v * e0.x; aE.y += v * e0.y;
    }
    int o = w * 32 + lane;
    ((float2*)imgI)[o] = aI;
    ((float2*)txtI)[o] = aT;
    g_ie1_h[o] = __floats2half2_rn(aE.x, aE.y);
    float inv = g_invrnm;
    float2 ie = ((const float2*)item_emb)[o];
    float2 cm = ((const float2*)g_colmean)[lane];
    float2 acc;
    acc.x = (ie.x - cm.x) * inv + aE.x;
    acc.y = (ie.y - cm.y) * inv + aE.y;
    ((float2*)g_i_acc)[o] = acc;
}

// ----------------------------- layer-2 GNN + final combine -------------------
__global__ __launch_bounds__(256) void k_gnn_u2(const float* __restrict__ imgU,
                                                const float* __restrict__ txtU,
                                                float* __restrict__ u_out) {
    int warp = (blockIdx.x * 256 + threadIdx.x) >> 5;
    int lane = threadIdx.x & 31;
    int row = warp * 2 + (lane >> 4);
    if (row >= NU) return;
    int c = lane & 15;
    const __half* __restrict__ Xh = (const __half*)g_ie1_h;
    const int2* __restrict__ E = g_edge_u;
    int s = g_offs_u[row], e = g_offs_u[row + 1];
    float4 acc = make_float4(0.f, 0.f, 0.f, 0.f);
    int k = s;
    for (; k + 8 <= e; k += 8) {
        int2 ev[8];
        uint2 raw[8];
#pragma unroll
        for (int u = 0; u < 8; u++) ev[u] = __ldg(&E[k + u]);
#pragma unroll
        for (int u = 0; u < 8; u++) raw[u] = *(const uint2*)&Xh[(size_t)ev[u].x * 64 + c * 4];
#pragma unroll
        for (int u = 0; u < 8; u++) {
            float v = __int_as_float(ev[u].y);
            float2 x0 = __half22float2(*reinterpret_cast<__half2*>(&raw[u].x));
            float2 x1 = __half22float2(*reinterpret_cast<__half2*>(&raw[u].y));
            acc.x += v * x0.x; acc.y += v * x0.y;
            acc.z += v * x1.x; acc.w += v * x1.y;
        }
    }
    for (; k < e; k++) {
        int2 ev = __ldg(&E[k]);
        float v = __int_as_float(ev.y);
        uint2 raw = *(const uint2*)&Xh[(size_t)ev.x * 64 + c * 4];
        float2 x0 = __half22float2(*reinterpret_cast<__half2*>(&raw.x));
        float2 x1 = __half22float2(*reinterpret_cast<__half2*>(&raw.y));
        acc.x += v * x0.x; acc.y += v * x0.y;
        acc.z += v * x1.x; acc.w += v * x1.y;
    }
    int o = row * 16 + c;
    {
        __half2 h0 = __floats2half2_rn(acc.x, acc.y);
        __half2 h1 = __floats2half2_rn(acc.z, acc.w);
        uint2 st;
        st.x = *reinterpret_cast<unsigned*>(&h0);
        st.y = *reinterpret_cast<unsigned*>(&h1);
        *(uint2*)&((__half*)g_ue2_h)[(size_t)row * 64 + c * 4] = st;
    }
    float4 g = ((const float4*)g_u_acc)[o];
    float4 a = ((const float4*)imgU)[o];
    float4 b = ((const float4*)txtU)[o];
    float sa = a.x * a.x + a.y * a.y + a.z * a.z + a.w * a.w;
    float sb = b.x * b.x + b.y * b.y + b.z * b.z + b.w * b.w;
#pragma unroll
    for (int of = 8; of; of >>= 1) {
        sa += __shfl_xor_sync(0xffffffffu, sa, of);
        sb += __shfl_xor_sync(0xffffffffu, sb, of);
    }
    float ia = 0.55f / fmaxf(sqrtf(sa), 1e-12f);
    float ib = 0.55f / fmaxf(sqrtf(sb), 1e-12f);
    float4 r;
    r.x = (g.x + acc.x) * (1.0f / 3.0f) + a.x * ia + b.x * ib;
    r.y = (g.y + acc.y) * (1.0f / 3.0f) + a.y * ia + b.y * ib;
    r.z = (g.z + acc.z) * (1.0f / 3.0f) + a.z * ia + b.z * ib;
    r.w = (g.w + acc.w) * (1.0f / 3.0f) + a.w * ia + b.w * ib;
    ((float4*)u_out)[o] = r;
}

__global__ __launch_bounds__(256) void k_gnn_i2(const float* __restrict__ imgI,
                                                const float* __restrict__ txtI,
                                                float* __restrict__ i_out) {
    int warp = (blockIdx.x * 256 + threadIdx.x) >> 5;
    int lane = threadIdx.x & 31;
    int row = warp * 2 + (lane >> 4);
    if (row >= NI) return;
    int c = lane & 15;
    const __half* __restrict__ Xh = (const __half*)g_ue2_h;
    const int2* __restrict__ E = g_edge_i;
    int s = g_offs_i[row], e = g_offs_i[row + 1];
    float4 acc = make_float4(0.f, 0.f, 0.f, 0.f);
    int k = s;
    for (; k + 8 <= e; k += 8) {
        int2 ev[8];
        uint2 raw[8];
#pragma unroll
        for (int u = 0; u < 8; u++) ev[u] = __ldg(&E[k + u]);
#pragma unroll
        for (int u = 0; u < 8; u++) raw[u] = *(const uint2*)&Xh[(size_t)ev[u].x * 64 + c * 4];
#pragma unroll
        for (int u = 0; u < 8; u++) {
            float v = __int_as_float(ev[u].y);
            float2 x0 = __half22float2(*reinterpret_cast<__half2*>(&raw[u].x));
            float2 x1 = __half22float2(*reinterpret_cast<__half2*>(&raw[u].y));
            acc.x += v * x0.x; acc.y += v * x0.y;
            acc.z += v * x1.x; acc.w += v * x1.y;
        }
    }
    for (; k < e; k++) {
        int2 ev = __ldg(&E[k]);
        float v = __int_as_float(ev.y);
        uint2 raw = *(const uint2*)&Xh[(size_t)ev.x * 64 + c * 4];
        float2 x0 = __half22float2(*reinterpret_cast<__half2*>(&raw.x));
        float2 x1 = __half22float2(*reinterpret_cast<__half2*>(&raw.y));
        acc.x += v * x0.x; acc.y += v * x0.y;
        acc.z += v * x1.x; acc.w += v * x1.y;
    }
    int o = row * 16 + c;
    float4 g = ((const float4*)g_i_acc)[o];
    float4 a = ((const float4*)imgI)[o];
    float4 b = ((const float4*)txtI)[o];
    float sa = a.x * a.x + a.y * a.y + a.z * a.z + a.w * a.w;
    float sb = b.x * b.x + b.y * b.y + b.z * b.z + b.w * b.w;
#pragma unroll
    for (int of = 8; of; of >>= 1) {
        sa += __shfl_xor_sync(0xffffffffu, sa, of);
        sb += __shfl_xor_sync(0xffffffffu, sb, of);
    }
    float ia = 0.55f / fmaxf(sqrtf(sa), 1e-12f);
    float ib = 0.55f / fmaxf(sqrtf(sb), 1e-12f);
    float4 r;
    r.x = (g.x + acc.x) * (1.0f / 3.0f) + a.x * ia + b.x * ib;
    r.y = (g.y + acc.y) * (1.0f / 3.0f) + a.y * ia + b.y * ib;
    r.z = (g.z + acc.z) * (1.0f / 3.0f) + a.z * ia + b.z * ib;
    r.w = (g.w + acc.w) * (1.0f / 3.0f) + a.w * ia + b.w * ib;
    ((float4*)i_out)[o] = r;
}

// ----------------------------- launch ---------------------------------------
// Streams/events created ONCE on the first (uncaptured correctness) call and
// reused by every capture; never destroyed. Per-call GPU work is identical.
static cudaStream_t s_sB = 0, s_sC = 0, s_sD = 0;
static cudaEvent_t s_evFork = 0, s_evB = 0, s_evC = 0, s_evD = 0;

extern "C" void kernel_launch(void* const* d_in, const int* in_sizes, int n_in,
                              void* d_out, int out_size) {
    const float* image_feats = (const float*)d_in[0];
    const float* text_feats  = (const float*)d_in[1];
    const float* user_emb    = (const float*)d_in[2];
    const float* item_emb    = (const float*)d_in[3];
    const float* W_img       = (const float*)d_in[4];
    const float* b_img       = (const float*)d_in[5];
    const float* W_txt       = (const float*)d_in[6];
    const float* b_txt       = (const float*)d_in[7];
    const float* val_ui      = (const float*)d_in[8];
    const float* val_iu      = (const float*)d_in[9];
    const int*   edge_u      = (const int*)d_in[10];
    const int*   edge_i      = (const int*)d_in[11];

    float* out        = (float*)d_out;
    float* u_out      = out;
    float* i_out      = u_out + (size_t)NU * DD;
    float* image_item = i_out + (size_t)NI * DD;
    float* text_item  = image_item + (size_t)NI * DD;
    float* image_user = text_item + (size_t)NI * DD;
    float* text_user  = image_user + (size_t)NU * DD;

    const int WU = (NU + 7) / 8;
    const int WI = (NI + 7) / 8;

    const int SM_IMG = 64 * (1024 + 8) * 2;  // 132096 B
    const int SM_TXT = 64 * (384 + 8) * 2;   // 50176 B
    cudaFuncSetAttribute(k_linear_mma<1024, 0>,
                         cudaFuncAttributeMaxDynamicSharedMemorySize, SM_IMG);
    cudaFuncSetAttribute(k_linear_mma<384, 1>,
                         cudaFuncAttributeMaxDynamicSharedMemorySize, SM_TXT);

    if (s_sB == 0) {  // one-time resource creation (outside capture, 1st call)
        cudaStreamCreateWithFlags(&s_sB, cudaStreamNonBlocking);
        cudaStreamCreateWithFlags(&s_sC, cudaStreamNonBlocking);
        cudaStreamCreateWithFlags(&s_sD, cudaStreamNonBlocking);
        cudaEventCreateWithFlags(&s_evFork, cudaEventDisableTiming);
        cudaEventCreateWithFlags(&s_evB, cudaEventDisableTiming);
        cudaEventCreateWithFlags(&s_evC, cudaEventDisableTiming);
        cudaEventCreateWithFlags(&s_evD, cudaEventDisableTiming);
    }

    void* cnt_u_ptr = nullptr;
    void* cnt_i_ptr = nullptr;
    void* ctr_ptr = nullptr;
    cudaGetSymbolAddress(&cnt_u_ptr, g_cnt_u);
    cudaGetSymbolAddress(&cnt_i_ptr, g_cnt_i);
    cudaGetSymbolAddress(&ctr_ptr, g_ctr);

    // fork three side streams off the capture stream
    cudaEventRecord(s_evFork, 0);
    cudaStreamWaitEvent(s_sB, s_evFork, 0);
    cudaStreamWaitEvent(s_sC, s_evFork, 0);
    cudaStreamWaitEvent(s_sD, s_evFork, 0);

    // branch B: tensor-core GEMMs (persistent, one wave)
    cudaMemsetAsync(ctr_ptr, 0, 2 * sizeof(int), s_sB);
    k_linear_mma<1024, 0><<<148, 512, SM_IMG, s_sB>>>(image_feats, W_img, b_img, NI);
    k_linear_mma<384, 1><<<148, 512, SM_TXT, s_sB>>>(text_feats, W_txt, b_txt, NI);

    // branch C: stats chain
    k_stats<<<SPART, 256, 0, s_sC>>>(user_emb, item_emb);
    k_stats_fin<<<1, 128, 0, s_sC>>>();
    k_norm_items<<<512, 256, 0, s_sC>>>(item_emb);

    // branch D: item-side CSR
    cudaMemsetAsync(cnt_i_ptr, 0, NI * sizeof(int), s_sD);
    k_hist_i<<<512, 256, 0, s_sD>>>(edge_i);
    k_scan<1><<<1, 1024, 0, s_sD>>>();
    k_scatter_i<<<1024, 256, 0, s_sD>>>(edge_u, edge_i, val_iu);
    cudaEventRecord(s_evD, s_sD);

    // main branch: user-side CSR
    cudaMemsetAsync(cnt_u_ptr, 0, NU * sizeof(int));
    k_hist_u<<<512, 256>>>(edge_u);
    k_scan<0><<<1, 1024>>>();
    k_scatter_u<<<1024, 256>>>(edge_u, edge_i, val_ui);

    // join GEMM + stats before fused_u
    cudaEventRecord(s_evB, s_sB);
    cudaEventRecord(s_evC, s_sC);
    cudaStreamWaitEvent(0, s_evB, 0);
    cudaStreamWaitEvent(0, s_evC, 0);

    // fused modal + GNN layer-1 (user side)
    k_fused_u<<<WU, 256>>>(user_emb, image_user, text_user);

    // item side additionally needs the item CSR
    cudaStreamWaitEvent(0, s_evD, 0);
    k_fused_i<<<WI, 256>>>(item_emb, image_item, text_item);

    // GNN layer-2 fused with final combine
    k_gnn_u2<<<(NU + 15) / 16, 256>>>(image_user, text_user, u_out);
    k_gnn_i2<<<(NI + 15) / 16, 256>>>(image_item, text_item, i_out);
}

// round 13
// speedup vs baseline: 3.4558x; 1.0060x over previous
#include <cuda_runtime.h>
#include <cuda_fp16.h>
#include <math.h>

#define NU 100000
#define NI 50000
#define DD 64
#define NE 2000000
#define NTOT (NU + NI)
#define SPART 128

// ----------------------------- scratch --------------------------------------
__device__ __half2 g_img_h[NI * 32];
__device__ __half2 g_txt_h[NI * 32];
__device__ __half2 g_in_h[NI * 32];
__device__ __half2 g_imgU_h[NU * 32];
__device__ __half2 g_txtU_h[NU * 32];
__device__ __half2 g_ue1_h[NU * 32];
__device__ __half2 g_ie1_h[NI * 32];
__device__ __half2 g_ue2_h[NU * 32];

__device__ float g_u_acc[NU * DD];
__device__ float g_i_acc[NI * DD];

__device__ int   g_cnt_u[NU];
__device__ int   g_offs_u[NU + 1];
__device__ int   g_cnt_i[NI];
__device__ int   g_offs_i[NI + 1];
__device__ unsigned short g_rank_u[NE];
__device__ unsigned short g_rank_i[NE];

__device__ int2  g_edge_u[NE];
__device__ int2  g_edge_i[NE];

__device__ float g_part[SPART * DD];
__device__ float g_part1[SPART];
__device__ float g_colmean[DD];
__device__ float g_invrnm;
__device__ int   g_ctr[2];

// ----------------------------- CSR build (per side, unroll-4) ----------------
__global__ void k_hist_u(const int* __restrict__ eu) {
    int i = blockIdx.x * blockDim.x + threadIdx.x;
    int st = gridDim.x * blockDim.x;
    int e = i;
    for (; e + 3 * st < NE; e += 4 * st) {
        int u0 = eu[e], u1 = eu[e + st], u2 = eu[e + 2 * st], u3 = eu[e + 3 * st];
        g_rank_u[e]          = (unsigned short)atomicAdd(&g_cnt_u[u0], 1);
        g_rank_u[e + st]     = (unsigned short)atomicAdd(&g_cnt_u[u1], 1);
        g_rank_u[e + 2 * st] = (unsigned short)atomicAdd(&g_cnt_u[u2], 1);
        g_rank_u[e + 3 * st] = (unsigned short)atomicAdd(&g_cnt_u[u3], 1);
    }
    for (; e < NE; e += st)
        g_rank_u[e] = (unsigned short)atomicAdd(&g_cnt_u[eu[e]], 1);
}

__global__ void k_hist_i(const int* __restrict__ ei) {
    int i = blockIdx.x * blockDim.x + threadIdx.x;
    int st = gridDim.x * blockDim.x;
    int e = i;
    for (; e + 3 * st < NE; e += 4 * st) {
        int u0 = ei[e], u1 = ei[e + st], u2 = ei[e + 2 * st], u3 = ei[e + 3 * st];
        g_rank_i[e]          = (unsigned short)atomicAdd(&g_cnt_i[u0], 1);
        g_rank_i[e + st]     = (unsigned short)atomicAdd(&g_cnt_i[u1], 1);
        g_rank_i[e + 2 * st] = (unsigned short)atomicAdd(&g_cnt_i[u2], 1);
        g_rank_i[e + 3 * st] = (unsigned short)atomicAdd(&g_cnt_i[u3], 1);
    }
    for (; e < NE; e += st)
        g_rank_i[e] = (unsigned short)atomicAdd(&g_cnt_i[ei[e]], 1);
}

template <int SIDE>
__global__ void k_scan() {
    const int* cnt = SIDE ? g_cnt_i : g_cnt_u;
    int* offs      = SIDE ? g_offs_i : g_offs_u;
    const int n    = SIDE ? NI : NU;

    __shared__ int warpsum[32];
    __shared__ int s_carry;
    int t = threadIdx.x, lane = t & 31, w = t >> 5;
    if (t == 0) { s_carry = 0; offs[0] = 0; }
    __syncthreads();

    for (int base = 0; base < n; base += 1024) {
        int i = base + t;
        int v = (i < n) ? cnt[i] : 0;
        int x = v;
#pragma unroll
        for (int d = 1; d < 32; d <<= 1) {
            int y = __shfl_up_sync(0xffffffffu, x, d);
            if (lane >= d) x += y;
        }
        if (lane == 31) warpsum[w] = x;
        __syncthreads();
        if (w == 0) {
            int ws = warpsum[lane];
#pragma unroll
            for (int d = 1; d < 32; d <<= 1) {
                int y = __shfl_up_sync(0xffffffffu, ws, d);
                if (lane >= d) ws += y;
            }
            warpsum[lane] = ws;
        }
        __syncthreads();
        int inc = x + (w ? warpsum[w - 1] : 0) + s_carry;
        if (i < n) offs[i + 1] = inc;
        __syncthreads();
        if (t == 1023) s_carry = inc;
        __syncthreads();
    }
}

__global__ void k_scatter_u(const int* __restrict__ eu, const int* __restrict__ ei,
                            const float* __restrict__ vui) {
    int i = blockIdx.x * blockDim.x + threadIdx.x;
    int st = gridDim.x * blockDim.x;
    int e = i;
    for (; e + 3 * st < NE; e += 4 * st) {
        int u0 = eu[e], u1 = eu[e + st], u2 = eu[e + 2 * st], u3 = eu[e + 3 * st];
        int s0 = ei[e], s1 = ei[e + st], s2 = ei[e + 2 * st], s3 = ei[e + 3 * st];
        float v0 = vui[e], v1 = vui[e + st], v2 = vui[e + 2 * st], v3 = vui[e + 3 * st];
        int r0 = g_rank_u[e], r1 = g_rank_u[e + st];
        int r2 = g_rank_u[e + 2 * st], r3 = g_rank_u[e + 3 * st];
        int o0 = g_offs_u[u0], o1 = g_offs_u[u1], o2 = g_offs_u[u2], o3 = g_offs_u[u3];
        g_edge_u[o0 + r0] = make_int2(s0, __float_as_int(v0));
        g_edge_u[o1 + r1] = make_int2(s1, __float_as_int(v1));
        g_edge_u[o2 + r2] = make_int2(s2, __float_as_int(v2));
        g_edge_u[o3 + r3] = make_int2(s3, __float_as_int(v3));
    }
    for (; e < NE; e += st) {
        int u = eu[e];
        int p = g_offs_u[u] + (int)g_rank_u[e];
        g_edge_u[p] = make_int2(ei[e], __float_as_int(vui[e]));
    }
}

__global__ void k_scatter_i(const int* __restrict__ eu, const int* __restrict__ ei,
                            const float* __restrict__ viu) {
    int i = blockIdx.x * blockDim.x + threadIdx.x;
    int st = gridDim.x * blockDim.x;
    int e = i;
    for (; e + 3 * st < NE; e += 4 * st) {
        int u0 = ei[e], u1 = ei[e + st], u2 = ei[e + 2 * st], u3 = ei[e + 3 * st];
        int s0 = eu[e], s1 = eu[e + st], s2 = eu[e + 2 * st], s3 = eu[e + 3 * st];
        float v0 = viu[e], v1 = viu[e + st], v2 = viu[e + 2 * st], v3 = viu[e + 3 * st];
        int r0 = g_rank_i[e], r1 = g_rank_i[e + st];
        int r2 = g_rank_i[e + 2 * st], r3 = g_rank_i[e + 3 * st];
        int o0 = g_offs_i[u0], o1 = g_offs_i[u1], o2 = g_offs_i[u2], o3 = g_offs_i[u3];
        g_edge_i[o0 + r0] = make_int2(s0, __float_as_int(v0));
        g_edge_i[o1 + r1] = make_int2(s1, __float_as_int(v1));
        g_edge_i[o2 + r2] = make_int2(s2, __float_as_int(v2));
        g_edge_i[o3 + r3] = make_int2(s3, __float_as_int(v3));
    }
    for (; e < NE; e += st) {
        int it = ei[e];
        int q = g_offs_i[it] + (int)g_rank_i[e];
        g_edge_i[q] = make_int2(eu[e], __float_as_int(viu[e]));
    }
}

// ----------------------------- tensor-core linear (persistent) --------------
__device__ __forceinline__ void mma16816(float* c, unsigned a0, unsigned a1,
                                         unsigned a2, unsigned a3,
                                         unsigned b0, unsigned b1) {
    asm volatile(
        "mma.sync.aligned.m16n8k16.row.col.f32.f16.f16.f32 "
        "{%0,%1,%2,%3}, {%4,%5,%6,%7}, {%8,%9}, {%0,%1,%2,%3};"
        : "+f"(c[0]), "+f"(c[1]), "+f"(c[2]), "+f"(c[3])
        : "r"(a0), "r"(a1), "r"(a2), "r"(a3), "r"(b0), "r"(b1));
}

__device__ __forceinline__ unsigned h2u(float lo, float hi) {
    __half2 h = __floats2half2_rn(lo, hi);
    return *reinterpret_cast<unsigned*>(&h);
}

template <int K, int WHICH>
__global__ __launch_bounds__(512) void k_linear_mma(const float* __restrict__ A,
                                                    const float* __restrict__ W,
                                                    const float* __restrict__ bias,
                                                    int M) {
    constexpr int PS = K + 8;
    extern __shared__ __half sWT[];
    __half* out = (__half*)(WHICH ? g_txt_h : g_img_h);

    int tid = threadIdx.x;
    for (int i = tid; i < K * 64; i += 512) {
        int k = i >> 6, n = i & 63;
        sWT[n * PS + k] = __float2half(W[(size_t)k * 64 + n]);
    }
    __syncthreads();

    int lane = tid & 31;
    int g = lane >> 2, q = lane & 3;

    for (;;) {
        int chunk = 0;
        if (lane == 0) chunk = atomicAdd(&g_ctr[WHICH], 1);
        chunk = __shfl_sync(0xffffffffu, chunk, 0);
        int m_base = chunk << 4;
        if (m_base >= M) break;

        int row0 = m_base + g, row1 = row0 + 8;
        const float* A0 = A + (size_t)row0 * K + q * 2;
        const float* A1 = A + (size_t)row1 * K + q * 2;

        float acc[8][4];
#pragma unroll
        for (int nt = 0; nt < 8; nt++)
#pragma unroll
            for (int j = 0; j < 4; j++) acc[nt][j] = 0.f;

#pragma unroll 2
        for (int kc = 0; kc < K; kc += 64) {
            float2 fa[4][4];
#pragma unroll
            for (int c = 0; c < 4; c++) {
                int kb = kc + c * 16;
                fa[c][0] = *(const float2*)(A0 + kb);
                fa[c][1] = *(const float2*)(A1 + kb);
                fa[c][2] = *(const float2*)(A0 + kb + 8);
                fa[c][3] = *(const float2*)(A1 + kb + 8);
            }
#pragma unroll
            for (int c = 0; c < 4; c++) {
                unsigned a0 = h2u(fa[c][0].x, fa[c][0].y);
                unsigned a1 = h2u(fa[c][1].x, fa[c][1].y);
                unsigned a2 = h2u(fa[c][2].x, fa[c][2].y);
                unsigned a3 = h2u(fa[c][3].x, fa[c][3].y);
                int kb = kc + c * 16 + q * 2;
#pragma unroll
                for (int nt = 0; nt < 8; nt++) {
                    int n = nt * 8 + g;
                    unsigned b0 = *(const unsigned*)&sWT[n * PS + kb];
                    unsigned b1 = *(const unsigned*)&sWT[n * PS + kb + 8];
                    mma16816(acc[nt], a0, a1, a2, a3, b0, b1);
                }
            }
        }

#pragma unroll
        for (int nt = 0; nt < 8; nt++) {
            int col = nt * 8 + q * 2;
            float bx = bias[col], by = bias[col + 1];
            __half2 h0 = __floats2half2_rn(acc[nt][0] + bx, acc[nt][1] + by);
            __half2 h1 = __floats2half2_rn(acc[nt][2] + bx, acc[nt][3] + by);
            *(unsigned*)&out[(size_t)row0 * 64 + col] = *reinterpret_cast<unsigned*>(&h0);
            *(unsigned*)&out[(size_t)row1 * 64 + col] = *reinterpret_cast<unsigned*>(&h1);
        }
    }
}

// ----------------------------- single-pass stats -----------------------------
__global__ __launch_bounds__(256) void k_stats(const float* __restrict__ ue,
                                               const float* __restrict__ ie) {
    int t = threadIdx.x, col = t & 63, rg = t >> 6;
    float s = 0.f, q = 0.f;
    for (int row = blockIdx.x * 4 + rg; row < NTOT; row += SPART * 4) {
        const float* p = (row < NU) ? ue + (size_t)row * 64 : ie + (size_t)(row - NU) * 64;
        float x = p[col];
        s += x;
        q += x * x;
    }
    __shared__ float sm[256];
    __shared__ float sq[256];
    sm[t] = s;
    sq[t] = q;
    __syncthreads();
    if (t < 64) g_part[blockIdx.x * 64 + t] = sm[t] + sm[t + 64] + sm[t + 128] + sm[t + 192];
    for (int o = 128; o >= 32; o >>= 1) {
        if (t < o) sq[t] += sq[t + o];
        __syncthreads();
    }
    if (t < 32) {
        float v = sq[t];
#pragma unroll
        for (int o = 16; o; o >>= 1) v += __shfl_xor_sync(0xffffffffu, v, o);
        if (t == 0) g_part1[blockIdx.x] = v;
    }
}

__global__ void k_stats_fin() {
    __shared__ float smean[64];
    __shared__ float red[128];
    int t = threadIdx.x;
    if (t < 64) {
        float s = 0.f;
#pragma unroll 8
        for (int b = 0; b < SPART; b++) s += g_part[b * 64 + t];
        float m = s / (float)NTOT;
        g_colmean[t] = m;
        smean[t] = m;
    }
    __syncthreads();
    float v = g_part1[t];
    if (t < 64) v -= (float)NTOT * smean[t] * smean[t];
    red[t] = v;
    __syncthreads();
    for (int o = 64; o >= 32; o >>= 1) {
        if (t < o) red[t] += red[t + o];
        __syncthreads();
    }
    if (t < 32) {
        float x = red[t];
#pragma unroll
        for (int o = 16; o; o >>= 1) x += __shfl_xor_sync(0xffffffffu, x, o);
        if (t == 0) g_invrnm = rsqrtf(x / (float)NTOT + 1e-6f);
    }
}

__global__ void k_norm_items(const float* __restrict__ ie) {
    float inv = g_invrnm;
    int st = gridDim.x * blockDim.x;
    int i0 = blockIdx.x * blockDim.x + threadIdx.x;
    const float4* i4 = (const float4*)ie;
    const float4* cm4 = (const float4*)g_colmean;
    __half* oh = (__half*)g_in_h;
    for (int idx = i0; idx < NI * 16; idx += st) {
        float4 v = i4[idx];
        float4 cm = cm4[idx & 15];
        __half2 h0 = __floats2half2_rn((v.x - cm.x) * inv, (v.y - cm.y) * inv);
        __half2 h1 = __floats2half2_rn((v.z - cm.z) * inv, (v.w - cm.w) * inv);
        uint2 s;
        s.x = *reinterpret_cast<unsigned*>(&h0);
        s.y = *reinterpret_cast<unsigned*>(&h1);
        *(uint2*)&oh[(size_t)idx * 4] = s;
    }
}

// ----------------------------- fused triple SpMM (2 rows/warp) --------------
__device__ __forceinline__ void fma_h2(float4& acc, float v, const uint2& raw) {
    float2 x0 = __half22float2(*reinterpret_cast<const __half2*>(&raw.x));
    float2 x1 = __half22float2(*reinterpret_cast<const __half2*>(&raw.y));
    acc.x += v * x0.x; acc.y += v * x0.y;
    acc.z += v * x1.x; acc.w += v * x1.y;
}

__global__ __launch_bounds__(256) void k_fused_u(const float* __restrict__ user_emb,
                                                 float* __restrict__ imgU,
                                                 float* __restrict__ txtU) {
    int warp = (blockIdx.x * 256 + threadIdx.x) >> 5;
    int lane = threadIdx.x & 31;
    int row = warp * 2 + (lane >> 4);
    if (row >= NU) return;
    int c = lane & 15;
    const uint2* __restrict__ MI = (const uint2*)g_img_h;
    const uint2* __restrict__ MT = (const uint2*)g_txt_h;
    const uint2* __restrict__ ME = (const uint2*)g_in_h;
    const int2* __restrict__ E = g_edge_u;
    int s = g_offs_u[row], e = g_offs_u[row + 1];
    float4 aI = make_float4(0.f, 0.f, 0.f, 0.f), aT = aI, aE = aI;
    for (int k = s; k < e; k += 8) {
        int2 ev[8];
#pragma unroll
        for (int u = 0; u < 8; u++) {
            int kk = k + u;
            int idx = (kk < e) ? kk : s;
            ev[u] = __ldg(&E[idx]);
            if (kk >= e) ev[u].y = 0;
        }
        uint2 ri[8], rt[8], re[8];
#pragma unroll
        for (int u = 0; u < 8; u++) {
            int b = ev[u].x * 16 + c;
            ri[u] = MI[b];
            rt[u] = MT[b];
            re[u] = ME[b];
        }
#pragma unroll
        for (int u = 0; u < 8; u++) {
            float v = __int_as_float(ev[u].y);
            fma_h2(aI, v, ri[u]);
            fma_h2(aT, v, rt[u]);
            fma_h2(aE, v, re[u]);
        }
    }
    int o = row * 16 + c;
    ((float4*)imgU)[o] = aI;
    ((float4*)txtU)[o] = aT;
    {
        __half2 h0 = __floats2half2_rn(aI.x, aI.y);
        __half2 h1 = __floats2half2_rn(aI.z, aI.w);
        uint2 st = {*reinterpret_cast<unsigned*>(&h0), *reinterpret_cast<unsigned*>(&h1)};
        ((uint2*)g_imgU_h)[o] = st;
        h0 = __floats2half2_rn(aT.x, aT.y);
        h1 = __floats2half2_rn(aT.z, aT.w);
        st.x = *reinterpret_cast<unsigned*>(&h0);
        st.y = *reinterpret_cast<unsigned*>(&h1);
        ((uint2*)g_txtU_h)[o] = st;
        h0 = __floats2half2_rn(aE.x, aE.y);
        h1 = __floats2half2_rn(aE.z, aE.w);
        st.x = *reinterpret_cast<unsigned*>(&h0);
        st.y = *reinterpret_cast<unsigned*>(&h1);
        ((uint2*)g_ue1_h)[o] = st;
    }
    float inv = g_invrnm;
    float4 ue = ((const float4*)user_emb)[o];
    float4 cm = ((const float4*)g_colmean)[c];
    float4 acc;
    acc.x = (ue.x - cm.x) * inv + aE.x;
    acc.y = (ue.y - cm.y) * inv + aE.y;
    acc.z = (ue.z - cm.z) * inv + aE.z;
    acc.w = (ue.w - cm.w) * inv + aE.w;
    ((float4*)g_u_acc)[o] = acc;
}

__global__ __launch_bounds__(256) void k_fused_i(const float* __restrict__ item_emb,
                                                 float* __restrict__ imgI,
                                                 float* __restrict__ txtI) {
    int warp = (blockIdx.x * 256 + threadIdx.x) >> 5;
    int lane = threadIdx.x & 31;
    int row = warp * 2 + (lane >> 4);
    if (row >= NI) return;
    int c = lane & 15;
    const uint2* __restrict__ MI = (const uint2*)g_imgU_h;
    const uint2* __restrict__ MT = (const uint2*)g_txtU_h;
    const uint2* __restrict__ ME = (const uint2*)g_ue1_h;
    const int2* __restrict__ E = g_edge_i;
    int s = g_offs_i[row], e = g_offs_i[row + 1];
    float4 aI = make_float4(0.f, 0.f, 0.f, 0.f), aT = aI, aE = aI;
    for (int k = s; k < e; k += 8) {
        int2 ev[8];
#pragma unroll
        for (int u = 0; u < 8; u++) {
            int kk = k + u;
            int idx = (kk < e) ? kk : s;
            ev[u] = __ldg(&E[idx]);
            if (kk >= e) ev[u].y = 0;
        }
        uint2 ri[8], rt[8], re[8];
#pragma unroll
        for (int u = 0; u < 8; u++) {
            int b = ev[u].x * 16 + c;
            ri[u] = MI[b];
            rt[u] = MT[b];
            re[u] = ME[b];
        }
#pragma unroll
        for (int u = 0; u < 8; u++) {
            float v = __int_as_float(ev[u].y);
            fma_h2(aI, v, ri[u]);
            fma_h2(aT, v, rt[u]);
            fma_h2(aE, v, re[u]);
        }
    }
    int o = row * 16 + c;
    ((float4*)imgI)[o] = aI;
    ((float4*)txtI)[o] = aT;
    {
        __half2 h0 = __floats2half2_rn(aE.x, aE.y);
        __half2 h1 = __floats2half2_rn(aE.z, aE.w);
        uint2 st = {*reinterpret_cast<unsigned*>(&h0), *reinterpret_cast<unsigned*>(&h1)};
        ((uint2*)g_ie1_h)[o] = st;
    }
    float inv = g_invrnm;
    float4 ie = ((const float4*)item_emb)[o];
    float4 cm = ((const float4*)g_colmean)[c];
    float4 acc;
    acc.x = (ie.x - cm.x) * inv + aE.x;
    acc.y = (ie.y - cm.y) * inv + aE.y;
    acc.z = (ie.z - cm.z) * inv + aE.z;
    acc.w = (ie.w - cm.w) * inv + aE.w;
    ((float4*)g_i_acc)[o] = acc;
}

// ----------------------------- layer-2 GNN + final combine -------------------
__global__ __launch_bounds__(256) void k_gnn_u2(const float* __restrict__ imgU,
                                                const float* __restrict__ txtU,
                                                float* __restrict__ u_out) {
    int warp = (blockIdx.x * 256 + threadIdx.x) >> 5;
    int lane = threadIdx.x & 31;
    int row = warp * 2 + (lane >> 4);
    if (row >= NU) return;
    int c = lane & 15;
    const uint2* __restrict__ X = (const uint2*)g_ie1_h;
    const int2* __restrict__ E = g_edge_u;
    int s = g_offs_u[row], e = g_offs_u[row + 1];
    float4 acc = make_float4(0.f, 0.f, 0.f, 0.f);
    for (int k = s; k < e; k += 8) {
        int2 ev[8];
#pragma unroll
        for (int u = 0; u < 8; u++) {
            int kk = k + u;
            int idx = (kk < e) ? kk : s;
            ev[u] = __ldg(&E[idx]);
            if (kk >= e) ev[u].y = 0;
        }
        uint2 raw[8];
#pragma unroll
        for (int u = 0; u < 8; u++) raw[u] = X[ev[u].x * 16 + c];
#pragma unroll
        for (int u = 0; u < 8; u++) fma_h2(acc, __int_as_float(ev[u].y), raw[u]);
    }
    int o = row * 16 + c;
    {
        __half2 h0 = __floats2half2_rn(acc.x, acc.y);
        __half2 h1 = __floats2half2_rn(acc.z, acc.w);
        uint2 st = {*reinterpret_cast<unsigned*>(&h0), *reinterpret_cast<unsigned*>(&h1)};
        ((uint2*)g_ue2_h)[o] = st;
    }
    float4 g = ((const float4*)g_u_acc)[o];
    float4 a = ((const float4*)imgU)[o];
    float4 b = ((const float4*)txtU)[o];
    float sa = a.x * a.x + a.y * a.y + a.z * a.z + a.w * a.w;
    float sb = b.x * b.x + b.y * b.y + b.z * b.z + b.w * b.w;
#pragma unroll
    for (int of = 8; of; of >>= 1) {
        sa += __shfl_xor_sync(0xffffffffu, sa, of);
        sb += __shfl_xor_sync(0xffffffffu, sb, of);
    }
    float ia = 0.55f / fmaxf(sqrtf(sa), 1e-12f);
    float ib = 0.55f / fmaxf(sqrtf(sb), 1e-12f);
    float4 r;
    r.x = (g.x + acc.x) * (1.0f / 3.0f) + a.x * ia + b.x * ib;
    r.y = (g.y + acc.y) * (1.0f / 3.0f) + a.y * ia + b.y * ib;
    r.z = (g.z + acc.z) * (1.0f / 3.0f) + a.z * ia + b.z * ib;
    r.w = (g.w + acc.w) * (1.0f / 3.0f) + a.w * ia + b.w * ib;
    ((float4*)u_out)[o] = r;
}

__global__ __launch_bounds__(256) void k_gnn_i2(const float* __restrict__ imgI,
                                                const float* __restrict__ txtI,
                                                float* __restrict__ i_out) {
    int warp = (blockIdx.x * 256 + threadIdx.x) >> 5;
    int lane = threadIdx.x & 31;
    int row = warp * 2 + (lane >> 4);
    if (row >= NI) return;
    int c = lane & 15;
    const uint2* __restrict__ X = (const uint2*)g_ue2_h;
    const int2* __restrict__ E = g_edge_i;
    int s = g_offs_i[row], e = g_offs_i[row + 1];
    float4 acc = make_float4(0.f, 0.f, 0.f, 0.f);
    for (int k = s; k < e; k += 8) {
        int2 ev[8];
#pragma unroll
        for (int u = 0; u < 8; u++) {
            int kk = k + u;
            int idx = (kk < e) ? kk : s;
            ev[u] = __ldg(&E[idx]);
            if (kk >= e) ev[u].y = 0;
        }
        uint2 raw[8];
#pragma unroll
        for (int u = 0; u < 8; u++) raw[u] = X[ev[u].x * 16 + c];
#pragma unroll
        for (int u = 0; u < 8; u++) fma_h2(acc, __int_as_float(ev[u].y), raw[u]);
    }
    int o = row * 16 + c;
    float4 g = ((const float4*)g_i_acc)[o];
    float4 a = ((const float4*)imgI)[o];
    float4 b = ((const float4*)txtI)[o];
    float sa = a.x * a.x + a.y * a.y + a.z * a.z + a.w * a.w;
    float sb = b.x * b.x + b.y * b.y + b.z * b.z + b.w * b.w;
#pragma unroll
    for (int of = 8; of; of >>= 1) {
        sa += __shfl_xor_sync(0xffffffffu, sa, of);
        sb += __shfl_xor_sync(0xffffffffu, sb, of);
    }
    float ia = 0.55f / fmaxf(sqrtf(sa), 1e-12f);
    float ib = 0.55f / fmaxf(sqrtf(sb), 1e-12f);
    float4 r;
    r.x = (g.x + acc.x) * (1.0f / 3.0f) + a.x * ia + b.x * ib;
    r.y = (g.y + acc.y) * (1.0f / 3.0f) + a.y * ia + b.y * ib;
    r.z = (g.z + acc.z) * (1.0f / 3.0f) + a.z * ia + b.z * ib;
    r.w = (g.w + acc.w) * (1.0f / 3.0f) + a.w * ia + b.w * ib;
    ((float4*)i_out)[o] = r;
}

// ----------------------------- launch ---------------------------------------
static cudaStream_t s_sB = 0, s_sC = 0, s_sD = 0;
static cudaEvent_t s_evFork = 0, s_evB = 0, s_evC = 0, s_evD = 0;

extern "C" void kernel_launch(void* const* d_in, const int* in_sizes, int n_in,
                              void* d_out, int out_size) {
    const float* image_feats = (const float*)d_in[0];
    const float* text_feats  = (const float*)d_in[1];
    const float* user_emb    = (const float*)d_in[2];
    const float* item_emb    = (const float*)d_in[3];
    const float* W_img       = (const float*)d_in[4];
    const float* b_img       = (const float*)d_in[5];
    const float* W_txt       = (const float*)d_in[6];
    const float* b_txt       = (const float*)d_in[7];
    const float* val_ui      = (const float*)d_in[8];
    const float* val_iu      = (const float*)d_in[9];
    const int*   edge_u      = (const int*)d_in[10];
    const int*   edge_i      = (const int*)d_in[11];

    float* out        = (float*)d_out;
    float* u_out      = out;
    float* i_out      = u_out + (size_t)NU * DD;
    float* image_item = i_out + (size_t)NI * DD;
    float* text_item  = image_item + (size_t)NI * DD;
    float* image_user = text_item + (size_t)NI * DD;
    float* text_user  = image_user + (size_t)NU * DD;

    const int SM_IMG = 64 * (1024 + 8) * 2;
    const int SM_TXT = 64 * (384 + 8) * 2;
    cudaFuncSetAttribute(k_linear_mma<1024, 0>,
                         cudaFuncAttributeMaxDynamicSharedMemorySize, SM_IMG);
    cudaFuncSetAttribute(k_linear_mma<384, 1>,
                         cudaFuncAttributeMaxDynamicSharedMemorySize, SM_TXT);

    if (s_sB == 0) {  // one-time resource creation (outside capture, 1st call)
        cudaStreamCreateWithFlags(&s_sB, cudaStreamNonBlocking);
        cudaStreamCreateWithFlags(&s_sC, cudaStreamNonBlocking);
        cudaStreamCreateWithFlags(&s_sD, cudaStreamNonBlocking);
        cudaEventCreateWithFlags(&s_evFork, cudaEventDisableTiming);
        cudaEventCreateWithFlags(&s_evB, cudaEventDisableTiming);
        cudaEventCreateWithFlags(&s_evC, cudaEventDisableTiming);
        cudaEventCreateWithFlags(&s_evD, cudaEventDisableTiming);
    }

    void* cnt_u_ptr = nullptr;
    void* cnt_i_ptr = nullptr;
    void* ctr_ptr = nullptr;
    cudaGetSymbolAddress(&cnt_u_ptr, g_cnt_u);
    cudaGetSymbolAddress(&cnt_i_ptr, g_cnt_i);
    cudaGetSymbolAddress(&ctr_ptr, g_ctr);

    // fork three side streams off the capture stream
    cudaEventRecord(s_evFork, 0);
    cudaStreamWaitEvent(s_sB, s_evFork, 0);
    cudaStreamWaitEvent(s_sC, s_evFork, 0);
    cudaStreamWaitEvent(s_sD, s_evFork, 0);

    // branch B: tensor-core GEMMs
    cudaMemsetAsync(ctr_ptr, 0, 2 * sizeof(int), s_sB);
    k_linear_mma<1024, 0><<<148, 512, SM_IMG, s_sB>>>(image_feats, W_img, b_img, NI);
    k_linear_mma<384, 1><<<148, 512, SM_TXT, s_sB>>>(text_feats, W_txt, b_txt, NI);

    // branch C: stats chain
    k_stats<<<SPART, 256, 0, s_sC>>>(user_emb, item_emb);
    k_stats_fin<<<1, 128, 0, s_sC>>>();
    k_norm_items<<<512, 256, 0, s_sC>>>(item_emb);

    // branch D: item-side CSR
    cudaMemsetAsync(cnt_i_ptr, 0, NI * sizeof(int), s_sD);
    k_hist_i<<<512, 256, 0, s_sD>>>(edge_i);
    k_scan<1><<<1, 1024, 0, s_sD>>>();
    k_scatter_i<<<1024, 256, 0, s_sD>>>(edge_u, edge_i, val_iu);
    cudaEventRecord(s_evD, s_sD);

    // main branch: user-side CSR
    cudaMemsetAsync(cnt_u_ptr, 0, NU * sizeof(int));
    k_hist_u<<<512, 256>>>(edge_u);
    k_scan<0><<<1, 1024>>>();
    k_scatter_u<<<1024, 256>>>(edge_u, edge_i, val_ui);

    // join GEMM + stats before fused_u
    cudaEventRecord(s_evB, s_sB);
    cudaEventRecord(s_evC, s_sC);
    cudaStreamWaitEvent(0, s_evB, 0);
    cudaStreamWaitEvent(0, s_evC, 0);

    // fused modal + GNN layer-1 (user side)
    k_fused_u<<<(NU + 15) / 16, 256>>>(user_emb, image_user, text_user);

    // item side additionally needs the item CSR
    cudaStreamWaitEvent(0, s_evD, 0);
    k_fused_i<<<(NI + 15) / 16, 256>>>(item_emb, image_item, text_item);

    // GNN layer-2 fused with final combine
    k_gnn_u2<<<(NU + 15) / 16, 256>>>(image_user, text_user, u_out);
    k_gnn_i2<<<(NI + 15) / 16, 256>>>(image_item, text_item, i_out);
}